// round 10
// baseline (speedup 1.0000x reference)
#include <cuda_runtime.h>
#include <cuda_bf16.h>
#include <math.h>
#include <stdint.h>

#define BB   2
#define TT   2048
#define CC   1024
#define NH   16
#define DH   64
#define NTOK (BB * TT)
#define C3   (3 * CC)
#define LOG2E 1.4426950408889634f

typedef __nv_bfloat16 bf16;

// pair-perm within 16-element k-groups: pair p -> pos ((p&3)<<1)|(p>>2),
// so mma pairs (tg, tg+4) land on adjacent bf16x2 words.
#define PPERM(k) ( ((k) & ~15) | ((((k) >> 1) & 3) << 2) | \
                   ((((k) >> 3) & 1) << 1) | ((k) & 1) )

// ---------------------------------------------------------------------------
// scratch (bf16 hi/lo pairs)
// ---------------------------------------------------------------------------
__device__ bf16 g_xh[NTOK * CC],  g_xl[NTOK * CC];
__device__ bf16 g_wth[C3 * CC],   g_wtl[C3 * CC];    // W_attn^T [3072][kperm]
__device__ bf16 g_wph[CC * CC],   g_wpl[CC * CC];    // W_proj^T [1024][kperm]
__device__ bf16 g_qh[NTOK * CC],  g_ql[NTOK * CC];   // [b][h][t][dperm], xLOG2E
__device__ bf16 g_kh[NTOK * CC],  g_kl[NTOK * CC];   // [b][h][t][dperm]
__device__ bf16 g_vth[NTOK * CC], g_vtl[NTOK * CC];  // [b][h][d][tperm]
__device__ bf16 g_yh[NTOK * CC],  g_yl[NTOK * CC];   // [tok][cperm]

// ---------------------------------------------------------------------------
// helpers
// ---------------------------------------------------------------------------
__device__ __forceinline__ float bfr(float x) {
    return __bfloat162float(__float2bfloat16(x));
}
__device__ __forceinline__ void splitb(float x, float& h, float& l) {
    h = bfr(x);
    l = bfr(x - h);
}
__device__ __forceinline__ uint32_t pack2(float a, float b) {
    __nv_bfloat162 t = __floats2bfloat162_rn(a, b);
    return *(uint32_t*)&t;
}
__device__ __forceinline__ float ex2f(float x) {
    float y; asm("ex2.approx.f32 %0, %1;" : "=f"(y) : "f"(x)); return y;
}
__device__ __forceinline__ void mma_bf16(float* d, const uint32_t* a,
                                         uint32_t b0, uint32_t b1) {
    asm volatile(
        "mma.sync.aligned.m16n8k16.row.col.f32.bf16.bf16.f32 "
        "{%0,%1,%2,%3}, {%4,%5,%6,%7}, {%8,%9}, {%0,%1,%2,%3};"
        : "+f"(d[0]), "+f"(d[1]), "+f"(d[2]), "+f"(d[3])
        : "r"(a[0]), "r"(a[1]), "r"(a[2]), "r"(a[3]), "r"(b0), "r"(b1));
}
__device__ __forceinline__ void cp16(uint32_t d, const void* s) {
    asm volatile("cp.async.cg.shared.global [%0], [%1], 16;" :: "r"(d), "l"(s));
}
__device__ __forceinline__ void cp_commit() {
    asm volatile("cp.async.commit_group;");
}
template <int N> __device__ __forceinline__ void cp_wait() {
    asm volatile("cp.async.wait_group %0;" :: "n"(N));
}

// ---------------------------------------------------------------------------
// prepass 1: x -> xh/xl bf16 with PPERM on cols
// ---------------------------------------------------------------------------
__global__ void __launch_bounds__(256) split_perm_kernel(
    const float* __restrict__ in, bf16* __restrict__ oh,
    bf16* __restrict__ ol, int n4)
{
    const int i4 = blockIdx.x * 256 + threadIdx.x;
    if (i4 >= n4) return;
    const int g = i4 * 4;
    float4 v = *(const float4*)&in[g];
#pragma unroll
    for (int j = 0; j < 4; j++) {
        const int c = g + j;
        const int oc = (c & ~15) | PPERM(c & 15);
        float h, l;
        splitb(j == 0 ? v.x : j == 1 ? v.y : j == 2 ? v.z : v.w, h, l);
        oh[oc] = __float2bfloat16(h);
        ol[oc] = __float2bfloat16(l);
    }
}

// ---------------------------------------------------------------------------
// prepass 2: W[K][N] -> oh/ol[N][PPERM(K)] bf16
// ---------------------------------------------------------------------------
__global__ void __launch_bounds__(256) tsp_kernel(
    const float* __restrict__ W, bf16* __restrict__ oh,
    bf16* __restrict__ ol, int K, int N)
{
    __shared__ float t[32][33];
    const int bx = blockIdx.x * 32;   // N
    const int by = blockIdx.y * 32;   // K
    const int tx = threadIdx.x & 31, ty = threadIdx.x >> 5;
#pragma unroll
    for (int j = 0; j < 32; j += 8)
        t[ty + j][tx] = W[(long)(by + ty + j) * N + bx + tx];
    __syncthreads();
    const int ok = by + PPERM(tx);
#pragma unroll
    for (int j = 0; j < 32; j += 8) {
        float h, l;
        splitb(t[tx][ty + j], h, l);
        oh[(long)(bx + ty + j) * K + ok] = __float2bfloat16(h);
        ol[(long)(bx + ty + j) * K + ok] = __float2bfloat16(l);
    }
}

// ---------------------------------------------------------------------------
// GEMM (3xBF16 split): C = A @ Bt^T + bias.
// 128 threads, 4 warps (2x2), warp tile 64x64, CTA tile 128x128, BK=32,
// 3-stage cp.async, ONE __syncthreads per iter.
// stage layout (words): AH 0 | AL 2048 | BH 4096 | BL 6144 -> 8192 w = 32KB
// ---------------------------------------------------------------------------
#define GW_STAGE 8192
#define GEMM_SMEM_BYTES (3 * GW_STAGE * 4)

__device__ __forceinline__ void gemm_stage_cp(
    uint32_t sb, int s, int tid,
    const bf16* __restrict__ Agh, const bf16* __restrict__ Agl,
    const bf16* __restrict__ Bgh, const bf16* __restrict__ Bgl,
    int m0, int n0, int K, int k0)
{
    const int r2 = tid >> 1, u = tid & 1;
#pragma unroll
    for (int p = 0; p < 2; p++) {
#pragma unroll
        for (int kc = 0; kc < 2; kc++) {
            const int r = p * 64 + r2;
            const uint32_t w = (uint32_t)(s * GW_STAGE + kc * 1024 + r * 8 + u * 4);
            const long sa  = (long)(m0 + r) * K + k0 + kc * 16 + u * 8;
            const long sbv = (long)(n0 + r) * K + k0 + kc * 16 + u * 8;
            cp16(sb + w * 4,          &Agh[sa]);
            cp16(sb + (w + 2048) * 4, &Agl[sa]);
            cp16(sb + (w + 4096) * 4, &Bgh[sbv]);
            cp16(sb + (w + 6144) * 4, &Bgl[sbv]);
        }
    }
    cp_commit();
}

template <int EPI>
__global__ void __launch_bounds__(128, 2) gemm_split_kernel(
    int M, int N, int K,
    const bf16* __restrict__ Agh, const bf16* __restrict__ Agl,
    const bf16* __restrict__ Bgh, const bf16* __restrict__ Bgl,
    const float* __restrict__ bias,
    float* __restrict__ C,
    bf16* __restrict__ qh, bf16* __restrict__ ql,
    bf16* __restrict__ kh, bf16* __restrict__ kl,
    bf16* __restrict__ vth, bf16* __restrict__ vtl)
{
    extern __shared__ uint32_t smw[];
    const uint32_t sb = (uint32_t)__cvta_generic_to_shared(smw);

    const int tid  = threadIdx.x;
    const int wid  = tid >> 5, lane = tid & 31;
    const int gr   = lane >> 2, tg = lane & 3;
    const int wr   = wid >> 1,  wc = wid & 1;   // 2x2 warp grid, 64x64 tiles
    const int m0   = blockIdx.y * 128;
    const int n0   = blockIdx.x * 128;

    float acc[4][8][4];
#pragma unroll
    for (int i = 0; i < 4; i++)
#pragma unroll
        for (int j = 0; j < 8; j++)
#pragma unroll
            for (int r = 0; r < 4; r++) acc[i][j][r] = 0.f;

    const int nIter = K / 32;
    gemm_stage_cp(sb, 0, tid, Agh, Agl, Bgh, Bgl, m0, n0, K, 0);
    gemm_stage_cp(sb, 1, tid, Agh, Agl, Bgh, Bgl, m0, n0, K, 32);

    int stq = 0;
    for (int it = 0; it < nIter; it++) {
        if (it + 1 < nIter) cp_wait<1>(); else cp_wait<0>();
        __syncthreads();
        if (it + 2 < nIter) {
            int s2 = stq + 2; if (s2 >= 3) s2 -= 3;
            gemm_stage_cp(sb, s2, tid, Agh, Agl, Bgh, Bgl,
                          m0, n0, K, (it + 2) * 32);
        }

        const uint32_t* base = smw + stq * GW_STAGE;
#pragma unroll
        for (int ks = 0; ks < 2; ks++) {
            uint32_t afh[4][4], afl[4][4];
#pragma unroll
            for (int mt = 0; mt < 4; mt++) {
                const int r0 = wr * 64 + mt * 16 + gr;
                uint2 h02 = *(const uint2*)(base + ks * 1024 + r0 * 8 + 2 * tg);
                uint2 h13 = *(const uint2*)(base + ks * 1024 + (r0 + 8) * 8 + 2 * tg);
                uint2 l02 = *(const uint2*)(base + 2048 + ks * 1024 + r0 * 8 + 2 * tg);
                uint2 l13 = *(const uint2*)(base + 2048 + ks * 1024 + (r0 + 8) * 8 + 2 * tg);
                afh[mt][0] = h02.x; afh[mt][1] = h13.x;
                afh[mt][2] = h02.y; afh[mt][3] = h13.y;
                afl[mt][0] = l02.x; afl[mt][1] = l13.x;
                afl[mt][2] = l02.y; afl[mt][3] = l13.y;
            }
#pragma unroll
            for (int nt = 0; nt < 8; nt++) {
                const int rn = wc * 64 + nt * 8 + gr;
                uint2 bh = *(const uint2*)(base + 4096 + ks * 1024 + rn * 8 + 2 * tg);
                uint2 bl = *(const uint2*)(base + 6144 + ks * 1024 + rn * 8 + 2 * tg);
#pragma unroll
                for (int mt = 0; mt < 4; mt++) {
                    mma_bf16(acc[mt][nt], afh[mt], bh.x, bh.y);
                    mma_bf16(acc[mt][nt], afh[mt], bl.x, bl.y);
                    mma_bf16(acc[mt][nt], afl[mt], bh.x, bh.y);
                }
            }
        }
        if (++stq == 3) stq = 0;
    }

    // ---- epilogue ----
#pragma unroll
    for (int nt = 0; nt < 8; nt++) {
        const int col = n0 + wc * 64 + nt * 8 + tg * 2;
        const float2 bv = *(const float2*)&bias[col];
#pragma unroll
        for (int mt = 0; mt < 4; mt++) {
            const int row = m0 + wr * 64 + mt * 16 + gr;
            const float v00 = acc[mt][nt][0] + bv.x;
            const float v01 = acc[mt][nt][1] + bv.y;
            const float v10 = acc[mt][nt][2] + bv.x;
            const float v11 = acc[mt][nt][3] + bv.y;
            if (EPI == 0) {
                *(float2*)&C[(long)row * N + col]       = make_float2(v00, v01);
                *(float2*)&C[(long)(row + 8) * N + col] = make_float2(v10, v11);
            } else {
                const int sec = col >> 10;
                const int dc  = col & 1023;
                const int hh  = dc >> 6, d0 = dc & 63;
                const int e0  = PPERM(d0);
#pragma unroll
                for (int rr = 0; rr < 2; rr++) {
                    const int m = row + rr * 8;
                    const int b = m >> 11, t = m & 2047;
                    float u0 = rr ? v10 : v00;
                    float u1 = rr ? v11 : v01;
                    if (sec < 2) {
                        const long a = ((long)((b * NH + hh) * TT) + t) * DH + e0;
                        float h0, l0, h1, l1;
                        if (sec == 0) { u0 *= LOG2E; u1 *= LOG2E; }
                        splitb(u0, h0, l0);
                        splitb(u1, h1, l1);
                        if (sec == 0) {
                            *(uint32_t*)&qh[a] = pack2(h0, h1);
                            *(uint32_t*)&ql[a] = pack2(l0, l1);
                        } else {
                            *(uint32_t*)&kh[a] = pack2(h0, h1);
                            *(uint32_t*)&kl[a] = pack2(l0, l1);
                        }
                    } else {
                        const int tp = PPERM(t);
                        const long a = ((long)((b * NH + hh) * DH + d0)) * TT + tp;
                        float h0, l0, h1, l1;
                        splitb(u0, h0, l0);
                        splitb(u1, h1, l1);
                        vth[a] = __float2bfloat16(h0);
                        vtl[a] = __float2bfloat16(l0);
                        vth[a + TT] = __float2bfloat16(h1);
                        vtl[a + TT] = __float2bfloat16(l1);
                    }
                }
            }
        }
    }
}

// ---------------------------------------------------------------------------
// Attention: 128 thr (4 warps), warp = 32 q-rows (2 groups of 16), BQ=128,
// BK=64, 3-stage cp.async, ONE sync/iter. K/V fragment loads amortized
// across both q-row groups. P in registers. PV 3-term bf16.
// stage layout (words): KH 0 | KL 2048 | VTH 4096 | VTL 6144 -> 8192 w
// ---------------------------------------------------------------------------
#define AW_STAGE 8192
#define AT_SMEM_BYTES (3 * AW_STAGE * 4)

__device__ __forceinline__ void attn_stage_cp(
    uint32_t sb, int s, int tid,
    const bf16* __restrict__ kh, const bf16* __restrict__ kl,
    const bf16* __restrict__ vth, const bf16* __restrict__ vtl,
    long kB, long vB, int j0)
{
#pragma unroll
    for (int q = 0; q < 4; q++) {
        const int j = q * 128 + tid;          // 0..511
        const int r = j >> 3, u = j & 7;      // row, 16B unit
        const uint32_t w = (uint32_t)(s * AW_STAGE + (u >> 1) * 512 + r * 8 + (u & 1) * 4);
        const long sk = kB + (long)(j0 + r) * DH + u * 8;
        const long sv = vB + (long)r * TT + j0 + u * 8;
        cp16(sb + w * 4,          &kh[sk]);
        cp16(sb + (w + 2048) * 4, &kl[sk]);
        cp16(sb + (w + 4096) * 4, &vth[sv]);
        cp16(sb + (w + 6144) * 4, &vtl[sv]);
    }
    cp_commit();
}

__global__ void __launch_bounds__(128, 2) attn_kernel(
    const bf16* __restrict__ qh, const bf16* __restrict__ ql,
    const bf16* __restrict__ kh, const bf16* __restrict__ kl,
    const bf16* __restrict__ vth, const bf16* __restrict__ vtl,
    bf16* __restrict__ yh, bf16* __restrict__ yl)
{
    extern __shared__ uint32_t smw[];
    const uint32_t sb = (uint32_t)__cvta_generic_to_shared(smw);

    const int tid  = threadIdx.x;
    const int wid  = tid >> 5, lane = tid & 31;
    const int gr   = lane >> 2, tg = lane & 3;
    const int b    = blockIdx.y >> 4, h = blockIdx.y & 15;
    const int qa   = blockIdx.x * 128 + wid * 32;   // warp's first q row
    const int hoff = h * DH;

    const long kB = (long)((b * NH + h) * TT) * DH;
    const long vB = (long)((b * NH + h) * DH) * TT;

    attn_stage_cp(sb, 0, tid, kh, kl, vth, vtl, kB, vB, 0);
    attn_stage_cp(sb, 1, tid, kh, kl, vth, vtl, kB, vB, 64);

    // Q fragments: two 16-row groups per warp
    uint32_t qfh[2][4][4], qfl[2][4][4];
#pragma unroll
    for (int g = 0; g < 2; g++) {
#pragma unroll
        for (int kt = 0; kt < 4; kt++) {
            const long e = kB + (long)(qa + g * 16 + gr) * DH + kt * 16 + 4 * tg;
            uint2 h02 = *(const uint2*)&qh[e];
            uint2 h13 = *(const uint2*)&qh[e + 8 * DH];
            uint2 l02 = *(const uint2*)&ql[e];
            uint2 l13 = *(const uint2*)&ql[e + 8 * DH];
            qfh[g][kt][0] = h02.x; qfh[g][kt][1] = h13.x;
            qfh[g][kt][2] = h02.y; qfh[g][kt][3] = h13.y;
            qfl[g][kt][0] = l02.x; qfl[g][kt][1] = l13.x;
            qfl[g][kt][2] = l02.y; qfl[g][kt][3] = l13.y;
        }
    }

    float oacc[2][8][4];
#pragma unroll
    for (int g = 0; g < 2; g++)
#pragma unroll
        for (int nt = 0; nt < 8; nt++)
#pragma unroll
            for (int r = 0; r < 4; r++) oacc[g][nt][r] = 0.f;
    float lA[2] = {0.f, 0.f}, lB[2] = {0.f, 0.f};

    int stq = 0;
    for (int jt = 0; jt < 32; jt++) {
        if (jt + 1 < 32) cp_wait<1>(); else cp_wait<0>();
        __syncthreads();
        if (jt + 2 < 32) {
            int s2 = stq + 2; if (s2 >= 3) s2 -= 3;
            attn_stage_cp(sb, s2, tid, kh, kl, vth, vtl, kB, vB,
                          (jt + 2) * 64);
        }
        const uint32_t* base = smw + stq * AW_STAGE;

        // ---- S = Q K^T (3xBF16), both groups per fragment load ----
        float sacc[2][8][4];
#pragma unroll
        for (int g = 0; g < 2; g++)
#pragma unroll
            for (int nt = 0; nt < 8; nt++)
#pragma unroll
                for (int r = 0; r < 4; r++) sacc[g][nt][r] = 0.f;

#pragma unroll
        for (int kt = 0; kt < 4; kt++) {
            const uint32_t* kbh = base + kt * 512;
            const uint32_t* kbl = base + 2048 + kt * 512;
#pragma unroll
            for (int nt = 0; nt < 8; nt++) {
                const int w = (nt * 8 + gr) * 8 + 2 * tg;
                uint2 bh = *(const uint2*)(kbh + w);
                uint2 bl = *(const uint2*)(kbl + w);
#pragma unroll
                for (int g = 0; g < 2; g++) {
                    mma_bf16(sacc[g][nt], qfh[g][kt], bh.x, bh.y);
                    mma_bf16(sacc[g][nt], qfh[g][kt], bl.x, bl.y);
                    mma_bf16(sacc[g][nt], qfl[g][kt], bh.x, bh.y);
                }
            }
        }

        // ---- softmax: p = 2^s; pack to bf16 P-fragments (frees sacc) ----
        uint32_t pah[2][4][4], pal[2][4][4];
#pragma unroll
        for (int g = 0; g < 2; g++) {
#pragma unroll
            for (int nt = 0; nt < 8; nt++) {
                float* s4 = sacc[g][nt];
                s4[0] = ex2f(s4[0]);
                s4[1] = ex2f(s4[1]);
                s4[2] = ex2f(s4[2]);
                s4[3] = ex2f(s4[3]);
                lA[g] += s4[0] + s4[1];
                lB[g] += s4[2] + s4[3];
                const int kt = nt >> 1, i = nt & 1;
                uint32_t w0 = pack2(s4[0], s4[1]);
                uint32_t w1 = pack2(s4[2], s4[3]);
                pah[g][kt][2 * i]     = w0;
                pah[g][kt][2 * i + 1] = w1;
                __nv_bfloat162 b0 = *(__nv_bfloat162*)&w0;
                __nv_bfloat162 b1 = *(__nv_bfloat162*)&w1;
                float2 f0 = __bfloat1622float2(b0);
                float2 f1 = __bfloat1622float2(b1);
                pal[g][kt][2 * i]     = pack2(s4[0] - f0.x, s4[1] - f0.y);
                pal[g][kt][2 * i + 1] = pack2(s4[2] - f1.x, s4[3] - f1.y);
            }
        }

        // ---- O += P V, both groups per V fragment load ----
#pragma unroll
        for (int kt = 0; kt < 4; kt++) {
            const uint32_t* vbh = base + 4096 + kt * 512;
            const uint32_t* vbl = base + 6144 + kt * 512;
#pragma unroll
            for (int nt = 0; nt < 8; nt++) {
                const int w = (nt * 8 + gr) * 8 + 2 * tg;
                uint2 vh = *(const uint2*)(vbh + w);
                uint2 vl = *(const uint2*)(vbl + w);
#pragma unroll
                for (int g = 0; g < 2; g++) {
                    mma_bf16(oacc[g][nt], pah[g][kt], vh.x, vh.y);
                    mma_bf16(oacc[g][nt], pah[g][kt], vl.x, vl.y);
                    mma_bf16(oacc[g][nt], pal[g][kt], vh.x, vh.y);
                }
            }
        }
        if (++stq == 3) stq = 0;
    }

    // row-quad reductions + epilogue per group
#pragma unroll
    for (int g = 0; g < 2; g++) {
        float la = lA[g], lb = lB[g];
        la += __shfl_xor_sync(0xffffffffu, la, 1);
        la += __shfl_xor_sync(0xffffffffu, la, 2);
        lb += __shfl_xor_sync(0xffffffffu, lb, 1);
        lb += __shfl_xor_sync(0xffffffffu, lb, 2);
        const float invA = 1.0f / (la * 8.0f);
        const float invB = 1.0f / (lb * 8.0f);
        const long rowA = (long)(b * TT + qa + g * 16 + gr) * CC;
        const long rowB = rowA + 8 * CC;
#pragma unroll
        for (int nt = 0; nt < 8; nt++) {
            const int p = (nt & 1) * 4 + tg;
            const int pos = ((p & 3) << 1) | (p >> 2);
            const int e = hoff + (nt >> 1) * 16 + pos * 2;
            float h0, l0, h1, l1;
            splitb(oacc[g][nt][0] * invA, h0, l0);
            splitb(oacc[g][nt][1] * invA, h1, l1);
            *(uint32_t*)&yh[rowA + e] = pack2(h0, h1);
            *(uint32_t*)&yl[rowA + e] = pack2(l0, l1);
            splitb(oacc[g][nt][2] * invB, h0, l0);
            splitb(oacc[g][nt][3] * invB, h1, l1);
            *(uint32_t*)&yh[rowB + e] = pack2(h0, h1);
            *(uint32_t*)&yl[rowB + e] = pack2(l0, l1);
        }
    }
}

// ---------------------------------------------------------------------------
extern "C" void kernel_launch(void* const* d_in, const int* in_sizes, int n_in,
                              void* d_out, int out_size)
{
    const float* x      = (const float*)d_in[0];
    const float* W_attn = (const float*)d_in[1];
    const float* b_attn = (const float*)d_in[2];
    const float* W_proj = (const float*)d_in[3];
    const float* b_proj = (const float*)d_in[4];
    float* out = (float*)d_out;

    bf16 *xh, *xl, *wth, *wtl, *wph, *wpl;
    bf16 *qhp, *qlp, *khp, *klp, *vthp, *vtlp, *yhp, *ylp;
    cudaGetSymbolAddress((void**)&xh,   g_xh);
    cudaGetSymbolAddress((void**)&xl,   g_xl);
    cudaGetSymbolAddress((void**)&wth,  g_wth);
    cudaGetSymbolAddress((void**)&wtl,  g_wtl);
    cudaGetSymbolAddress((void**)&wph,  g_wph);
    cudaGetSymbolAddress((void**)&wpl,  g_wpl);
    cudaGetSymbolAddress((void**)&qhp,  g_qh);
    cudaGetSymbolAddress((void**)&qlp,  g_ql);
    cudaGetSymbolAddress((void**)&khp,  g_kh);
    cudaGetSymbolAddress((void**)&klp,  g_kl);
    cudaGetSymbolAddress((void**)&vthp, g_vth);
    cudaGetSymbolAddress((void**)&vtlp, g_vtl);
    cudaGetSymbolAddress((void**)&yhp,  g_yh);
    cudaGetSymbolAddress((void**)&ylp,  g_yl);

    cudaFuncSetAttribute(gemm_split_kernel<0>,
                         cudaFuncAttributeMaxDynamicSharedMemorySize,
                         GEMM_SMEM_BYTES);
    cudaFuncSetAttribute(gemm_split_kernel<1>,
                         cudaFuncAttributeMaxDynamicSharedMemorySize,
                         GEMM_SMEM_BYTES);
    cudaFuncSetAttribute(attn_kernel,
                         cudaFuncAttributeMaxDynamicSharedMemorySize,
                         AT_SMEM_BYTES);

    // prepasses
    split_perm_kernel<<<(NTOK * CC / 4 + 255) / 256, 256>>>(x, xh, xl,
                                                            NTOK * CC / 4);
    tsp_kernel<<<dim3(C3 / 32, CC / 32), 256>>>(W_attn, wth, wtl, CC, C3);
    tsp_kernel<<<dim3(CC / 32, CC / 32), 256>>>(W_proj, wph, wpl, CC, CC);

    // 1) QKV GEMM + routing epilogue (Q scaled by log2e)
    gemm_split_kernel<1><<<dim3(C3 / 128, NTOK / 128), 128, GEMM_SMEM_BYTES>>>(
        NTOK, C3, CC, xh, xl, wth, wtl, b_attn,
        nullptr, qhp, qlp, khp, klp, vthp, vtlp);

    // 2) attention
    attn_kernel<<<dim3(TT / 128, BB * NH), 128, AT_SMEM_BYTES>>>(
        qhp, qlp, khp, klp, vthp, vtlp, yhp, ylp);

    // 3) proj GEMM
    gemm_split_kernel<0><<<dim3(CC / 128, NTOK / 128), 128, GEMM_SMEM_BYTES>>>(
        NTOK, CC, CC, yhp, ylp, wph, wpl, b_proj,
        out, nullptr, nullptr, nullptr, nullptr, nullptr, nullptr);
}

// round 11
// speedup vs baseline: 1.3990x; 1.3990x over previous
#include <cuda_runtime.h>
#include <cuda_bf16.h>
#include <math.h>
#include <stdint.h>

#define BB   2
#define TT   2048
#define CC   1024
#define NH   16
#define DH   64
#define NTOK (BB * TT)
#define C3   (3 * CC)
#define LOG2E 1.4426950408889634f

typedef __nv_bfloat16 bf16;

// ---------------------------------------------------------------------------
// Fragment-major layouts (16x16 tiles, 32 lanes x 16B):
//  A-type (row operand), lane(gr,tg):  w0=(row gr,  kpair tg)  w1=(row gr+8, tg)
//                                      w2=(row gr,  tg+4)      w3=(row gr+8, tg+4)
//  B-type (col operand), lane(gr,tg):  w0=(col gr,  kpair tg)  w1=(col gr,  tg+4)
//                                      w2=(col gr+8, tg)       w3=(col gr+8, tg+4)
//  kpair p = elements {2p, 2p+1}. Tile = 512B; flat tile idx varies per tensor.
// ---------------------------------------------------------------------------
__device__ bf16 g_xh[NTOK * CC],  g_xl[NTOK * CC];   // A-type [m/16][64]
__device__ bf16 g_wth[C3 * CC],   g_wtl[C3 * CC];    // B-type [n/16][64]
__device__ bf16 g_wph[CC * CC],   g_wpl[CC * CC];    // B-type [n/16][64]
__device__ bf16 g_qh[NTOK * CC],  g_ql[NTOK * CC];   // A-type [bh][t/16][4]
__device__ bf16 g_kh[NTOK * CC],  g_kl[NTOK * CC];   // B-type [bh][t/16][4]
__device__ bf16 g_vth[NTOK * CC], g_vtl[NTOK * CC];  // B-type [bh][d/16][t/16]
__device__ bf16 g_yh[NTOK * CC],  g_yl[NTOK * CC];   // A-type [m/16][64]

// ---------------------------------------------------------------------------
// helpers
// ---------------------------------------------------------------------------
__device__ __forceinline__ float bfr(float x) {
    return __bfloat162float(__float2bfloat16(x));
}
__device__ __forceinline__ void splitb(float x, float& h, float& l) {
    h = bfr(x);
    l = bfr(x - h);
}
__device__ __forceinline__ uint32_t pack2(float a, float b) {
    __nv_bfloat162 t = __floats2bfloat162_rn(a, b);
    return *(uint32_t*)&t;
}
__device__ __forceinline__ float ex2f(float x) {
    float y; asm("ex2.approx.f32 %0, %1;" : "=f"(y) : "f"(x)); return y;
}
__device__ __forceinline__ void mma_bf16(float* d, const uint32_t* a,
                                         uint32_t b0, uint32_t b1) {
    asm volatile(
        "mma.sync.aligned.m16n8k16.row.col.f32.bf16.bf16.f32 "
        "{%0,%1,%2,%3}, {%4,%5,%6,%7}, {%8,%9}, {%0,%1,%2,%3};"
        : "+f"(d[0]), "+f"(d[1]), "+f"(d[2]), "+f"(d[3])
        : "r"(a[0]), "r"(a[1]), "r"(a[2]), "r"(a[3]), "r"(b0), "r"(b1));
}
__device__ __forceinline__ void cp16(uint32_t d, const void* s) {
    asm volatile("cp.async.cg.shared.global [%0], [%1], 16;" :: "r"(d), "l"(s));
}
__device__ __forceinline__ void cp_commit() {
    asm volatile("cp.async.commit_group;");
}
template <int N> __device__ __forceinline__ void cp_wait() {
    asm volatile("cp.async.wait_group %0;" :: "n"(N));
}

// ---------------------------------------------------------------------------
// prepass 1: x[4096][1024] f32 -> A-type frag-major hi/lo (tiles [m/16][64])
// thread handles 4 consecutive k of one row (2 k-pairs).
// ---------------------------------------------------------------------------
__global__ void __launch_bounds__(256) split_a_kernel(
    const float* __restrict__ in, uint32_t* __restrict__ oh,
    uint32_t* __restrict__ ol, int n4)
{
    const int i4 = blockIdx.x * 256 + threadIdx.x;
    if (i4 >= n4) return;
    const int g = i4 * 4;
    const int m = g >> 10, k0 = g & 1023;
    float4 v = *(const float4*)&in[g];

    const int r = m & 15, gr = r & 7, hi = (r >> 3) & 1;
    const int tile = ((m >> 4) << 6) + (k0 >> 4);
    const int p0 = (k0 & 15) >> 1;      // even pair
#pragma unroll
    for (int q = 0; q < 2; q++) {
        const int p = p0 + q;
        const int lane = gr * 4 + (p & 3);
        const int w = hi + 2 * (p >> 2);
        const int a32 = (tile * 32 + lane) * 4 + w;
        float e0 = q ? v.z : v.x, e1 = q ? v.w : v.y;
        float h0, l0, h1, l1;
        splitb(e0, h0, l0);
        splitb(e1, h1, l1);
        oh[a32] = pack2(h0, h1);
        ol[a32] = pack2(l0, l1);
    }
}

// ---------------------------------------------------------------------------
// prepass 2: W[K=1024][N] -> B-type frag-major hi/lo (tiles [n/16][64])
// ---------------------------------------------------------------------------
__global__ void __launch_bounds__(256) tsp_b_kernel(
    const float* __restrict__ W, bf16* __restrict__ oh,
    bf16* __restrict__ ol, int N)
{
    __shared__ float t[32][33];
    const int bx = blockIdx.x * 32;   // N
    const int by = blockIdx.y * 32;   // K
    const int tx = threadIdx.x & 31, ty = threadIdx.x >> 5;
#pragma unroll
    for (int j = 0; j < 32; j += 8)
        t[ty + j][tx] = W[(long)(by + ty + j) * N + bx + tx];
    __syncthreads();
    const int k = by + tx;
    const int ki = k >> 4, kk = k & 15, p = kk >> 1, e = kk & 1;
#pragma unroll
    for (int j = 0; j < 32; j += 8) {
        const int n = bx + ty + j;
        const int c = n & 15;
        const int lane = (c & 7) * 4 + (p & 3);
        const int w = ((c >> 3) & 1) * 2 + (p >> 2);
        const long flat = ((long)(((n >> 4) << 6) + ki) * 32 + lane) * 8 + w * 2 + e;
        float h, l;
        splitb(t[tx][ty + j], h, l);
        oh[flat] = __float2bfloat16(h);
        ol[flat] = __float2bfloat16(l);
    }
}

// ---------------------------------------------------------------------------
// GEMM (3xBF16): C = A @ Bt^T + bias. 256 thr, 8 warps (2x4), warp 64x32,
// CTA 128x128, BK=32, 3-stage cp.async, frag-major LDS.128 operand loads.
// stage (words): AH 0 | AL 2048 | BH 4096 | BL 6144 = 8192 w = 32KB
// smem word (plane): (ktile2*8 + tile16)*128 + lane*4
// ---------------------------------------------------------------------------
#define GW_STAGE 8192
#define GEMM_SMEM_BYTES (3 * GW_STAGE * 4)

__device__ __forceinline__ void gemm_stage_cp(
    uint32_t sb, int s, int tid,
    const bf16* __restrict__ Agh, const bf16* __restrict__ Agl,
    const bf16* __restrict__ Bgh, const bf16* __restrict__ Bgl,
    int mt0, int nt0, int kt0)
{
#pragma unroll
    for (int i = 0; i < 2; i++) {
        const int c = tid + i * 256;            // 0..511
        const int kt2 = c >> 8, t8 = (c >> 5) & 7, lane = c & 31;
        const uint32_t w = (uint32_t)(s * GW_STAGE + (kt2 * 8 + t8) * 128 + lane * 4);
        const long ga = ((long)((mt0 + t8) * 64 + kt0 + kt2) * 32 + lane) * 8;
        const long gb = ((long)((nt0 + t8) * 64 + kt0 + kt2) * 32 + lane) * 8;
        cp16(sb + w * 4,          &Agh[ga]);
        cp16(sb + (w + 2048) * 4, &Agl[ga]);
        cp16(sb + (w + 4096) * 4, &Bgh[gb]);
        cp16(sb + (w + 6144) * 4, &Bgl[gb]);
    }
    cp_commit();
}

template <int EPI>
__global__ void __launch_bounds__(256, 2) gemm_split_kernel(
    int M, int N, int K,
    const bf16* __restrict__ Agh, const bf16* __restrict__ Agl,
    const bf16* __restrict__ Bgh, const bf16* __restrict__ Bgl,
    const float* __restrict__ bias,
    float* __restrict__ C,
    uint32_t* __restrict__ qh32, uint32_t* __restrict__ ql32,
    uint32_t* __restrict__ kh32, uint32_t* __restrict__ kl32,
    bf16* __restrict__ vth, bf16* __restrict__ vtl)
{
    extern __shared__ uint32_t smw[];
    const uint32_t sb = (uint32_t)__cvta_generic_to_shared(smw);

    const int tid  = threadIdx.x;
    const int wid  = tid >> 5, lane = tid & 31;
    const int gr   = lane >> 2, tg = lane & 3;
    const int wr   = wid >> 2,  wc = wid & 3;   // 2x4, warp 64x32
    const int m0   = blockIdx.y * 128;
    const int n0   = blockIdx.x * 128;
    const int mt0  = m0 >> 4, nt0 = n0 >> 4;

    float acc[4][4][4];
#pragma unroll
    for (int i = 0; i < 4; i++)
#pragma unroll
        for (int j = 0; j < 4; j++)
#pragma unroll
            for (int r = 0; r < 4; r++) acc[i][j][r] = 0.f;

    const int nIter = K / 32;
    gemm_stage_cp(sb, 0, tid, Agh, Agl, Bgh, Bgl, mt0, nt0, 0);
    gemm_stage_cp(sb, 1, tid, Agh, Agl, Bgh, Bgl, mt0, nt0, 2);

    int stq = 0;
    for (int it = 0; it < nIter; it++) {
        if (it + 1 < nIter) cp_wait<1>(); else cp_wait<0>();
        __syncthreads();
        if (it + 2 < nIter) {
            int s2 = stq + 2; if (s2 >= 3) s2 -= 3;
            gemm_stage_cp(sb, s2, tid, Agh, Agl, Bgh, Bgl,
                          mt0, nt0, (it + 2) * 2);
        }

        const uint32_t* base = smw + stq * GW_STAGE;
#pragma unroll
        for (int ks = 0; ks < 2; ks++) {
            uint4 afh[4], afl[4];
#pragma unroll
            for (int mt = 0; mt < 4; mt++) {
                const int o = (ks * 8 + wr * 4 + mt) * 128 + lane * 4;
                afh[mt] = *(const uint4*)(base + o);
                afl[mt] = *(const uint4*)(base + 2048 + o);
            }
#pragma unroll
            for (int j = 0; j < 2; j++) {
                const int o = (ks * 8 + wc * 2 + j) * 128 + lane * 4;
                uint4 bh4 = *(const uint4*)(base + 4096 + o);
                uint4 bl4 = *(const uint4*)(base + 6144 + o);
#pragma unroll
                for (int jj = 0; jj < 2; jj++) {
                    const int nt = 2 * j + jj;
                    const uint32_t b0 = jj ? bh4.z : bh4.x;
                    const uint32_t b1 = jj ? bh4.w : bh4.y;
                    const uint32_t c0 = jj ? bl4.z : bl4.x;
                    const uint32_t c1 = jj ? bl4.w : bl4.y;
#pragma unroll
                    for (int mt = 0; mt < 4; mt++) {
                        mma_bf16(acc[mt][nt], (const uint32_t*)&afh[mt], b0, b1);
                        mma_bf16(acc[mt][nt], (const uint32_t*)&afh[mt], c0, c1);
                        mma_bf16(acc[mt][nt], (const uint32_t*)&afl[mt], b0, b1);
                    }
                }
            }
        }
        if (++stq == 3) stq = 0;
    }

    // ---- epilogue ----
#pragma unroll
    for (int nt = 0; nt < 4; nt++) {
        const int col = n0 + wc * 32 + nt * 8 + tg * 2;
        const float2 bv = *(const float2*)&bias[col];
#pragma unroll
        for (int mt = 0; mt < 4; mt++) {
            const int row = m0 + wr * 64 + mt * 16 + gr;
            const float v00 = acc[mt][nt][0] + bv.x;
            const float v01 = acc[mt][nt][1] + bv.y;
            const float v10 = acc[mt][nt][2] + bv.x;
            const float v11 = acc[mt][nt][3] + bv.y;
            if (EPI == 0) {
                *(float2*)&C[(long)row * N + col]       = make_float2(v00, v01);
                *(float2*)&C[(long)(row + 8) * N + col] = make_float2(v10, v11);
            } else {
                const int sec = col >> 10;
                const int dc  = col & 1023;
                const int hh  = dc >> 6, d0 = dc & 63;   // d0 even
#pragma unroll
                for (int rr = 0; rr < 2; rr++) {
                    const int m = row + rr * 8;
                    const int b = m >> 11, t = m & 2047;
                    float u0 = rr ? v10 : v00;
                    float u1 = rr ? v11 : v01;
                    float h0, l0, h1, l1;
                    if (sec == 0) {
                        u0 *= LOG2E; u1 *= LOG2E;
                        splitb(u0, h0, l0); splitb(u1, h1, l1);
                        const int lane_ = (t & 7) * 4 + ((d0 >> 1) & 3);
                        const int w = ((t >> 3) & 1) + 2 * ((d0 >> 3) & 1);
                        const int tile = ((b * NH + hh) * 128 + (t >> 4)) * 4 + (d0 >> 4);
                        const int a32 = (tile * 32 + lane_) * 4 + w;
                        qh32[a32] = pack2(h0, h1);
                        ql32[a32] = pack2(l0, l1);
                    } else if (sec == 1) {
                        splitb(u0, h0, l0); splitb(u1, h1, l1);
                        const int lane_ = (t & 7) * 4 + ((d0 >> 1) & 3);
                        const int w = ((t >> 3) & 1) * 2 + ((d0 >> 3) & 1);
                        const int tile = ((b * NH + hh) * 128 + (t >> 4)) * 4 + (d0 >> 4);
                        const int a32 = (tile * 32 + lane_) * 4 + w;
                        kh32[a32] = pack2(h0, h1);
                        kl32[a32] = pack2(l0, l1);
                    } else {
                        splitb(u0, h0, l0); splitb(u1, h1, l1);
                        const int lane_ = (d0 & 7) * 4 + ((t >> 1) & 3);
                        const int w = ((d0 >> 3) & 1) * 2 + ((t >> 3) & 1);
                        const int tile = ((b * NH + hh) * 4 + (d0 >> 4)) * 128 + (t >> 4);
                        const long f = ((long)tile * 32 + lane_) * 8 + w * 2 + (t & 1);
                        vth[f] = __float2bfloat16(h0);
                        vtl[f] = __float2bfloat16(l0);
                        vth[f + 32] = __float2bfloat16(h1);   // d0+1: lane_+4
                        vtl[f + 32] = __float2bfloat16(l1);
                    }
                }
            }
        }
    }
}

// ---------------------------------------------------------------------------
// Attention: 128 thr (4 warps), warp = 32 q-rows (2 groups), BQ=128, BK=64,
// 3-stage cp.async, frag-major LDS.128 K/V loads, P in registers.
// stage (words): KH 0 | KL 2048 | VTH 4096 | VTL 6144 = 8192 w
// K smem: (dtile*4 + ttile)*128 + lane*4 ; V smem: (ttile*4 + dtile)*128 + ...
// ---------------------------------------------------------------------------
#define AW_STAGE 8192
#define AT_SMEM_BYTES (3 * AW_STAGE * 4)

__device__ __forceinline__ void attn_stage_cp(
    uint32_t sb, int s, int tid, int bh32,
    const bf16* __restrict__ kh, const bf16* __restrict__ kl,
    const bf16* __restrict__ vth, const bf16* __restrict__ vtl,
    int jt0)   // token tile16 index of this 64-key tile (j0/16)
{
#pragma unroll
    for (int q = 0; q < 4; q++) {
        const int c = q * 128 + tid;          // 0..511
        const int dt = c >> 7, tt = (c >> 5) & 3, lane = c & 31;
        const long gk = ((long)((bh32 * 128 + jt0 + tt) * 4 + dt) * 32 + lane) * 8;
        const long gv = ((long)((bh32 * 4 + dt) * 128 + jt0 + tt) * 32 + lane) * 8;
        const uint32_t wk = (uint32_t)(s * AW_STAGE + (dt * 4 + tt) * 128 + lane * 4);
        const uint32_t wv = (uint32_t)(s * AW_STAGE + 4096 + (tt * 4 + dt) * 128 + lane * 4);
        cp16(sb + wk * 4,          &kh[gk]);
        cp16(sb + (wk + 2048) * 4, &kl[gk]);
        cp16(sb + wv * 4,          &vth[gv]);
        cp16(sb + (wv + 2048) * 4, &vtl[gv]);
    }
    cp_commit();
}

__global__ void __launch_bounds__(128, 2) attn_kernel(
    const uint32_t* __restrict__ qh32, const uint32_t* __restrict__ ql32,
    const bf16* __restrict__ kh, const bf16* __restrict__ kl,
    const bf16* __restrict__ vth, const bf16* __restrict__ vtl,
    uint32_t* __restrict__ yh32, uint32_t* __restrict__ yl32)
{
    extern __shared__ uint32_t smw[];
    const uint32_t sb = (uint32_t)__cvta_generic_to_shared(smw);

    const int tid  = threadIdx.x;
    const int wid  = tid >> 5, lane = tid & 31;
    const int gr   = lane >> 2, tg = lane & 3;
    const int bh32 = blockIdx.y;
    const int b    = bh32 >> 4, h = bh32 & 15;
    const int qa   = blockIdx.x * 128 + wid * 32;

    attn_stage_cp(sb, 0, tid, bh32, kh, kl, vth, vtl, 0);
    attn_stage_cp(sb, 1, tid, bh32, kh, kl, vth, vtl, 4);

    // Q fragments: LDG.128 per (g,kt), words = a0..a3 directly
    uint4 qfh[2][4], qfl[2][4];
#pragma unroll
    for (int g = 0; g < 2; g++) {
#pragma unroll
        for (int kt = 0; kt < 4; kt++) {
            const int tile = (bh32 * 128 + ((qa + g * 16) >> 4)) * 4 + kt;
            qfh[g][kt] = *(const uint4*)(qh32 + (tile * 32 + lane) * 4);
            qfl[g][kt] = *(const uint4*)(ql32 + (tile * 32 + lane) * 4);
        }
    }

    float oacc[2][8][4];
#pragma unroll
    for (int g = 0; g < 2; g++)
#pragma unroll
        for (int nt = 0; nt < 8; nt++)
#pragma unroll
            for (int r = 0; r < 4; r++) oacc[g][nt][r] = 0.f;
    float lA[2] = {0.f, 0.f}, lB[2] = {0.f, 0.f};

    int stq = 0;
    for (int jt = 0; jt < 32; jt++) {
        if (jt + 1 < 32) cp_wait<1>(); else cp_wait<0>();
        __syncthreads();
        if (jt + 2 < 32) {
            int s2 = stq + 2; if (s2 >= 3) s2 -= 3;
            attn_stage_cp(sb, s2, tid, bh32, kh, kl, vth, vtl, (jt + 2) * 4);
        }
        const uint32_t* base = smw + stq * AW_STAGE;

        // ---- S = Q K^T (3xBF16) ----
        float sacc[2][8][4];
#pragma unroll
        for (int g = 0; g < 2; g++)
#pragma unroll
            for (int nt = 0; nt < 8; nt++)
#pragma unroll
                for (int r = 0; r < 4; r++) sacc[g][nt][r] = 0.f;

#pragma unroll
        for (int kt = 0; kt < 4; kt++) {          // d-tiles
#pragma unroll
            for (int ntp = 0; ntp < 4; ntp++) {   // token-tile16 pairs
                const int o = (kt * 4 + ntp) * 128 + lane * 4;
                uint4 kh4 = *(const uint4*)(base + o);
                uint4 kl4 = *(const uint4*)(base + 2048 + o);
#pragma unroll
                for (int jj = 0; jj < 2; jj++) {
                    const int nt = 2 * ntp + jj;
                    const uint32_t b0 = jj ? kh4.z : kh4.x;
                    const uint32_t b1 = jj ? kh4.w : kh4.y;
                    const uint32_t c0 = jj ? kl4.z : kl4.x;
                    const uint32_t c1 = jj ? kl4.w : kl4.y;
#pragma unroll
                    for (int g = 0; g < 2; g++) {
                        mma_bf16(sacc[g][nt], (const uint32_t*)&qfh[g][kt], b0, b1);
                        mma_bf16(sacc[g][nt], (const uint32_t*)&qfh[g][kt], c0, c1);
                        mma_bf16(sacc[g][nt], (const uint32_t*)&qfl[g][kt], b0, b1);
                    }
                }
            }
        }

        // ---- softmax: p = 2^s; pack to bf16 P-fragments ----
        uint32_t pah[2][4][4], pal[2][4][4];
#pragma unroll
        for (int g = 0; g < 2; g++) {
#pragma unroll
            for (int nt = 0; nt < 8; nt++) {
                float* s4 = sacc[g][nt];
                s4[0] = ex2f(s4[0]);
                s4[1] = ex2f(s4[1]);
                s4[2] = ex2f(s4[2]);
                s4[3] = ex2f(s4[3]);
                lA[g] += s4[0] + s4[1];
                lB[g] += s4[2] + s4[3];
                const int kt = nt >> 1, i = nt & 1;
                uint32_t w0 = pack2(s4[0], s4[1]);
                uint32_t w1 = pack2(s4[2], s4[3]);
                pah[g][kt][2 * i]     = w0;
                pah[g][kt][2 * i + 1] = w1;
                __nv_bfloat162 b0 = *(__nv_bfloat162*)&w0;
                __nv_bfloat162 b1 = *(__nv_bfloat162*)&w1;
                float2 f0 = __bfloat1622float2(b0);
                float2 f1 = __bfloat1622float2(b1);
                pal[g][kt][2 * i]     = pack2(s4[0] - f0.x, s4[1] - f0.y);
                pal[g][kt][2 * i + 1] = pack2(s4[2] - f1.x, s4[3] - f1.y);
            }
        }

        // ---- O += P V ----
#pragma unroll
        for (int kt = 0; kt < 4; kt++) {          // token-tiles
#pragma unroll
            for (int ntp = 0; ntp < 4; ntp++) {   // d-tile16 pairs
                const int o = 4096 + (kt * 4 + ntp) * 128 + lane * 4;
                uint4 vh4 = *(const uint4*)(base + o);
                uint4 vl4 = *(const uint4*)(base + 2048 + o);
#pragma unroll
                for (int jj = 0; jj < 2; jj++) {
                    const int nt = 2 * ntp + jj;
                    const uint32_t b0 = jj ? vh4.z : vh4.x;
                    const uint32_t b1 = jj ? vh4.w : vh4.y;
                    const uint32_t c0 = jj ? vl4.z : vl4.x;
                    const uint32_t c1 = jj ? vl4.w : vl4.y;
#pragma unroll
                    for (int g = 0; g < 2; g++) {
                        mma_bf16(oacc[g][nt], pah[g][kt], b0, b1);
                        mma_bf16(oacc[g][nt], pah[g][kt], c0, c1);
                        mma_bf16(oacc[g][nt], pal[g][kt], b0, b1);
                    }
                }
            }
        }
        if (++stq == 3) stq = 0;
    }

    // ---- epilogue: y = O / (l*8), A-type frag-major store ----
#pragma unroll
    for (int g = 0; g < 2; g++) {
        float la = lA[g], lb = lB[g];
        la += __shfl_xor_sync(0xffffffffu, la, 1);
        la += __shfl_xor_sync(0xffffffffu, la, 2);
        lb += __shfl_xor_sync(0xffffffffu, lb, 1);
        lb += __shfl_xor_sync(0xffffffffu, lb, 2);
        const float invA = 1.0f / (la * 8.0f);
        const float invB = 1.0f / (lb * 8.0f);
        const int t = qa + g * 16 + gr;      // row gr; row gr+8 flips w bit0
        const int mtile = (b * TT + t) >> 4;
#pragma unroll
        for (int nt = 0; nt < 8; nt++) {
            const int ctile = h * 4 + (nt >> 1);
            const int a32 = ((mtile * 64 + ctile) * 32 + lane) * 4;
            const int w0 = 2 * (nt & 1);     // row gr
            float h0, l0, h1, l1;
            splitb(oacc[g][nt][0] * invA, h0, l0);
            splitb(oacc[g][nt][1] * invA, h1, l1);
            yh32[a32 + w0] = pack2(h0, h1);
            yl32[a32 + w0] = pack2(l0, l1);
            splitb(oacc[g][nt][2] * invB, h0, l0);
            splitb(oacc[g][nt][3] * invB, h1, l1);
            yh32[a32 + w0 + 1] = pack2(h0, h1);
            yl32[a32 + w0 + 1] = pack2(l0, l1);
        }
    }
}

// ---------------------------------------------------------------------------
extern "C" void kernel_launch(void* const* d_in, const int* in_sizes, int n_in,
                              void* d_out, int out_size)
{
    const float* x      = (const float*)d_in[0];
    const float* W_attn = (const float*)d_in[1];
    const float* b_attn = (const float*)d_in[2];
    const float* W_proj = (const float*)d_in[3];
    const float* b_proj = (const float*)d_in[4];
    float* out = (float*)d_out;

    bf16 *xh, *xl, *wth, *wtl, *wph, *wpl;
    bf16 *qhp, *qlp, *khp, *klp, *vthp, *vtlp, *yhp, *ylp;
    cudaGetSymbolAddress((void**)&xh,   g_xh);
    cudaGetSymbolAddress((void**)&xl,   g_xl);
    cudaGetSymbolAddress((void**)&wth,  g_wth);
    cudaGetSymbolAddress((void**)&wtl,  g_wtl);
    cudaGetSymbolAddress((void**)&wph,  g_wph);
    cudaGetSymbolAddress((void**)&wpl,  g_wpl);
    cudaGetSymbolAddress((void**)&qhp,  g_qh);
    cudaGetSymbolAddress((void**)&qlp,  g_ql);
    cudaGetSymbolAddress((void**)&khp,  g_kh);
    cudaGetSymbolAddress((void**)&klp,  g_kl);
    cudaGetSymbolAddress((void**)&vthp, g_vth);
    cudaGetSymbolAddress((void**)&vtlp, g_vtl);
    cudaGetSymbolAddress((void**)&yhp,  g_yh);
    cudaGetSymbolAddress((void**)&ylp,  g_yl);

    cudaFuncSetAttribute(gemm_split_kernel<0>,
                         cudaFuncAttributeMaxDynamicSharedMemorySize,
                         GEMM_SMEM_BYTES);
    cudaFuncSetAttribute(gemm_split_kernel<1>,
                         cudaFuncAttributeMaxDynamicSharedMemorySize,
                         GEMM_SMEM_BYTES);
    cudaFuncSetAttribute(attn_kernel,
                         cudaFuncAttributeMaxDynamicSharedMemorySize,
                         AT_SMEM_BYTES);

    // prepasses
    split_a_kernel<<<(NTOK * CC / 4 + 255) / 256, 256>>>(
        x, (uint32_t*)xh, (uint32_t*)xl, NTOK * CC / 4);
    tsp_b_kernel<<<dim3(C3 / 32, CC / 32), 256>>>(W_attn, wth, wtl, C3);
    tsp_b_kernel<<<dim3(CC / 32, CC / 32), 256>>>(W_proj, wph, wpl, CC);

    // 1) QKV GEMM + routing epilogue (Q scaled by log2e)
    gemm_split_kernel<1><<<dim3(C3 / 128, NTOK / 128), 256, GEMM_SMEM_BYTES>>>(
        NTOK, C3, CC, xh, xl, wth, wtl, b_attn,
        nullptr, (uint32_t*)qhp, (uint32_t*)qlp,
        (uint32_t*)khp, (uint32_t*)klp, vthp, vtlp);

    // 2) attention
    attn_kernel<<<dim3(TT / 128, BB * NH), 128, AT_SMEM_BYTES>>>(
        (const uint32_t*)qhp, (const uint32_t*)qlp, khp, klp, vthp, vtlp,
        (uint32_t*)yhp, (uint32_t*)ylp);

    // 3) proj GEMM
    gemm_split_kernel<0><<<dim3(CC / 128, NTOK / 128), 256, GEMM_SMEM_BYTES>>>(
        NTOK, CC, CC, yhp, ylp, wph, wpl, b_proj,
        out, nullptr, nullptr, nullptr, nullptr, nullptr, nullptr);
}

// round 12
// speedup vs baseline: 1.4118x; 1.0092x over previous
#include <cuda_runtime.h>
#include <cuda_bf16.h>
#include <cuda_fp16.h>
#include <math.h>
#include <stdint.h>

#define BB   2
#define TT   2048
#define CC   1024
#define NH   16
#define DH   64
#define NTOK (BB * TT)
#define C3   (3 * CC)
#define LOG2E 1.4426950408889634f

typedef __nv_bfloat16 bf16;

// ---------------------------------------------------------------------------
// Fragment-major layouts (16x16 tiles, 32 lanes x 16B):
//  A-type (row operand), lane(gr,tg):  w0=(row gr, kpair tg) w1=(row gr+8, tg)
//                                      w2=(row gr, tg+4)     w3=(row gr+8, tg+4)
//  B-type (col operand), lane(gr,tg):  w0=(col gr, kpair tg) w1=(col gr, tg+4)
//                                      w2=(col gr+8, tg)     w3=(col gr+8, tg+4)
// ---------------------------------------------------------------------------
__device__ bf16 g_xh[NTOK * CC],  g_xl[NTOK * CC];   // A-type
__device__ bf16 g_wth[C3 * CC],   g_wtl[C3 * CC];    // B-type
__device__ half g_wpfh[CC * CC],  g_wpfl[CC * CC];   // B-type fp16 (proj)
__device__ bf16 g_qh[NTOK * CC],  g_ql[NTOK * CC];   // A-type per (b,h)
__device__ bf16 g_kh[NTOK * CC],  g_kl[NTOK * CC];   // B-type per (b,h)
__device__ bf16 g_vth[NTOK * CC], g_vtl[NTOK * CC];  // B-type transposed
__device__ half g_yf[NTOK * CC];                     // A-type fp16 single

// ---------------------------------------------------------------------------
// helpers
// ---------------------------------------------------------------------------
__device__ __forceinline__ float bfr(float x) {
    return __bfloat162float(__float2bfloat16(x));
}
__device__ __forceinline__ void splitb(float x, float& h, float& l) {
    h = bfr(x);
    l = bfr(x - h);
}
__device__ __forceinline__ uint32_t pack2(float a, float b) {
    __nv_bfloat162 t = __floats2bfloat162_rn(a, b);
    return *(uint32_t*)&t;
}
__device__ __forceinline__ uint32_t pack2h(float a, float b) {
    __half2 t = __floats2half2_rn(a, b);
    return *(uint32_t*)&t;
}
__device__ __forceinline__ float ex2f(float x) {
    float y; asm("ex2.approx.f32 %0, %1;" : "=f"(y) : "f"(x)); return y;
}
__device__ __forceinline__ void mma_bf16(float* d, const uint32_t* a,
                                         uint32_t b0, uint32_t b1) {
    asm volatile(
        "mma.sync.aligned.m16n8k16.row.col.f32.bf16.bf16.f32 "
        "{%0,%1,%2,%3}, {%4,%5,%6,%7}, {%8,%9}, {%0,%1,%2,%3};"
        : "+f"(d[0]), "+f"(d[1]), "+f"(d[2]), "+f"(d[3])
        : "r"(a[0]), "r"(a[1]), "r"(a[2]), "r"(a[3]), "r"(b0), "r"(b1));
}
__device__ __forceinline__ void mma_f16(float* d, const uint32_t* a,
                                        uint32_t b0, uint32_t b1) {
    asm volatile(
        "mma.sync.aligned.m16n8k16.row.col.f32.f16.f16.f32 "
        "{%0,%1,%2,%3}, {%4,%5,%6,%7}, {%8,%9}, {%0,%1,%2,%3};"
        : "+f"(d[0]), "+f"(d[1]), "+f"(d[2]), "+f"(d[3])
        : "r"(a[0]), "r"(a[1]), "r"(a[2]), "r"(a[3]), "r"(b0), "r"(b1));
}
__device__ __forceinline__ void cp16(uint32_t d, const void* s) {
    asm volatile("cp.async.cg.shared.global [%0], [%1], 16;" :: "r"(d), "l"(s));
}
__device__ __forceinline__ void cp_commit() {
    asm volatile("cp.async.commit_group;");
}
template <int N> __device__ __forceinline__ void cp_wait() {
    asm volatile("cp.async.wait_group %0;" :: "n"(N));
}

// ---------------------------------------------------------------------------
// prepass 1: x -> A-type frag-major bf16 hi/lo
// ---------------------------------------------------------------------------
__global__ void __launch_bounds__(256) split_a_kernel(
    const float* __restrict__ in, uint32_t* __restrict__ oh,
    uint32_t* __restrict__ ol, int n4)
{
    const int i4 = blockIdx.x * 256 + threadIdx.x;
    if (i4 >= n4) return;
    const int g = i4 * 4;
    const int m = g >> 10, k0 = g & 1023;
    float4 v = *(const float4*)&in[g];

    const int r = m & 15, gr = r & 7, hi = (r >> 3) & 1;
    const int tile = ((m >> 4) << 6) + (k0 >> 4);
    const int p0 = (k0 & 15) >> 1;
#pragma unroll
    for (int q = 0; q < 2; q++) {
        const int p = p0 + q;
        const int lane = gr * 4 + (p & 3);
        const int w = hi + 2 * (p >> 2);
        const int a32 = (tile * 32 + lane) * 4 + w;
        float e0 = q ? v.z : v.x, e1 = q ? v.w : v.y;
        float h0, l0, h1, l1;
        splitb(e0, h0, l0);
        splitb(e1, h1, l1);
        oh[a32] = pack2(h0, h1);
        ol[a32] = pack2(l0, l1);
    }
}

// ---------------------------------------------------------------------------
// prepass 2a: W_attn[K][N] -> B-type frag-major bf16 hi/lo
// ---------------------------------------------------------------------------
__global__ void __launch_bounds__(256) tsp_b_kernel(
    const float* __restrict__ W, bf16* __restrict__ oh,
    bf16* __restrict__ ol, int N)
{
    __shared__ float t[32][33];
    const int bx = blockIdx.x * 32;
    const int by = blockIdx.y * 32;
    const int tx = threadIdx.x & 31, ty = threadIdx.x >> 5;
#pragma unroll
    for (int j = 0; j < 32; j += 8)
        t[ty + j][tx] = W[(long)(by + ty + j) * N + bx + tx];
    __syncthreads();
    const int k = by + tx;
    const int ki = k >> 4, kk = k & 15, p = kk >> 1, e = kk & 1;
#pragma unroll
    for (int j = 0; j < 32; j += 8) {
        const int n = bx + ty + j;
        const int c = n & 15;
        const int lane = (c & 7) * 4 + (p & 3);
        const int w = ((c >> 3) & 1) * 2 + (p >> 2);
        const long flat = ((long)(((n >> 4) << 6) + ki) * 32 + lane) * 8 + w * 2 + e;
        float h, l;
        splitb(t[tx][ty + j], h, l);
        oh[flat] = __float2bfloat16(h);
        ol[flat] = __float2bfloat16(l);
    }
}

// ---------------------------------------------------------------------------
// prepass 2b: W_proj[K][N] -> B-type frag-major FP16 hi/lo
// ---------------------------------------------------------------------------
__global__ void __launch_bounds__(256) tsp_b_f16_kernel(
    const float* __restrict__ W, half* __restrict__ oh,
    half* __restrict__ ol, int N)
{
    __shared__ float t[32][33];
    const int bx = blockIdx.x * 32;
    const int by = blockIdx.y * 32;
    const int tx = threadIdx.x & 31, ty = threadIdx.x >> 5;
#pragma unroll
    for (int j = 0; j < 32; j += 8)
        t[ty + j][tx] = W[(long)(by + ty + j) * N + bx + tx];
    __syncthreads();
    const int k = by + tx;
    const int ki = k >> 4, kk = k & 15, p = kk >> 1, e = kk & 1;
#pragma unroll
    for (int j = 0; j < 32; j += 8) {
        const int n = bx + ty + j;
        const int c = n & 15;
        const int lane = (c & 7) * 4 + (p & 3);
        const int w = ((c >> 3) & 1) * 2 + (p >> 2);
        const long flat = ((long)(((n >> 4) << 6) + ki) * 32 + lane) * 8 + w * 2 + e;
        const float v = t[tx][ty + j];
        half hh = __float2half_rn(v);
        half ll = __float2half_rn(v - __half2float(hh));
        oh[flat] = hh;
        ol[flat] = ll;
    }
}

// ---------------------------------------------------------------------------
// QKV GEMM (3xBF16): 256 thr, 8 warps (2x4), warp 64x32, CTA 128x128,
// BK=32, 3-stage cp.async, frag-major LDS.128.
// stage (words): AH 0 | AL 2048 | BH 4096 | BL 6144 = 8192 w
// ---------------------------------------------------------------------------
#define GW_STAGE 8192
#define GEMM_SMEM_BYTES (3 * GW_STAGE * 4)

__device__ __forceinline__ void gemm_stage_cp(
    uint32_t sb, int s, int tid,
    const bf16* __restrict__ Agh, const bf16* __restrict__ Agl,
    const bf16* __restrict__ Bgh, const bf16* __restrict__ Bgl,
    int mt0, int nt0, int kt0)
{
#pragma unroll
    for (int i = 0; i < 2; i++) {
        const int c = tid + i * 256;
        const int kt2 = c >> 8, t8 = (c >> 5) & 7, lane = c & 31;
        const uint32_t w = (uint32_t)(s * GW_STAGE + (kt2 * 8 + t8) * 128 + lane * 4);
        const long ga = ((long)((mt0 + t8) * 64 + kt0 + kt2) * 32 + lane) * 8;
        const long gb = ((long)((nt0 + t8) * 64 + kt0 + kt2) * 32 + lane) * 8;
        cp16(sb + w * 4,          &Agh[ga]);
        cp16(sb + (w + 2048) * 4, &Agl[ga]);
        cp16(sb + (w + 4096) * 4, &Bgh[gb]);
        cp16(sb + (w + 6144) * 4, &Bgl[gb]);
    }
    cp_commit();
}

__global__ void __launch_bounds__(256, 2) gemm_qkv_kernel(
    int M, int N, int K,
    const bf16* __restrict__ Agh, const bf16* __restrict__ Agl,
    const bf16* __restrict__ Bgh, const bf16* __restrict__ Bgl,
    const float* __restrict__ bias,
    uint32_t* __restrict__ qh32, uint32_t* __restrict__ ql32,
    uint32_t* __restrict__ kh32, uint32_t* __restrict__ kl32,
    bf16* __restrict__ vth, bf16* __restrict__ vtl)
{
    extern __shared__ uint32_t smw[];
    const uint32_t sb = (uint32_t)__cvta_generic_to_shared(smw);

    const int tid  = threadIdx.x;
    const int wid  = tid >> 5, lane = tid & 31;
    const int gr   = lane >> 2, tg = lane & 3;
    const int wr   = wid >> 2,  wc = wid & 3;
    const int m0   = blockIdx.y * 128;
    const int n0   = blockIdx.x * 128;
    const int mt0  = m0 >> 4, nt0 = n0 >> 4;

    float acc[4][4][4];
#pragma unroll
    for (int i = 0; i < 4; i++)
#pragma unroll
        for (int j = 0; j < 4; j++)
#pragma unroll
            for (int r = 0; r < 4; r++) acc[i][j][r] = 0.f;

    const int nIter = K / 32;
    gemm_stage_cp(sb, 0, tid, Agh, Agl, Bgh, Bgl, mt0, nt0, 0);
    gemm_stage_cp(sb, 1, tid, Agh, Agl, Bgh, Bgl, mt0, nt0, 2);

    int stq = 0;
    for (int it = 0; it < nIter; it++) {
        if (it + 1 < nIter) cp_wait<1>(); else cp_wait<0>();
        __syncthreads();
        if (it + 2 < nIter) {
            int s2 = stq + 2; if (s2 >= 3) s2 -= 3;
            gemm_stage_cp(sb, s2, tid, Agh, Agl, Bgh, Bgl,
                          mt0, nt0, (it + 2) * 2);
        }

        const uint32_t* base = smw + stq * GW_STAGE;
#pragma unroll
        for (int ks = 0; ks < 2; ks++) {
            uint4 afh[4], afl[4];
#pragma unroll
            for (int mt = 0; mt < 4; mt++) {
                const int o = (ks * 8 + wr * 4 + mt) * 128 + lane * 4;
                afh[mt] = *(const uint4*)(base + o);
                afl[mt] = *(const uint4*)(base + 2048 + o);
            }
#pragma unroll
            for (int j = 0; j < 2; j++) {
                const int o = (ks * 8 + wc * 2 + j) * 128 + lane * 4;
                uint4 bh4 = *(const uint4*)(base + 4096 + o);
                uint4 bl4 = *(const uint4*)(base + 6144 + o);
#pragma unroll
                for (int jj = 0; jj < 2; jj++) {
                    const int nt = 2 * j + jj;
                    const uint32_t b0 = jj ? bh4.z : bh4.x;
                    const uint32_t b1 = jj ? bh4.w : bh4.y;
                    const uint32_t c0 = jj ? bl4.z : bl4.x;
                    const uint32_t c1 = jj ? bl4.w : bl4.y;
#pragma unroll
                    for (int mt = 0; mt < 4; mt++) {
                        mma_bf16(acc[mt][nt], (const uint32_t*)&afh[mt], b0, b1);
                        mma_bf16(acc[mt][nt], (const uint32_t*)&afh[mt], c0, c1);
                        mma_bf16(acc[mt][nt], (const uint32_t*)&afl[mt], b0, b1);
                    }
                }
            }
        }
        if (++stq == 3) stq = 0;
    }

    // ---- routing epilogue ----
#pragma unroll
    for (int nt = 0; nt < 4; nt++) {
        const int col = n0 + wc * 32 + nt * 8 + tg * 2;
        const float2 bv = *(const float2*)&bias[col];
#pragma unroll
        for (int mt = 0; mt < 4; mt++) {
            const int row = m0 + wr * 64 + mt * 16 + gr;
            const float v00 = acc[mt][nt][0] + bv.x;
            const float v01 = acc[mt][nt][1] + bv.y;
            const float v10 = acc[mt][nt][2] + bv.x;
            const float v11 = acc[mt][nt][3] + bv.y;
            const int sec = col >> 10;
            const int dc  = col & 1023;
            const int hh  = dc >> 6, d0 = dc & 63;
#pragma unroll
            for (int rr = 0; rr < 2; rr++) {
                const int m = row + rr * 8;
                const int b = m >> 11, t = m & 2047;
                float u0 = rr ? v10 : v00;
                float u1 = rr ? v11 : v01;
                float h0, l0, h1, l1;
                if (sec == 0) {
                    u0 *= LOG2E; u1 *= LOG2E;
                    splitb(u0, h0, l0); splitb(u1, h1, l1);
                    const int lane_ = (t & 7) * 4 + ((d0 >> 1) & 3);
                    const int w = ((t >> 3) & 1) + 2 * ((d0 >> 3) & 1);
                    const int tile = ((b * NH + hh) * 128 + (t >> 4)) * 4 + (d0 >> 4);
                    const int a32 = (tile * 32 + lane_) * 4 + w;
                    qh32[a32] = pack2(h0, h1);
                    ql32[a32] = pack2(l0, l1);
                } else if (sec == 1) {
                    splitb(u0, h0, l0); splitb(u1, h1, l1);
                    const int lane_ = (t & 7) * 4 + ((d0 >> 1) & 3);
                    const int w = ((t >> 3) & 1) * 2 + ((d0 >> 3) & 1);
                    const int tile = ((b * NH + hh) * 128 + (t >> 4)) * 4 + (d0 >> 4);
                    const int a32 = (tile * 32 + lane_) * 4 + w;
                    kh32[a32] = pack2(h0, h1);
                    kl32[a32] = pack2(l0, l1);
                } else {
                    splitb(u0, h0, l0); splitb(u1, h1, l1);
                    const int lane_ = (d0 & 7) * 4 + ((t >> 1) & 3);
                    const int w = ((d0 >> 3) & 1) * 2 + ((t >> 3) & 1);
                    const int tile = ((b * NH + hh) * 4 + (d0 >> 4)) * 128 + (t >> 4);
                    const long f = ((long)tile * 32 + lane_) * 8 + w * 2 + (t & 1);
                    vth[f] = __float2bfloat16(h0);
                    vtl[f] = __float2bfloat16(l0);
                    vth[f + 32] = __float2bfloat16(h1);
                    vtl[f + 32] = __float2bfloat16(l1);
                }
            }
        }
    }
}

// ---------------------------------------------------------------------------
// PROJ GEMM (fp16 2-term): out = yf @ Wp^T + bias.
// A = yf single fp16 plane, B = fp16 hi/lo. 256 thr, warp 64x32.
// stage (words): A 0 | BH 2048 | BL 4096 = 6144 w = 24KB
// ---------------------------------------------------------------------------
#define PW_STAGE 6144
#define PROJ_SMEM_BYTES (3 * PW_STAGE * 4)

__device__ __forceinline__ void proj_stage_cp(
    uint32_t sb, int s, int tid,
    const half* __restrict__ Af,
    const half* __restrict__ Bh, const half* __restrict__ Bl,
    int mt0, int nt0, int kt0)
{
#pragma unroll
    for (int i = 0; i < 2; i++) {     // A: chunks 0..511
        const int c = tid + i * 256;
        const int kt2 = c >> 8, t8 = (c >> 5) & 7, lane = c & 31;
        const uint32_t w = (uint32_t)(s * PW_STAGE + (kt2 * 8 + t8) * 128 + lane * 4);
        const long ga = ((long)((mt0 + t8) * 64 + kt0 + kt2) * 32 + lane) * 8;
        cp16(sb + w * 4, &Af[ga]);
    }
#pragma unroll
    for (int i = 0; i < 2; i++) {     // BH
        const int c = tid + i * 256;
        const int kt2 = c >> 8, t8 = (c >> 5) & 7, lane = c & 31;
        const uint32_t w = (uint32_t)(s * PW_STAGE + 2048 + (kt2 * 8 + t8) * 128 + lane * 4);
        const long gb = ((long)((nt0 + t8) * 64 + kt0 + kt2) * 32 + lane) * 8;
        cp16(sb + w * 4, &Bh[gb]);
    }
#pragma unroll
    for (int i = 0; i < 2; i++) {     // BL
        const int c = tid + i * 256;
        const int kt2 = c >> 8, t8 = (c >> 5) & 7, lane = c & 31;
        const uint32_t w = (uint32_t)(s * PW_STAGE + 4096 + (kt2 * 8 + t8) * 128 + lane * 4);
        const long gb = ((long)((nt0 + t8) * 64 + kt0 + kt2) * 32 + lane) * 8;
        cp16(sb + w * 4, &Bl[gb]);
    }
    cp_commit();
}

__global__ void __launch_bounds__(256, 2) gemm_proj_kernel(
    int M, int N, int K,
    const half* __restrict__ Af,
    const half* __restrict__ Bh, const half* __restrict__ Bl,
    const float* __restrict__ bias, float* __restrict__ C)
{
    extern __shared__ uint32_t smw[];
    const uint32_t sb = (uint32_t)__cvta_generic_to_shared(smw);

    const int tid  = threadIdx.x;
    const int wid  = tid >> 5, lane = tid & 31;
    const int gr   = lane >> 2, tg = lane & 3;
    const int wr   = wid >> 2,  wc = wid & 3;
    const int m0   = blockIdx.y * 128;
    const int n0   = blockIdx.x * 128;
    const int mt0  = m0 >> 4, nt0 = n0 >> 4;

    float acc[4][4][4];
#pragma unroll
    for (int i = 0; i < 4; i++)
#pragma unroll
        for (int j = 0; j < 4; j++)
#pragma unroll
            for (int r = 0; r < 4; r++) acc[i][j][r] = 0.f;

    const int nIter = K / 32;
    proj_stage_cp(sb, 0, tid, Af, Bh, Bl, mt0, nt0, 0);
    proj_stage_cp(sb, 1, tid, Af, Bh, Bl, mt0, nt0, 2);

    int stq = 0;
    for (int it = 0; it < nIter; it++) {
        if (it + 1 < nIter) cp_wait<1>(); else cp_wait<0>();
        __syncthreads();
        if (it + 2 < nIter) {
            int s2 = stq + 2; if (s2 >= 3) s2 -= 3;
            proj_stage_cp(sb, s2, tid, Af, Bh, Bl, mt0, nt0, (it + 2) * 2);
        }

        const uint32_t* base = smw + stq * PW_STAGE;
#pragma unroll
        for (int ks = 0; ks < 2; ks++) {
            uint4 af[4];
#pragma unroll
            for (int mt = 0; mt < 4; mt++) {
                const int o = (ks * 8 + wr * 4 + mt) * 128 + lane * 4;
                af[mt] = *(const uint4*)(base + o);
            }
#pragma unroll
            for (int j = 0; j < 2; j++) {
                const int o = (ks * 8 + wc * 2 + j) * 128 + lane * 4;
                uint4 bh4 = *(const uint4*)(base + 2048 + o);
                uint4 bl4 = *(const uint4*)(base + 4096 + o);
#pragma unroll
                for (int jj = 0; jj < 2; jj++) {
                    const int nt = 2 * j + jj;
                    const uint32_t b0 = jj ? bh4.z : bh4.x;
                    const uint32_t b1 = jj ? bh4.w : bh4.y;
                    const uint32_t c0 = jj ? bl4.z : bl4.x;
                    const uint32_t c1 = jj ? bl4.w : bl4.y;
#pragma unroll
                    for (int mt = 0; mt < 4; mt++) {
                        mma_f16(acc[mt][nt], (const uint32_t*)&af[mt], b0, b1);
                        mma_f16(acc[mt][nt], (const uint32_t*)&af[mt], c0, c1);
                    }
                }
            }
        }
        if (++stq == 3) stq = 0;
    }

#pragma unroll
    for (int nt = 0; nt < 4; nt++) {
        const int col = n0 + wc * 32 + nt * 8 + tg * 2;
        const float2 bv = *(const float2*)&bias[col];
#pragma unroll
        for (int mt = 0; mt < 4; mt++) {
            const int row = m0 + wr * 64 + mt * 16 + gr;
            *(float2*)&C[(long)row * N + col] =
                make_float2(acc[mt][nt][0] + bv.x, acc[mt][nt][1] + bv.y);
            *(float2*)&C[(long)(row + 8) * N + col] =
                make_float2(acc[mt][nt][2] + bv.x, acc[mt][nt][3] + bv.y);
        }
    }
}

// ---------------------------------------------------------------------------
// Attention: 256 thr (8 warps), warp = ONE 16-row q-group, BQ=128, BK=64,
// 3-stage cp.async, frag-major LDS.128, Q reloaded per j-tile (L1-resident),
// P in registers, PV 3-term bf16. 2 CTAs/SM -> 16 warps.
// stage (words): KH 0 | KL 2048 | VTH 4096 | VTL 6144 = 8192 w
// ---------------------------------------------------------------------------
#define AW_STAGE 8192
#define AT_SMEM_BYTES (3 * AW_STAGE * 4)

__device__ __forceinline__ void attn_stage_cp(
    uint32_t sb, int s, int tid, int bh32,
    const bf16* __restrict__ kh, const bf16* __restrict__ kl,
    const bf16* __restrict__ vth, const bf16* __restrict__ vtl,
    int jt0)
{
#pragma unroll
    for (int q = 0; q < 2; q++) {
        const int c = q * 256 + tid;          // 0..511
        const int dt = c >> 7, tt = (c >> 5) & 3, lane = c & 31;
        const long gk = ((long)((bh32 * 128 + jt0 + tt) * 4 + dt) * 32 + lane) * 8;
        const long gv = ((long)((bh32 * 4 + dt) * 128 + jt0 + tt) * 32 + lane) * 8;
        const uint32_t wk = (uint32_t)(s * AW_STAGE + (dt * 4 + tt) * 128 + lane * 4);
        const uint32_t wv = (uint32_t)(s * AW_STAGE + 4096 + (tt * 4 + dt) * 128 + lane * 4);
        cp16(sb + wk * 4,          &kh[gk]);
        cp16(sb + (wk + 2048) * 4, &kl[gk]);
        cp16(sb + wv * 4,          &vth[gv]);
        cp16(sb + (wv + 2048) * 4, &vtl[gv]);
    }
    cp_commit();
}

__global__ void __launch_bounds__(256, 2) attn_kernel(
    const uint32_t* __restrict__ qh32, const uint32_t* __restrict__ ql32,
    const bf16* __restrict__ kh, const bf16* __restrict__ kl,
    const bf16* __restrict__ vth, const bf16* __restrict__ vtl,
    uint32_t* __restrict__ yf32)
{
    extern __shared__ uint32_t smw[];
    const uint32_t sb = (uint32_t)__cvta_generic_to_shared(smw);

    const int tid  = threadIdx.x;
    const int wid  = tid >> 5, lane = tid & 31;
    const int gr   = lane >> 2, tg = lane & 3;
    const int bh32 = blockIdx.y;
    const int b    = bh32 >> 4, h = bh32 & 15;
    const int qa   = blockIdx.x * 128 + wid * 16;
    const int qt   = bh32 * 128 + (qa >> 4);   // Q tile16 index

    attn_stage_cp(sb, 0, tid, bh32, kh, kl, vth, vtl, 0);
    attn_stage_cp(sb, 1, tid, bh32, kh, kl, vth, vtl, 4);

    float oacc[8][4];
#pragma unroll
    for (int nt = 0; nt < 8; nt++)
#pragma unroll
        for (int r = 0; r < 4; r++) oacc[nt][r] = 0.f;
    float lA = 0.f, lB = 0.f;

    int stq = 0;
    for (int jt = 0; jt < 32; jt++) {
        if (jt + 1 < 32) cp_wait<1>(); else cp_wait<0>();
        __syncthreads();
        if (jt + 2 < 32) {
            int s2 = stq + 2; if (s2 >= 3) s2 -= 3;
            attn_stage_cp(sb, s2, tid, bh32, kh, kl, vth, vtl, (jt + 2) * 4);
        }
        const uint32_t* base = smw + stq * AW_STAGE;

        // Q fragments (L1-resident reload)
        uint4 qfh[4], qfl[4];
#pragma unroll
        for (int kt = 0; kt < 4; kt++) {
            const int a = ((qt * 4 + kt) * 32 + lane) * 4;
            qfh[kt] = *(const uint4*)(qh32 + a);
            qfl[kt] = *(const uint4*)(ql32 + a);
        }

        // ---- S = Q K^T (3xBF16) ----
        float sacc[8][4];
#pragma unroll
        for (int nt = 0; nt < 8; nt++)
#pragma unroll
            for (int r = 0; r < 4; r++) sacc[nt][r] = 0.f;

#pragma unroll
        for (int kt = 0; kt < 4; kt++) {
#pragma unroll
            for (int ntp = 0; ntp < 4; ntp++) {
                const int o = (kt * 4 + ntp) * 128 + lane * 4;
                uint4 kh4 = *(const uint4*)(base + o);
                uint4 kl4 = *(const uint4*)(base + 2048 + o);
#pragma unroll
                for (int jj = 0; jj < 2; jj++) {
                    const int nt = 2 * ntp + jj;
                    const uint32_t b0 = jj ? kh4.z : kh4.x;
                    const uint32_t b1 = jj ? kh4.w : kh4.y;
                    const uint32_t c0 = jj ? kl4.z : kl4.x;
                    const uint32_t c1 = jj ? kl4.w : kl4.y;
                    mma_bf16(sacc[nt], (const uint32_t*)&qfh[kt], b0, b1);
                    mma_bf16(sacc[nt], (const uint32_t*)&qfh[kt], c0, c1);
                    mma_bf16(sacc[nt], (const uint32_t*)&qfl[kt], b0, b1);
                }
            }
        }

        // ---- softmax: p = 2^s; pack to bf16 P-fragments ----
        uint32_t pah[4][4], pal[4][4];
#pragma unroll
        for (int nt = 0; nt < 8; nt++) {
            float* s4 = sacc[nt];
            s4[0] = ex2f(s4[0]);
            s4[1] = ex2f(s4[1]);
            s4[2] = ex2f(s4[2]);
            s4[3] = ex2f(s4[3]);
            lA += s4[0] + s4[1];
            lB += s4[2] + s4[3];
            const int kt = nt >> 1, i = nt & 1;
            uint32_t w0 = pack2(s4[0], s4[1]);
            uint32_t w1 = pack2(s4[2], s4[3]);
            pah[kt][2 * i]     = w0;
            pah[kt][2 * i + 1] = w1;
            __nv_bfloat162 b0 = *(__nv_bfloat162*)&w0;
            __nv_bfloat162 b1 = *(__nv_bfloat162*)&w1;
            float2 f0 = __bfloat1622float2(b0);
            float2 f1 = __bfloat1622float2(b1);
            pal[kt][2 * i]     = pack2(s4[0] - f0.x, s4[1] - f0.y);
            pal[kt][2 * i + 1] = pack2(s4[2] - f1.x, s4[3] - f1.y);
        }

        // ---- O += P V ----
#pragma unroll
        for (int kt = 0; kt < 4; kt++) {
#pragma unroll
            for (int ntp = 0; ntp < 4; ntp++) {
                const int o = 4096 + (kt * 4 + ntp) * 128 + lane * 4;
                uint4 vh4 = *(const uint4*)(base + o);
                uint4 vl4 = *(const uint4*)(base + 2048 + o);
#pragma unroll
                for (int jj = 0; jj < 2; jj++) {
                    const int nt = 2 * ntp + jj;
                    const uint32_t b0 = jj ? vh4.z : vh4.x;
                    const uint32_t b1 = jj ? vh4.w : vh4.y;
                    const uint32_t c0 = jj ? vl4.z : vl4.x;
                    const uint32_t c1 = jj ? vl4.w : vl4.y;
                    mma_bf16(oacc[nt], pah[kt], b0, b1);
                    mma_bf16(oacc[nt], pah[kt], c0, c1);
                    mma_bf16(oacc[nt], pal[kt], b0, b1);
                }
            }
        }
        if (++stq == 3) stq = 0;
    }

    // reductions + fp16 single-plane epilogue
    lA += __shfl_xor_sync(0xffffffffu, lA, 1);
    lA += __shfl_xor_sync(0xffffffffu, lA, 2);
    lB += __shfl_xor_sync(0xffffffffu, lB, 1);
    lB += __shfl_xor_sync(0xffffffffu, lB, 2);
    const float invA = 1.0f / (lA * 8.0f);
    const float invB = 1.0f / (lB * 8.0f);
    const int t = qa + gr;
    const int mtile = (b * TT + t) >> 4;
#pragma unroll
    for (int nt = 0; nt < 8; nt++) {
        const int ctile = h * 4 + (nt >> 1);
        const int a32 = ((mtile * 64 + ctile) * 32 + lane) * 4;
        const int w0 = 2 * (nt & 1);
        yf32[a32 + w0]     = pack2h(oacc[nt][0] * invA, oacc[nt][1] * invA);
        yf32[a32 + w0 + 1] = pack2h(oacc[nt][2] * invB, oacc[nt][3] * invB);
    }
}

// ---------------------------------------------------------------------------
extern "C" void kernel_launch(void* const* d_in, const int* in_sizes, int n_in,
                              void* d_out, int out_size)
{
    const float* x      = (const float*)d_in[0];
    const float* W_attn = (const float*)d_in[1];
    const float* b_attn = (const float*)d_in[2];
    const float* W_proj = (const float*)d_in[3];
    const float* b_proj = (const float*)d_in[4];
    float* out = (float*)d_out;

    bf16 *xh, *xl, *wth, *wtl;
    bf16 *qhp, *qlp, *khp, *klp, *vthp, *vtlp;
    half *wpfh, *wpfl, *yf;
    cudaGetSymbolAddress((void**)&xh,   g_xh);
    cudaGetSymbolAddress((void**)&xl,   g_xl);
    cudaGetSymbolAddress((void**)&wth,  g_wth);
    cudaGetSymbolAddress((void**)&wtl,  g_wtl);
    cudaGetSymbolAddress((void**)&wpfh, g_wpfh);
    cudaGetSymbolAddress((void**)&wpfl, g_wpfl);
    cudaGetSymbolAddress((void**)&qhp,  g_qh);
    cudaGetSymbolAddress((void**)&qlp,  g_ql);
    cudaGetSymbolAddress((void**)&khp,  g_kh);
    cudaGetSymbolAddress((void**)&klp,  g_kl);
    cudaGetSymbolAddress((void**)&vthp, g_vth);
    cudaGetSymbolAddress((void**)&vtlp, g_vtl);
    cudaGetSymbolAddress((void**)&yf,   g_yf);

    cudaFuncSetAttribute(gemm_qkv_kernel,
                         cudaFuncAttributeMaxDynamicSharedMemorySize,
                         GEMM_SMEM_BYTES);
    cudaFuncSetAttribute(gemm_proj_kernel,
                         cudaFuncAttributeMaxDynamicSharedMemorySize,
                         PROJ_SMEM_BYTES);
    cudaFuncSetAttribute(attn_kernel,
                         cudaFuncAttributeMaxDynamicSharedMemorySize,
                         AT_SMEM_BYTES);

    // prepasses
    split_a_kernel<<<(NTOK * CC / 4 + 255) / 256, 256>>>(
        x, (uint32_t*)xh, (uint32_t*)xl, NTOK * CC / 4);
    tsp_b_kernel<<<dim3(C3 / 32, CC / 32), 256>>>(W_attn, wth, wtl, C3);
    tsp_b_f16_kernel<<<dim3(CC / 32, CC / 32), 256>>>(W_proj, wpfh, wpfl, CC);

    // 1) QKV GEMM + routing epilogue (Q scaled by log2e)
    gemm_qkv_kernel<<<dim3(C3 / 128, NTOK / 128), 256, GEMM_SMEM_BYTES>>>(
        NTOK, C3, CC, xh, xl, wth, wtl, b_attn,
        (uint32_t*)qhp, (uint32_t*)qlp, (uint32_t*)khp, (uint32_t*)klp,
        vthp, vtlp);

    // 2) attention
    attn_kernel<<<dim3(TT / 128, BB * NH), 256, AT_SMEM_BYTES>>>(
        (const uint32_t*)qhp, (const uint32_t*)qlp, khp, klp, vthp, vtlp,
        (uint32_t*)yf);

    // 3) proj GEMM (fp16 2-term)
    gemm_proj_kernel<<<dim3(CC / 128, NTOK / 128), 256, PROJ_SMEM_BYTES>>>(
        NTOK, CC, CC, yf, wpfh, wpfl, b_proj, out);
}

// round 13
// speedup vs baseline: 1.4212x; 1.0066x over previous
#include <cuda_runtime.h>
#include <cuda_bf16.h>
#include <cuda_fp16.h>
#include <math.h>
#include <stdint.h>

#define BB   2
#define TT   2048
#define CC   1024
#define NH   16
#define DH   64
#define NTOK (BB * TT)
#define C3   (3 * CC)
#define LOG2E 1.4426950408889634f

typedef __nv_bfloat16 bf16;

// ---------------------------------------------------------------------------
// Fragment-major layouts (16x16 tiles, 32 lanes x 16B) — see round 11 notes.
// ---------------------------------------------------------------------------
__device__ bf16 g_xh[NTOK * CC],  g_xl[NTOK * CC];   // A-type
__device__ bf16 g_wth[C3 * CC],   g_wtl[C3 * CC];    // B-type
__device__ half g_wpfh[CC * CC],  g_wpfl[CC * CC];   // B-type fp16 (proj)
__device__ bf16 g_qh[NTOK * CC],  g_ql[NTOK * CC];   // A-type per (b,h)
__device__ bf16 g_kh[NTOK * CC],  g_kl[NTOK * CC];   // B-type per (b,h)
__device__ bf16 g_vth[NTOK * CC], g_vtl[NTOK * CC];  // B-type transposed
__device__ half g_yf[NTOK * CC];                     // A-type fp16 single

// ---------------------------------------------------------------------------
// helpers
// ---------------------------------------------------------------------------
__device__ __forceinline__ float bfr(float x) {
    return __bfloat162float(__float2bfloat16(x));
}
__device__ __forceinline__ void splitb(float x, float& h, float& l) {
    h = bfr(x);
    l = bfr(x - h);
}
__device__ __forceinline__ uint32_t pack2(float a, float b) {
    __nv_bfloat162 t = __floats2bfloat162_rn(a, b);
    return *(uint32_t*)&t;
}
__device__ __forceinline__ uint32_t pack2h(float a, float b) {
    __half2 t = __floats2half2_rn(a, b);
    return *(uint32_t*)&t;
}
__device__ __forceinline__ float ex2f(float x) {
    float y; asm("ex2.approx.f32 %0, %1;" : "=f"(y) : "f"(x)); return y;
}
__device__ __forceinline__ void mma_bf16(float* d, const uint32_t* a,
                                         uint32_t b0, uint32_t b1) {
    asm volatile(
        "mma.sync.aligned.m16n8k16.row.col.f32.bf16.bf16.f32 "
        "{%0,%1,%2,%3}, {%4,%5,%6,%7}, {%8,%9}, {%0,%1,%2,%3};"
        : "+f"(d[0]), "+f"(d[1]), "+f"(d[2]), "+f"(d[3])
        : "r"(a[0]), "r"(a[1]), "r"(a[2]), "r"(a[3]), "r"(b0), "r"(b1));
}
__device__ __forceinline__ void mma_f16(float* d, const uint32_t* a,
                                        uint32_t b0, uint32_t b1) {
    asm volatile(
        "mma.sync.aligned.m16n8k16.row.col.f32.f16.f16.f32 "
        "{%0,%1,%2,%3}, {%4,%5,%6,%7}, {%8,%9}, {%0,%1,%2,%3};"
        : "+f"(d[0]), "+f"(d[1]), "+f"(d[2]), "+f"(d[3])
        : "r"(a[0]), "r"(a[1]), "r"(a[2]), "r"(a[3]), "r"(b0), "r"(b1));
}
__device__ __forceinline__ void cp16(uint32_t d, const void* s) {
    asm volatile("cp.async.cg.shared.global [%0], [%1], 16;" :: "r"(d), "l"(s));
}
__device__ __forceinline__ void cp_commit() {
    asm volatile("cp.async.commit_group;");
}
template <int N> __device__ __forceinline__ void cp_wait() {
    asm volatile("cp.async.wait_group %0;" :: "n"(N));
}

// ---------------------------------------------------------------------------
// prepass 1: x -> A-type frag-major bf16 hi/lo
// ---------------------------------------------------------------------------
__global__ void __launch_bounds__(256) split_a_kernel(
    const float* __restrict__ in, uint32_t* __restrict__ oh,
    uint32_t* __restrict__ ol, int n4)
{
    const int i4 = blockIdx.x * 256 + threadIdx.x;
    if (i4 >= n4) return;
    const int g = i4 * 4;
    const int m = g >> 10, k0 = g & 1023;
    float4 v = *(const float4*)&in[g];

    const int r = m & 15, gr = r & 7, hi = (r >> 3) & 1;
    const int tile = ((m >> 4) << 6) + (k0 >> 4);
    const int p0 = (k0 & 15) >> 1;
#pragma unroll
    for (int q = 0; q < 2; q++) {
        const int p = p0 + q;
        const int lane = gr * 4 + (p & 3);
        const int w = hi + 2 * (p >> 2);
        const int a32 = (tile * 32 + lane) * 4 + w;
        float e0 = q ? v.z : v.x, e1 = q ? v.w : v.y;
        float h0, l0, h1, l1;
        splitb(e0, h0, l0);
        splitb(e1, h1, l1);
        oh[a32] = pack2(h0, h1);
        ol[a32] = pack2(l0, l1);
    }
}

// ---------------------------------------------------------------------------
// prepass 2a: W_attn[K][N] -> B-type frag-major bf16 hi/lo
// ---------------------------------------------------------------------------
__global__ void __launch_bounds__(256) tsp_b_kernel(
    const float* __restrict__ W, bf16* __restrict__ oh,
    bf16* __restrict__ ol, int N)
{
    __shared__ float t[32][33];
    const int bx = blockIdx.x * 32;
    const int by = blockIdx.y * 32;
    const int tx = threadIdx.x & 31, ty = threadIdx.x >> 5;
#pragma unroll
    for (int j = 0; j < 32; j += 8)
        t[ty + j][tx] = W[(long)(by + ty + j) * N + bx + tx];
    __syncthreads();
    const int k = by + tx;
    const int ki = k >> 4, kk = k & 15, p = kk >> 1, e = kk & 1;
#pragma unroll
    for (int j = 0; j < 32; j += 8) {
        const int n = bx + ty + j;
        const int c = n & 15;
        const int lane = (c & 7) * 4 + (p & 3);
        const int w = ((c >> 3) & 1) * 2 + (p >> 2);
        const long flat = ((long)(((n >> 4) << 6) + ki) * 32 + lane) * 8 + w * 2 + e;
        float h, l;
        splitb(t[tx][ty + j], h, l);
        oh[flat] = __float2bfloat16(h);
        ol[flat] = __float2bfloat16(l);
    }
}

// ---------------------------------------------------------------------------
// prepass 2b: W_proj[K][N] -> B-type frag-major FP16 hi/lo
// ---------------------------------------------------------------------------
__global__ void __launch_bounds__(256) tsp_b_f16_kernel(
    const float* __restrict__ W, half* __restrict__ oh,
    half* __restrict__ ol, int N)
{
    __shared__ float t[32][33];
    const int bx = blockIdx.x * 32;
    const int by = blockIdx.y * 32;
    const int tx = threadIdx.x & 31, ty = threadIdx.x >> 5;
#pragma unroll
    for (int j = 0; j < 32; j += 8)
        t[ty + j][tx] = W[(long)(by + ty + j) * N + bx + tx];
    __syncthreads();
    const int k = by + tx;
    const int ki = k >> 4, kk = k & 15, p = kk >> 1, e = kk & 1;
#pragma unroll
    for (int j = 0; j < 32; j += 8) {
        const int n = bx + ty + j;
        const int c = n & 15;
        const int lane = (c & 7) * 4 + (p & 3);
        const int w = ((c >> 3) & 1) * 2 + (p >> 2);
        const long flat = ((long)(((n >> 4) << 6) + ki) * 32 + lane) * 8 + w * 2 + e;
        const float v = t[tx][ty + j];
        half hh = __float2half_rn(v);
        half ll = __float2half_rn(v - __half2float(hh));
        oh[flat] = hh;
        ol[flat] = ll;
    }
}

// ---------------------------------------------------------------------------
// QKV GEMM (3xBF16): 256 thr, 8 warps (2x4), warp 64x32, CTA 128x128,
// BK=32, 3-stage cp.async, frag-major LDS.128, TERM-MAJOR mma order
// (acc reuse distance = 8 mma instead of 1).
// ---------------------------------------------------------------------------
#define GW_STAGE 8192
#define GEMM_SMEM_BYTES (3 * GW_STAGE * 4)

__device__ __forceinline__ void gemm_stage_cp(
    uint32_t sb, int s, int tid,
    const bf16* __restrict__ Agh, const bf16* __restrict__ Agl,
    const bf16* __restrict__ Bgh, const bf16* __restrict__ Bgl,
    int mt0, int nt0, int kt0)
{
#pragma unroll
    for (int i = 0; i < 2; i++) {
        const int c = tid + i * 256;
        const int kt2 = c >> 8, t8 = (c >> 5) & 7, lane = c & 31;
        const uint32_t w = (uint32_t)(s * GW_STAGE + (kt2 * 8 + t8) * 128 + lane * 4);
        const long ga = ((long)((mt0 + t8) * 64 + kt0 + kt2) * 32 + lane) * 8;
        const long gb = ((long)((nt0 + t8) * 64 + kt0 + kt2) * 32 + lane) * 8;
        cp16(sb + w * 4,          &Agh[ga]);
        cp16(sb + (w + 2048) * 4, &Agl[ga]);
        cp16(sb + (w + 4096) * 4, &Bgh[gb]);
        cp16(sb + (w + 6144) * 4, &Bgl[gb]);
    }
    cp_commit();
}

__global__ void __launch_bounds__(256, 2) gemm_qkv_kernel(
    int M, int N, int K,
    const bf16* __restrict__ Agh, const bf16* __restrict__ Agl,
    const bf16* __restrict__ Bgh, const bf16* __restrict__ Bgl,
    const float* __restrict__ bias,
    uint32_t* __restrict__ qh32, uint32_t* __restrict__ ql32,
    uint32_t* __restrict__ kh32, uint32_t* __restrict__ kl32,
    bf16* __restrict__ vth, bf16* __restrict__ vtl)
{
    extern __shared__ uint32_t smw[];
    const uint32_t sb = (uint32_t)__cvta_generic_to_shared(smw);

    const int tid  = threadIdx.x;
    const int wid  = tid >> 5, lane = tid & 31;
    const int gr   = lane >> 2, tg = lane & 3;
    const int wr   = wid >> 2,  wc = wid & 3;
    const int m0   = blockIdx.y * 128;
    const int n0   = blockIdx.x * 128;
    const int mt0  = m0 >> 4, nt0 = n0 >> 4;

    float acc[4][4][4];
#pragma unroll
    for (int i = 0; i < 4; i++)
#pragma unroll
        for (int j = 0; j < 4; j++)
#pragma unroll
            for (int r = 0; r < 4; r++) acc[i][j][r] = 0.f;

    const int nIter = K / 32;
    gemm_stage_cp(sb, 0, tid, Agh, Agl, Bgh, Bgl, mt0, nt0, 0);
    gemm_stage_cp(sb, 1, tid, Agh, Agl, Bgh, Bgl, mt0, nt0, 2);

    int stq = 0;
    for (int it = 0; it < nIter; it++) {
        if (it + 1 < nIter) cp_wait<1>(); else cp_wait<0>();
        __syncthreads();
        if (it + 2 < nIter) {
            int s2 = stq + 2; if (s2 >= 3) s2 -= 3;
            gemm_stage_cp(sb, s2, tid, Agh, Agl, Bgh, Bgl,
                          mt0, nt0, (it + 2) * 2);
        }

        const uint32_t* base = smw + stq * GW_STAGE;
#pragma unroll
        for (int ks = 0; ks < 2; ks++) {
            uint4 afh[4], afl[4];
#pragma unroll
            for (int mt = 0; mt < 4; mt++) {
                const int o = (ks * 8 + wr * 4 + mt) * 128 + lane * 4;
                afh[mt] = *(const uint4*)(base + o);
                afl[mt] = *(const uint4*)(base + 2048 + o);
            }
#pragma unroll
            for (int j = 0; j < 2; j++) {
                const int o = (ks * 8 + wc * 2 + j) * 128 + lane * 4;
                uint4 bh4 = *(const uint4*)(base + 4096 + o);
                uint4 bl4 = *(const uint4*)(base + 6144 + o);
                const uint32_t bx[2][2] = {{bh4.x, bh4.y}, {bh4.z, bh4.w}};
                const uint32_t cx[2][2] = {{bl4.x, bl4.y}, {bl4.z, bl4.w}};
                // term hh — 8 independent accs
#pragma unroll
                for (int jj = 0; jj < 2; jj++)
#pragma unroll
                    for (int mt = 0; mt < 4; mt++)
                        mma_bf16(acc[mt][2 * j + jj], (const uint32_t*)&afh[mt],
                                 bx[jj][0], bx[jj][1]);
                // term hl
#pragma unroll
                for (int jj = 0; jj < 2; jj++)
#pragma unroll
                    for (int mt = 0; mt < 4; mt++)
                        mma_bf16(acc[mt][2 * j + jj], (const uint32_t*)&afh[mt],
                                 cx[jj][0], cx[jj][1]);
                // term lh
#pragma unroll
                for (int jj = 0; jj < 2; jj++)
#pragma unroll
                    for (int mt = 0; mt < 4; mt++)
                        mma_bf16(acc[mt][2 * j + jj], (const uint32_t*)&afl[mt],
                                 bx[jj][0], bx[jj][1]);
            }
        }
        if (++stq == 3) stq = 0;
    }

    // ---- routing epilogue ----
#pragma unroll
    for (int nt = 0; nt < 4; nt++) {
        const int col = n0 + wc * 32 + nt * 8 + tg * 2;
        const float2 bv = *(const float2*)&bias[col];
#pragma unroll
        for (int mt = 0; mt < 4; mt++) {
            const int row = m0 + wr * 64 + mt * 16 + gr;
            const float v00 = acc[mt][nt][0] + bv.x;
            const float v01 = acc[mt][nt][1] + bv.y;
            const float v10 = acc[mt][nt][2] + bv.x;
            const float v11 = acc[mt][nt][3] + bv.y;
            const int sec = col >> 10;
            const int dc  = col & 1023;
            const int hh  = dc >> 6, d0 = dc & 63;
#pragma unroll
            for (int rr = 0; rr < 2; rr++) {
                const int m = row + rr * 8;
                const int b = m >> 11, t = m & 2047;
                float u0 = rr ? v10 : v00;
                float u1 = rr ? v11 : v01;
                float h0, l0, h1, l1;
                if (sec == 0) {
                    u0 *= LOG2E; u1 *= LOG2E;
                    splitb(u0, h0, l0); splitb(u1, h1, l1);
                    const int lane_ = (t & 7) * 4 + ((d0 >> 1) & 3);
                    const int w = ((t >> 3) & 1) + 2 * ((d0 >> 3) & 1);
                    const int tile = ((b * NH + hh) * 128 + (t >> 4)) * 4 + (d0 >> 4);
                    const int a32 = (tile * 32 + lane_) * 4 + w;
                    qh32[a32] = pack2(h0, h1);
                    ql32[a32] = pack2(l0, l1);
                } else if (sec == 1) {
                    splitb(u0, h0, l0); splitb(u1, h1, l1);
                    const int lane_ = (t & 7) * 4 + ((d0 >> 1) & 3);
                    const int w = ((t >> 3) & 1) * 2 + ((d0 >> 3) & 1);
                    const int tile = ((b * NH + hh) * 128 + (t >> 4)) * 4 + (d0 >> 4);
                    const int a32 = (tile * 32 + lane_) * 4 + w;
                    kh32[a32] = pack2(h0, h1);
                    kl32[a32] = pack2(l0, l1);
                } else {
                    splitb(u0, h0, l0); splitb(u1, h1, l1);
                    const int lane_ = (d0 & 7) * 4 + ((t >> 1) & 3);
                    const int w = ((d0 >> 3) & 1) * 2 + ((t >> 3) & 1);
                    const int tile = ((b * NH + hh) * 4 + (d0 >> 4)) * 128 + (t >> 4);
                    const long f = ((long)tile * 32 + lane_) * 8 + w * 2 + (t & 1);
                    vth[f] = __float2bfloat16(h0);
                    vtl[f] = __float2bfloat16(l0);
                    vth[f + 32] = __float2bfloat16(h1);
                    vtl[f + 32] = __float2bfloat16(l1);
                }
            }
        }
    }
}

// ---------------------------------------------------------------------------
// PROJ GEMM (fp16 2-term): term-major mma order.
// ---------------------------------------------------------------------------
#define PW_STAGE 6144
#define PROJ_SMEM_BYTES (3 * PW_STAGE * 4)

__device__ __forceinline__ void proj_stage_cp(
    uint32_t sb, int s, int tid,
    const half* __restrict__ Af,
    const half* __restrict__ Bh, const half* __restrict__ Bl,
    int mt0, int nt0, int kt0)
{
#pragma unroll
    for (int i = 0; i < 2; i++) {
        const int c = tid + i * 256;
        const int kt2 = c >> 8, t8 = (c >> 5) & 7, lane = c & 31;
        const uint32_t w = (uint32_t)(s * PW_STAGE + (kt2 * 8 + t8) * 128 + lane * 4);
        const long ga = ((long)((mt0 + t8) * 64 + kt0 + kt2) * 32 + lane) * 8;
        cp16(sb + w * 4, &Af[ga]);
    }
#pragma unroll
    for (int i = 0; i < 2; i++) {
        const int c = tid + i * 256;
        const int kt2 = c >> 8, t8 = (c >> 5) & 7, lane = c & 31;
        const uint32_t w = (uint32_t)(s * PW_STAGE + 2048 + (kt2 * 8 + t8) * 128 + lane * 4);
        const long gb = ((long)((nt0 + t8) * 64 + kt0 + kt2) * 32 + lane) * 8;
        cp16(sb + w * 4, &Bh[gb]);
    }
#pragma unroll
    for (int i = 0; i < 2; i++) {
        const int c = tid + i * 256;
        const int kt2 = c >> 8, t8 = (c >> 5) & 7, lane = c & 31;
        const uint32_t w = (uint32_t)(s * PW_STAGE + 4096 + (kt2 * 8 + t8) * 128 + lane * 4);
        const long gb = ((long)((nt0 + t8) * 64 + kt0 + kt2) * 32 + lane) * 8;
        cp16(sb + w * 4, &Bl[gb]);
    }
    cp_commit();
}

__global__ void __launch_bounds__(256, 2) gemm_proj_kernel(
    int M, int N, int K,
    const half* __restrict__ Af,
    const half* __restrict__ Bh, const half* __restrict__ Bl,
    const float* __restrict__ bias, float* __restrict__ C)
{
    extern __shared__ uint32_t smw[];
    const uint32_t sb = (uint32_t)__cvta_generic_to_shared(smw);

    const int tid  = threadIdx.x;
    const int wid  = tid >> 5, lane = tid & 31;
    const int gr   = lane >> 2, tg = lane & 3;
    const int wr   = wid >> 2,  wc = wid & 3;
    const int m0   = blockIdx.y * 128;
    const int n0   = blockIdx.x * 128;
    const int mt0  = m0 >> 4, nt0 = n0 >> 4;

    float acc[4][4][4];
#pragma unroll
    for (int i = 0; i < 4; i++)
#pragma unroll
        for (int j = 0; j < 4; j++)
#pragma unroll
            for (int r = 0; r < 4; r++) acc[i][j][r] = 0.f;

    const int nIter = K / 32;
    proj_stage_cp(sb, 0, tid, Af, Bh, Bl, mt0, nt0, 0);
    proj_stage_cp(sb, 1, tid, Af, Bh, Bl, mt0, nt0, 2);

    int stq = 0;
    for (int it = 0; it < nIter; it++) {
        if (it + 1 < nIter) cp_wait<1>(); else cp_wait<0>();
        __syncthreads();
        if (it + 2 < nIter) {
            int s2 = stq + 2; if (s2 >= 3) s2 -= 3;
            proj_stage_cp(sb, s2, tid, Af, Bh, Bl, mt0, nt0, (it + 2) * 2);
        }

        const uint32_t* base = smw + stq * PW_STAGE;
#pragma unroll
        for (int ks = 0; ks < 2; ks++) {
            uint4 af[4];
#pragma unroll
            for (int mt = 0; mt < 4; mt++) {
                const int o = (ks * 8 + wr * 4 + mt) * 128 + lane * 4;
                af[mt] = *(const uint4*)(base + o);
            }
#pragma unroll
            for (int j = 0; j < 2; j++) {
                const int o = (ks * 8 + wc * 2 + j) * 128 + lane * 4;
                uint4 bh4 = *(const uint4*)(base + 2048 + o);
                uint4 bl4 = *(const uint4*)(base + 4096 + o);
                const uint32_t bx[2][2] = {{bh4.x, bh4.y}, {bh4.z, bh4.w}};
                const uint32_t cx[2][2] = {{bl4.x, bl4.y}, {bl4.z, bl4.w}};
#pragma unroll
                for (int jj = 0; jj < 2; jj++)
#pragma unroll
                    for (int mt = 0; mt < 4; mt++)
                        mma_f16(acc[mt][2 * j + jj], (const uint32_t*)&af[mt],
                                bx[jj][0], bx[jj][1]);
#pragma unroll
                for (int jj = 0; jj < 2; jj++)
#pragma unroll
                    for (int mt = 0; mt < 4; mt++)
                        mma_f16(acc[mt][2 * j + jj], (const uint32_t*)&af[mt],
                                cx[jj][0], cx[jj][1]);
            }
        }
        if (++stq == 3) stq = 0;
    }

#pragma unroll
    for (int nt = 0; nt < 4; nt++) {
        const int col = n0 + wc * 32 + nt * 8 + tg * 2;
        const float2 bv = *(const float2*)&bias[col];
#pragma unroll
        for (int mt = 0; mt < 4; mt++) {
            const int row = m0 + wr * 64 + mt * 16 + gr;
            *(float2*)&C[(long)row * N + col] =
                make_float2(acc[mt][nt][0] + bv.x, acc[mt][nt][1] + bv.y);
            *(float2*)&C[(long)(row + 8) * N + col] =
                make_float2(acc[mt][nt][2] + bv.x, acc[mt][nt][3] + bv.y);
        }
    }
}

// ---------------------------------------------------------------------------
// Attention: 256 thr (8 warps), warp = 16 q-rows, BQ=128, BK=64, 3-stage
// cp.async, Q reloaded per j-tile (L1), P in regs, term-major mma order
// over ntp-pairs (acc reuse distance 4).
// ---------------------------------------------------------------------------
#define AW_STAGE 8192
#define AT_SMEM_BYTES (3 * AW_STAGE * 4)

__device__ __forceinline__ void attn_stage_cp(
    uint32_t sb, int s, int tid, int bh32,
    const bf16* __restrict__ kh, const bf16* __restrict__ kl,
    const bf16* __restrict__ vth, const bf16* __restrict__ vtl,
    int jt0)
{
#pragma unroll
    for (int q = 0; q < 2; q++) {
        const int c = q * 256 + tid;
        const int dt = c >> 7, tt = (c >> 5) & 3, lane = c & 31;
        const long gk = ((long)((bh32 * 128 + jt0 + tt) * 4 + dt) * 32 + lane) * 8;
        const long gv = ((long)((bh32 * 4 + dt) * 128 + jt0 + tt) * 32 + lane) * 8;
        const uint32_t wk = (uint32_t)(s * AW_STAGE + (dt * 4 + tt) * 128 + lane * 4);
        const uint32_t wv = (uint32_t)(s * AW_STAGE + 4096 + (tt * 4 + dt) * 128 + lane * 4);
        cp16(sb + wk * 4,          &kh[gk]);
        cp16(sb + (wk + 2048) * 4, &kl[gk]);
        cp16(sb + wv * 4,          &vth[gv]);
        cp16(sb + (wv + 2048) * 4, &vtl[gv]);
    }
    cp_commit();
}

__global__ void __launch_bounds__(256, 2) attn_kernel(
    const uint32_t* __restrict__ qh32, const uint32_t* __restrict__ ql32,
    const bf16* __restrict__ kh, const bf16* __restrict__ kl,
    const bf16* __restrict__ vth, const bf16* __restrict__ vtl,
    uint32_t* __restrict__ yf32)
{
    extern __shared__ uint32_t smw[];
    const uint32_t sb = (uint32_t)__cvta_generic_to_shared(smw);

    const int tid  = threadIdx.x;
    const int wid  = tid >> 5, lane = tid & 31;
    const int gr   = lane >> 2, tg = lane & 3;
    const int bh32 = blockIdx.y;
    const int b    = bh32 >> 4, h = bh32 & 15;
    const int qa   = blockIdx.x * 128 + wid * 16;
    const int qt   = bh32 * 128 + (qa >> 4);

    attn_stage_cp(sb, 0, tid, bh32, kh, kl, vth, vtl, 0);
    attn_stage_cp(sb, 1, tid, bh32, kh, kl, vth, vtl, 4);

    float oacc[8][4];
#pragma unroll
    for (int nt = 0; nt < 8; nt++)
#pragma unroll
        for (int r = 0; r < 4; r++) oacc[nt][r] = 0.f;
    float lA = 0.f, lB = 0.f;

    int stq = 0;
    for (int jt = 0; jt < 32; jt++) {
        if (jt + 1 < 32) cp_wait<1>(); else cp_wait<0>();
        __syncthreads();
        if (jt + 2 < 32) {
            int s2 = stq + 2; if (s2 >= 3) s2 -= 3;
            attn_stage_cp(sb, s2, tid, bh32, kh, kl, vth, vtl, (jt + 2) * 4);
        }
        const uint32_t* base = smw + stq * AW_STAGE;

        // Q fragments (L1-resident reload)
        uint4 qfh[4], qfl[4];
#pragma unroll
        for (int kt = 0; kt < 4; kt++) {
            const int a = ((qt * 4 + kt) * 32 + lane) * 4;
            qfh[kt] = *(const uint4*)(qh32 + a);
            qfl[kt] = *(const uint4*)(ql32 + a);
        }

        // ---- S = Q K^T (3xBF16, term-major over ntp-pairs) ----
        float sacc[8][4];
#pragma unroll
        for (int nt = 0; nt < 8; nt++)
#pragma unroll
            for (int r = 0; r < 4; r++) sacc[nt][r] = 0.f;

#pragma unroll
        for (int kt = 0; kt < 4; kt++) {
#pragma unroll
            for (int hp = 0; hp < 2; hp++) {   // ntp pair {2hp, 2hp+1}
                uint4 k4h[2], k4l[2];
#pragma unroll
                for (int p = 0; p < 2; p++) {
                    const int o = (kt * 4 + 2 * hp + p) * 128 + lane * 4;
                    k4h[p] = *(const uint4*)(base + o);
                    k4l[p] = *(const uint4*)(base + 2048 + o);
                }
                // term hh (4 independent accs)
#pragma unroll
                for (int p = 0; p < 2; p++) {
                    const int nt0_ = (2 * hp + p) * 2;
                    mma_bf16(sacc[nt0_],     (const uint32_t*)&qfh[kt], k4h[p].x, k4h[p].y);
                    mma_bf16(sacc[nt0_ + 1], (const uint32_t*)&qfh[kt], k4h[p].z, k4h[p].w);
                }
                // term hl
#pragma unroll
                for (int p = 0; p < 2; p++) {
                    const int nt0_ = (2 * hp + p) * 2;
                    mma_bf16(sacc[nt0_],     (const uint32_t*)&qfh[kt], k4l[p].x, k4l[p].y);
                    mma_bf16(sacc[nt0_ + 1], (const uint32_t*)&qfh[kt], k4l[p].z, k4l[p].w);
                }
                // term lh
#pragma unroll
                for (int p = 0; p < 2; p++) {
                    const int nt0_ = (2 * hp + p) * 2;
                    mma_bf16(sacc[nt0_],     (const uint32_t*)&qfl[kt], k4h[p].x, k4h[p].y);
                    mma_bf16(sacc[nt0_ + 1], (const uint32_t*)&qfl[kt], k4h[p].z, k4h[p].w);
                }
            }
        }

        // ---- softmax: p = 2^s; pack to bf16 P-fragments ----
        uint32_t pah[4][4], pal[4][4];
#pragma unroll
        for (int nt = 0; nt < 8; nt++) {
            float* s4 = sacc[nt];
            s4[0] = ex2f(s4[0]);
            s4[1] = ex2f(s4[1]);
            s4[2] = ex2f(s4[2]);
            s4[3] = ex2f(s4[3]);
            lA += s4[0] + s4[1];
            lB += s4[2] + s4[3];
            const int kt = nt >> 1, i = nt & 1;
            uint32_t w0 = pack2(s4[0], s4[1]);
            uint32_t w1 = pack2(s4[2], s4[3]);
            pah[kt][2 * i]     = w0;
            pah[kt][2 * i + 1] = w1;
            __nv_bfloat162 b0 = *(__nv_bfloat162*)&w0;
            __nv_bfloat162 b1 = *(__nv_bfloat162*)&w1;
            float2 f0 = __bfloat1622float2(b0);
            float2 f1 = __bfloat1622float2(b1);
            pal[kt][2 * i]     = pack2(s4[0] - f0.x, s4[1] - f0.y);
            pal[kt][2 * i + 1] = pack2(s4[2] - f1.x, s4[3] - f1.y);
        }

        // ---- O += P V (term-major over ntp-pairs) ----
#pragma unroll
        for (int kt = 0; kt < 4; kt++) {
#pragma unroll
            for (int hp = 0; hp < 2; hp++) {
                uint4 v4h[2], v4l[2];
#pragma unroll
                for (int p = 0; p < 2; p++) {
                    const int o = 4096 + (kt * 4 + 2 * hp + p) * 128 + lane * 4;
                    v4h[p] = *(const uint4*)(base + o);
                    v4l[p] = *(const uint4*)(base + 2048 + o);
                }
#pragma unroll
                for (int p = 0; p < 2; p++) {
                    const int nt0_ = (2 * hp + p) * 2;
                    mma_bf16(oacc[nt0_],     pah[kt], v4h[p].x, v4h[p].y);
                    mma_bf16(oacc[nt0_ + 1], pah[kt], v4h[p].z, v4h[p].w);
                }
#pragma unroll
                for (int p = 0; p < 2; p++) {
                    const int nt0_ = (2 * hp + p) * 2;
                    mma_bf16(oacc[nt0_],     pah[kt], v4l[p].x, v4l[p].y);
                    mma_bf16(oacc[nt0_ + 1], pah[kt], v4l[p].z, v4l[p].w);
                }
#pragma unroll
                for (int p = 0; p < 2; p++) {
                    const int nt0_ = (2 * hp + p) * 2;
                    mma_bf16(oacc[nt0_],     pal[kt], v4h[p].x, v4h[p].y);
                    mma_bf16(oacc[nt0_ + 1], pal[kt], v4h[p].z, v4h[p].w);
                }
            }
        }
        if (++stq == 3) stq = 0;
    }

    // reductions + fp16 single-plane epilogue
    lA += __shfl_xor_sync(0xffffffffu, lA, 1);
    lA += __shfl_xor_sync(0xffffffffu, lA, 2);
    lB += __shfl_xor_sync(0xffffffffu, lB, 1);
    lB += __shfl_xor_sync(0xffffffffu, lB, 2);
    const float invA = 1.0f / (lA * 8.0f);
    const float invB = 1.0f / (lB * 8.0f);
    const int t = qa + gr;
    const int mtile = (b * TT + t) >> 4;
#pragma unroll
    for (int nt = 0; nt < 8; nt++) {
        const int ctile = h * 4 + (nt >> 1);
        const int a32 = ((mtile * 64 + ctile) * 32 + lane) * 4;
        const int w0 = 2 * (nt & 1);
        yf32[a32 + w0]     = pack2h(oacc[nt][0] * invA, oacc[nt][1] * invA);
        yf32[a32 + w0 + 1] = pack2h(oacc[nt][2] * invB, oacc[nt][3] * invB);
    }
}

// ---------------------------------------------------------------------------
extern "C" void kernel_launch(void* const* d_in, const int* in_sizes, int n_in,
                              void* d_out, int out_size)
{
    const float* x      = (const float*)d_in[0];
    const float* W_attn = (const float*)d_in[1];
    const float* b_attn = (const float*)d_in[2];
    const float* W_proj = (const float*)d_in[3];
    const float* b_proj = (const float*)d_in[4];
    float* out = (float*)d_out;

    bf16 *xh, *xl, *wth, *wtl;
    bf16 *qhp, *qlp, *khp, *klp, *vthp, *vtlp;
    half *wpfh, *wpfl, *yf;
    cudaGetSymbolAddress((void**)&xh,   g_xh);
    cudaGetSymbolAddress((void**)&xl,   g_xl);
    cudaGetSymbolAddress((void**)&wth,  g_wth);
    cudaGetSymbolAddress((void**)&wtl,  g_wtl);
    cudaGetSymbolAddress((void**)&wpfh, g_wpfh);
    cudaGetSymbolAddress((void**)&wpfl, g_wpfl);
    cudaGetSymbolAddress((void**)&qhp,  g_qh);
    cudaGetSymbolAddress((void**)&qlp,  g_ql);
    cudaGetSymbolAddress((void**)&khp,  g_kh);
    cudaGetSymbolAddress((void**)&klp,  g_kl);
    cudaGetSymbolAddress((void**)&vthp, g_vth);
    cudaGetSymbolAddress((void**)&vtlp, g_vtl);
    cudaGetSymbolAddress((void**)&yf,   g_yf);

    cudaFuncSetAttribute(gemm_qkv_kernel,
                         cudaFuncAttributeMaxDynamicSharedMemorySize,
                         GEMM_SMEM_BYTES);
    cudaFuncSetAttribute(gemm_proj_kernel,
                         cudaFuncAttributeMaxDynamicSharedMemorySize,
                         PROJ_SMEM_BYTES);
    cudaFuncSetAttribute(attn_kernel,
                         cudaFuncAttributeMaxDynamicSharedMemorySize,
                         AT_SMEM_BYTES);

    // prepasses
    split_a_kernel<<<(NTOK * CC / 4 + 255) / 256, 256>>>(
        x, (uint32_t*)xh, (uint32_t*)xl, NTOK * CC / 4);
    tsp_b_kernel<<<dim3(C3 / 32, CC / 32), 256>>>(W_attn, wth, wtl, C3);
    tsp_b_f16_kernel<<<dim3(CC / 32, CC / 32), 256>>>(W_proj, wpfh, wpfl, CC);

    // 1) QKV GEMM + routing epilogue (Q scaled by log2e)
    gemm_qkv_kernel<<<dim3(C3 / 128, NTOK / 128), 256, GEMM_SMEM_BYTES>>>(
        NTOK, C3, CC, xh, xl, wth, wtl, b_attn,
        (uint32_t*)qhp, (uint32_t*)qlp, (uint32_t*)khp, (uint32_t*)klp,
        vthp, vtlp);

    // 2) attention
    attn_kernel<<<dim3(TT / 128, BB * NH), 256, AT_SMEM_BYTES>>>(
        (const uint32_t*)qhp, (const uint32_t*)qlp, khp, klp, vthp, vtlp,
        (uint32_t*)yf);

    // 3) proj GEMM (fp16 2-term)
    gemm_proj_kernel<<<dim3(CC / 128, NTOK / 128), 256, PROJ_SMEM_BYTES>>>(
        NTOK, CC, CC, yf, wpfh, wpfl, b_proj, out);
}

// round 15
// speedup vs baseline: 1.4444x; 1.0164x over previous
#include <cuda_runtime.h>
#include <cuda_bf16.h>
#include <cuda_fp16.h>
#include <math.h>
#include <stdint.h>

#define BB   2
#define TT   2048
#define CC   1024
#define NH   16
#define DH   64
#define NTOK (BB * TT)
#define C3   (3 * CC)
#define LOG2E 1.4426950408889634f

typedef __nv_bfloat16 bf16;

// ---------------------------------------------------------------------------
// Fragment-major layouts (16x16 tiles, 32 lanes x 16B) — see round 11 notes.
// ---------------------------------------------------------------------------
__device__ bf16 g_xh[NTOK * CC],  g_xl[NTOK * CC];   // A-type
__device__ bf16 g_wth[C3 * CC],   g_wtl[C3 * CC];    // B-type
__device__ half g_wpfh[CC * CC],  g_wpfl[CC * CC];   // B-type fp16 (proj)
__device__ bf16 g_qh[NTOK * CC],  g_ql[NTOK * CC];   // A-type per (b,h)
__device__ bf16 g_kh[NTOK * CC],  g_kl[NTOK * CC];   // B-type per (b,h)
__device__ bf16 g_vth[NTOK * CC], g_vtl[NTOK * CC];  // B-type transposed
__device__ half g_yf[NTOK * CC];                     // A-type fp16 single

// ---------------------------------------------------------------------------
// helpers
// ---------------------------------------------------------------------------
__device__ __forceinline__ float bfr(float x) {
    return __bfloat162float(__float2bfloat16(x));
}
__device__ __forceinline__ void splitb(float x, float& h, float& l) {
    h = bfr(x);
    l = bfr(x - h);
}
__device__ __forceinline__ uint32_t pack2(float a, float b) {
    __nv_bfloat162 t = __floats2bfloat162_rn(a, b);
    return *(uint32_t*)&t;
}
__device__ __forceinline__ uint32_t pack2h(float a, float b) {
    __half2 t = __floats2half2_rn(a, b);
    return *(uint32_t*)&t;
}
__device__ __forceinline__ float ex2f(float x) {
    float y; asm("ex2.approx.f32 %0, %1;" : "=f"(y) : "f"(x)); return y;
}
__device__ __forceinline__ void mma_bf16(float* d, const uint32_t* a,
                                         uint32_t b0, uint32_t b1) {
    asm volatile(
        "mma.sync.aligned.m16n8k16.row.col.f32.bf16.bf16.f32 "
        "{%0,%1,%2,%3}, {%4,%5,%6,%7}, {%8,%9}, {%0,%1,%2,%3};"
        : "+f"(d[0]), "+f"(d[1]), "+f"(d[2]), "+f"(d[3])
        : "r"(a[0]), "r"(a[1]), "r"(a[2]), "r"(a[3]), "r"(b0), "r"(b1));
}
__device__ __forceinline__ void mma_f16(float* d, const uint32_t* a,
                                        uint32_t b0, uint32_t b1) {
    asm volatile(
        "mma.sync.aligned.m16n8k16.row.col.f32.f16.f16.f32 "
        "{%0,%1,%2,%3}, {%4,%5,%6,%7}, {%8,%9}, {%0,%1,%2,%3};"
        : "+f"(d[0]), "+f"(d[1]), "+f"(d[2]), "+f"(d[3])
        : "r"(a[0]), "r"(a[1]), "r"(a[2]), "r"(a[3]), "r"(b0), "r"(b1));
}
__device__ __forceinline__ void cp16(uint32_t d, const void* s) {
    asm volatile("cp.async.cg.shared.global [%0], [%1], 16;" :: "r"(d), "l"(s));
}
__device__ __forceinline__ void cp_commit() {
    asm volatile("cp.async.commit_group;");
}
template <int N> __device__ __forceinline__ void cp_wait() {
    asm volatile("cp.async.wait_group %0;" :: "n"(N));
}

// ---------------------------------------------------------------------------
// prepass 1: x -> A-type frag-major bf16 hi/lo
// ---------------------------------------------------------------------------
__global__ void __launch_bounds__(256) split_a_kernel(
    const float* __restrict__ in, uint32_t* __restrict__ oh,
    uint32_t* __restrict__ ol, int n4)
{
    const int i4 = blockIdx.x * 256 + threadIdx.x;
    if (i4 >= n4) return;
    const int g = i4 * 4;
    const int m = g >> 10, k0 = g & 1023;
    float4 v = *(const float4*)&in[g];

    const int r = m & 15, gr = r & 7, hi = (r >> 3) & 1;
    const int tile = ((m >> 4) << 6) + (k0 >> 4);
    const int p0 = (k0 & 15) >> 1;
#pragma unroll
    for (int q = 0; q < 2; q++) {
        const int p = p0 + q;
        const int lane = gr * 4 + (p & 3);
        const int w = hi + 2 * (p >> 2);
        const int a32 = (tile * 32 + lane) * 4 + w;
        float e0 = q ? v.z : v.x, e1 = q ? v.w : v.y;
        float h0, l0, h1, l1;
        splitb(e0, h0, l0);
        splitb(e1, h1, l1);
        oh[a32] = pack2(h0, h1);
        ol[a32] = pack2(l0, l1);
    }
}

// ---------------------------------------------------------------------------
// prepass 2a: W_attn[K][N] -> B-type frag-major bf16 hi/lo
// ---------------------------------------------------------------------------
__global__ void __launch_bounds__(256) tsp_b_kernel(
    const float* __restrict__ W, bf16* __restrict__ oh,
    bf16* __restrict__ ol, int N)
{
    __shared__ float t[32][33];
    const int bx = blockIdx.x * 32;
    const int by = blockIdx.y * 32;
    const int tx = threadIdx.x & 31, ty = threadIdx.x >> 5;
#pragma unroll
    for (int j = 0; j < 32; j += 8)
        t[ty + j][tx] = W[(long)(by + ty + j) * N + bx + tx];
    __syncthreads();
    const int k = by + tx;
    const int ki = k >> 4, kk = k & 15, p = kk >> 1, e = kk & 1;
#pragma unroll
    for (int j = 0; j < 32; j += 8) {
        const int n = bx + ty + j;
        const int c = n & 15;
        const int lane = (c & 7) * 4 + (p & 3);
        const int w = ((c >> 3) & 1) * 2 + (p >> 2);
        const long flat = ((long)(((n >> 4) << 6) + ki) * 32 + lane) * 8 + w * 2 + e;
        float h, l;
        splitb(t[tx][ty + j], h, l);
        oh[flat] = __float2bfloat16(h);
        ol[flat] = __float2bfloat16(l);
    }
}

// ---------------------------------------------------------------------------
// prepass 2b: W_proj[K][N] -> B-type frag-major FP16 hi/lo
// ---------------------------------------------------------------------------
__global__ void __launch_bounds__(256) tsp_b_f16_kernel(
    const float* __restrict__ W, half* __restrict__ oh,
    half* __restrict__ ol, int N)
{
    __shared__ float t[32][33];
    const int bx = blockIdx.x * 32;
    const int by = blockIdx.y * 32;
    const int tx = threadIdx.x & 31, ty = threadIdx.x >> 5;
#pragma unroll
    for (int j = 0; j < 32; j += 8)
        t[ty + j][tx] = W[(long)(by + ty + j) * N + bx + tx];
    __syncthreads();
    const int k = by + tx;
    const int ki = k >> 4, kk = k & 15, p = kk >> 1, e = kk & 1;
#pragma unroll
    for (int j = 0; j < 32; j += 8) {
        const int n = bx + ty + j;
        const int c = n & 15;
        const int lane = (c & 7) * 4 + (p & 3);
        const int w = ((c >> 3) & 1) * 2 + (p >> 2);
        const long flat = ((long)(((n >> 4) << 6) + ki) * 32 + lane) * 8 + w * 2 + e;
        const float v = t[tx][ty + j];
        half hh = __float2half_rn(v);
        half ll = __float2half_rn(v - __half2float(hh));
        oh[flat] = hh;
        ol[flat] = ll;
    }
}

// ---------------------------------------------------------------------------
// QKV GEMM (3xBF16): 256 thr, 8 warps (2x4), warp 64x32, CTA 128x128,
// BK=32, 3-stage cp.async, order: wait -> sync -> issue -> compute
// (round-13 proven-correct structure).
// ---------------------------------------------------------------------------
#define GW_STAGE 8192
#define GEMM_SMEM_BYTES (3 * GW_STAGE * 4)

__device__ __forceinline__ void gemm_stage_cp(
    uint32_t sb, int s, int tid,
    const bf16* __restrict__ Agh, const bf16* __restrict__ Agl,
    const bf16* __restrict__ Bgh, const bf16* __restrict__ Bgl,
    int mt0, int nt0, int kt0)
{
#pragma unroll
    for (int i = 0; i < 2; i++) {
        const int c = tid + i * 256;
        const int kt2 = c >> 8, t8 = (c >> 5) & 7, lane = c & 31;
        const uint32_t w = (uint32_t)(s * GW_STAGE + (kt2 * 8 + t8) * 128 + lane * 4);
        const long ga = ((long)((mt0 + t8) * 64 + kt0 + kt2) * 32 + lane) * 8;
        const long gb = ((long)((nt0 + t8) * 64 + kt0 + kt2) * 32 + lane) * 8;
        cp16(sb + w * 4,          &Agh[ga]);
        cp16(sb + (w + 2048) * 4, &Agl[ga]);
        cp16(sb + (w + 4096) * 4, &Bgh[gb]);
        cp16(sb + (w + 6144) * 4, &Bgl[gb]);
    }
    cp_commit();
}

__global__ void __launch_bounds__(256, 2) gemm_qkv_kernel(
    int M, int N, int K,
    const bf16* __restrict__ Agh, const bf16* __restrict__ Agl,
    const bf16* __restrict__ Bgh, const bf16* __restrict__ Bgl,
    const float* __restrict__ bias,
    uint32_t* __restrict__ qh32, uint32_t* __restrict__ ql32,
    uint32_t* __restrict__ kh32, uint32_t* __restrict__ kl32,
    bf16* __restrict__ vth, bf16* __restrict__ vtl)
{
    extern __shared__ uint32_t smw[];
    const uint32_t sb = (uint32_t)__cvta_generic_to_shared(smw);

    const int tid  = threadIdx.x;
    const int wid  = tid >> 5, lane = tid & 31;
    const int gr   = lane >> 2, tg = lane & 3;
    const int wr   = wid >> 2,  wc = wid & 3;
    const int m0   = blockIdx.y * 128;
    const int n0   = blockIdx.x * 128;
    const int mt0  = m0 >> 4, nt0 = n0 >> 4;

    float acc[4][4][4];
#pragma unroll
    for (int i = 0; i < 4; i++)
#pragma unroll
        for (int j = 0; j < 4; j++)
#pragma unroll
            for (int r = 0; r < 4; r++) acc[i][j][r] = 0.f;

    const int nIter = K / 32;
    gemm_stage_cp(sb, 0, tid, Agh, Agl, Bgh, Bgl, mt0, nt0, 0);
    gemm_stage_cp(sb, 1, tid, Agh, Agl, Bgh, Bgl, mt0, nt0, 2);

    int stq = 0;
    for (int it = 0; it < nIter; it++) {
        if (it + 1 < nIter) cp_wait<1>(); else cp_wait<0>();
        __syncthreads();
        if (it + 2 < nIter) {
            int s2 = stq + 2; if (s2 >= 3) s2 -= 3;
            gemm_stage_cp(sb, s2, tid, Agh, Agl, Bgh, Bgl,
                          mt0, nt0, (it + 2) * 2);
        }

        const uint32_t* base = smw + stq * GW_STAGE;
#pragma unroll
        for (int ks = 0; ks < 2; ks++) {
            uint4 afh[4], afl[4];
#pragma unroll
            for (int mt = 0; mt < 4; mt++) {
                const int o = (ks * 8 + wr * 4 + mt) * 128 + lane * 4;
                afh[mt] = *(const uint4*)(base + o);
                afl[mt] = *(const uint4*)(base + 2048 + o);
            }
#pragma unroll
            for (int j = 0; j < 2; j++) {
                const int o = (ks * 8 + wc * 2 + j) * 128 + lane * 4;
                uint4 bh4 = *(const uint4*)(base + 4096 + o);
                uint4 bl4 = *(const uint4*)(base + 6144 + o);
                const uint32_t bx[2][2] = {{bh4.x, bh4.y}, {bh4.z, bh4.w}};
                const uint32_t cx[2][2] = {{bl4.x, bl4.y}, {bl4.z, bl4.w}};
#pragma unroll
                for (int jj = 0; jj < 2; jj++)
#pragma unroll
                    for (int mt = 0; mt < 4; mt++)
                        mma_bf16(acc[mt][2 * j + jj], (const uint32_t*)&afh[mt],
                                 bx[jj][0], bx[jj][1]);
#pragma unroll
                for (int jj = 0; jj < 2; jj++)
#pragma unroll
                    for (int mt = 0; mt < 4; mt++)
                        mma_bf16(acc[mt][2 * j + jj], (const uint32_t*)&afh[mt],
                                 cx[jj][0], cx[jj][1]);
#pragma unroll
                for (int jj = 0; jj < 2; jj++)
#pragma unroll
                    for (int mt = 0; mt < 4; mt++)
                        mma_bf16(acc[mt][2 * j + jj], (const uint32_t*)&afl[mt],
                                 bx[jj][0], bx[jj][1]);
            }
        }
        if (++stq == 3) stq = 0;
    }

    // ---- routing epilogue ----
#pragma unroll
    for (int nt = 0; nt < 4; nt++) {
        const int col = n0 + wc * 32 + nt * 8 + tg * 2;
        const float2 bv = *(const float2*)&bias[col];
#pragma unroll
        for (int mt = 0; mt < 4; mt++) {
            const int row = m0 + wr * 64 + mt * 16 + gr;
            const float v00 = acc[mt][nt][0] + bv.x;
            const float v01 = acc[mt][nt][1] + bv.y;
            const float v10 = acc[mt][nt][2] + bv.x;
            const float v11 = acc[mt][nt][3] + bv.y;
            const int sec = col >> 10;
            const int dc  = col & 1023;
            const int hh  = dc >> 6, d0 = dc & 63;
#pragma unroll
            for (int rr = 0; rr < 2; rr++) {
                const int m = row + rr * 8;
                const int b = m >> 11, t = m & 2047;
                float u0 = rr ? v10 : v00;
                float u1 = rr ? v11 : v01;
                float h0, l0, h1, l1;
                if (sec == 0) {
                    u0 *= LOG2E; u1 *= LOG2E;
                    splitb(u0, h0, l0); splitb(u1, h1, l1);
                    const int lane_ = (t & 7) * 4 + ((d0 >> 1) & 3);
                    const int w = ((t >> 3) & 1) + 2 * ((d0 >> 3) & 1);
                    const int tile = ((b * NH + hh) * 128 + (t >> 4)) * 4 + (d0 >> 4);
                    const int a32 = (tile * 32 + lane_) * 4 + w;
                    qh32[a32] = pack2(h0, h1);
                    ql32[a32] = pack2(l0, l1);
                } else if (sec == 1) {
                    splitb(u0, h0, l0); splitb(u1, h1, l1);
                    const int lane_ = (t & 7) * 4 + ((d0 >> 1) & 3);
                    const int w = ((t >> 3) & 1) * 2 + ((d0 >> 3) & 1);
                    const int tile = ((b * NH + hh) * 128 + (t >> 4)) * 4 + (d0 >> 4);
                    const int a32 = (tile * 32 + lane_) * 4 + w;
                    kh32[a32] = pack2(h0, h1);
                    kl32[a32] = pack2(l0, l1);
                } else {
                    splitb(u0, h0, l0); splitb(u1, h1, l1);
                    const int lane_ = (d0 & 7) * 4 + ((t >> 1) & 3);
                    const int w = ((d0 >> 3) & 1) * 2 + ((t >> 3) & 1);
                    const int tile = ((b * NH + hh) * 4 + (d0 >> 4)) * 128 + (t >> 4);
                    const long f = ((long)tile * 32 + lane_) * 8 + w * 2 + (t & 1);
                    vth[f] = __float2bfloat16(h0);
                    vtl[f] = __float2bfloat16(l0);
                    vth[f + 32] = __float2bfloat16(h1);
                    vtl[f + 32] = __float2bfloat16(l1);
                }
            }
        }
    }
}

// ---------------------------------------------------------------------------
// PROJ GEMM (fp16 2-term), round-13 structure.
// ---------------------------------------------------------------------------
#define PW_STAGE 6144
#define PROJ_SMEM_BYTES (3 * PW_STAGE * 4)

__device__ __forceinline__ void proj_stage_cp(
    uint32_t sb, int s, int tid,
    const half* __restrict__ Af,
    const half* __restrict__ Bh, const half* __restrict__ Bl,
    int mt0, int nt0, int kt0)
{
#pragma unroll
    for (int i = 0; i < 2; i++) {
        const int c = tid + i * 256;
        const int kt2 = c >> 8, t8 = (c >> 5) & 7, lane = c & 31;
        const uint32_t w = (uint32_t)(s * PW_STAGE + (kt2 * 8 + t8) * 128 + lane * 4);
        const long ga = ((long)((mt0 + t8) * 64 + kt0 + kt2) * 32 + lane) * 8;
        cp16(sb + w * 4, &Af[ga]);
    }
#pragma unroll
    for (int i = 0; i < 2; i++) {
        const int c = tid + i * 256;
        const int kt2 = c >> 8, t8 = (c >> 5) & 7, lane = c & 31;
        const uint32_t w = (uint32_t)(s * PW_STAGE + 2048 + (kt2 * 8 + t8) * 128 + lane * 4);
        const long gb = ((long)((nt0 + t8) * 64 + kt0 + kt2) * 32 + lane) * 8;
        cp16(sb + w * 4, &Bh[gb]);
    }
#pragma unroll
    for (int i = 0; i < 2; i++) {
        const int c = tid + i * 256;
        const int kt2 = c >> 8, t8 = (c >> 5) & 7, lane = c & 31;
        const uint32_t w = (uint32_t)(s * PW_STAGE + 4096 + (kt2 * 8 + t8) * 128 + lane * 4);
        const long gb = ((long)((nt0 + t8) * 64 + kt0 + kt2) * 32 + lane) * 8;
        cp16(sb + w * 4, &Bl[gb]);
    }
    cp_commit();
}

__global__ void __launch_bounds__(256, 2) gemm_proj_kernel(
    int M, int N, int K,
    const half* __restrict__ Af,
    const half* __restrict__ Bh, const half* __restrict__ Bl,
    const float* __restrict__ bias, float* __restrict__ C)
{
    extern __shared__ uint32_t smw[];
    const uint32_t sb = (uint32_t)__cvta_generic_to_shared(smw);

    const int tid  = threadIdx.x;
    const int wid  = tid >> 5, lane = tid & 31;
    const int gr   = lane >> 2, tg = lane & 3;
    const int wr   = wid >> 2,  wc = wid & 3;
    const int m0   = blockIdx.y * 128;
    const int n0   = blockIdx.x * 128;
    const int mt0  = m0 >> 4, nt0 = n0 >> 4;

    float acc[4][4][4];
#pragma unroll
    for (int i = 0; i < 4; i++)
#pragma unroll
        for (int j = 0; j < 4; j++)
#pragma unroll
            for (int r = 0; r < 4; r++) acc[i][j][r] = 0.f;

    const int nIter = K / 32;
    proj_stage_cp(sb, 0, tid, Af, Bh, Bl, mt0, nt0, 0);
    proj_stage_cp(sb, 1, tid, Af, Bh, Bl, mt0, nt0, 2);

    int stq = 0;
    for (int it = 0; it < nIter; it++) {
        if (it + 1 < nIter) cp_wait<1>(); else cp_wait<0>();
        __syncthreads();
        if (it + 2 < nIter) {
            int s2 = stq + 2; if (s2 >= 3) s2 -= 3;
            proj_stage_cp(sb, s2, tid, Af, Bh, Bl, mt0, nt0, (it + 2) * 2);
        }

        const uint32_t* base = smw + stq * PW_STAGE;
#pragma unroll
        for (int ks = 0; ks < 2; ks++) {
            uint4 af[4];
#pragma unroll
            for (int mt = 0; mt < 4; mt++) {
                const int o = (ks * 8 + wr * 4 + mt) * 128 + lane * 4;
                af[mt] = *(const uint4*)(base + o);
            }
#pragma unroll
            for (int j = 0; j < 2; j++) {
                const int o = (ks * 8 + wc * 2 + j) * 128 + lane * 4;
                uint4 bh4 = *(const uint4*)(base + 2048 + o);
                uint4 bl4 = *(const uint4*)(base + 4096 + o);
                const uint32_t bx[2][2] = {{bh4.x, bh4.y}, {bh4.z, bh4.w}};
                const uint32_t cx[2][2] = {{bl4.x, bl4.y}, {bl4.z, bl4.w}};
#pragma unroll
                for (int jj = 0; jj < 2; jj++)
#pragma unroll
                    for (int mt = 0; mt < 4; mt++)
                        mma_f16(acc[mt][2 * j + jj], (const uint32_t*)&af[mt],
                                bx[jj][0], bx[jj][1]);
#pragma unroll
                for (int jj = 0; jj < 2; jj++)
#pragma unroll
                    for (int mt = 0; mt < 4; mt++)
                        mma_f16(acc[mt][2 * j + jj], (const uint32_t*)&af[mt],
                                cx[jj][0], cx[jj][1]);
            }
        }
        if (++stq == 3) stq = 0;
    }

#pragma unroll
    for (int nt = 0; nt < 4; nt++) {
        const int col = n0 + wc * 32 + nt * 8 + tg * 2;
        const float2 bv = *(const float2*)&bias[col];
#pragma unroll
        for (int mt = 0; mt < 4; mt++) {
            const int row = m0 + wr * 64 + mt * 16 + gr;
            *(float2*)&C[(long)row * N + col] =
                make_float2(acc[mt][nt][0] + bv.x, acc[mt][nt][1] + bv.y);
            *(float2*)&C[(long)(row + 8) * N + col] =
                make_float2(acc[mt][nt][2] + bv.x, acc[mt][nt][3] + bv.y);
        }
    }
}

// ---------------------------------------------------------------------------
// Attention: 256 thr (8 warps), warp = 16 q-rows, BQ=128, BK=64, 3-stage
// cp.async (round-13 structure), Q PERSISTENT in registers.
// ---------------------------------------------------------------------------
#define AW_STAGE 8192
#define AT_SMEM_BYTES (3 * AW_STAGE * 4)

__device__ __forceinline__ void attn_stage_cp(
    uint32_t sb, int s, int tid, int bh32,
    const bf16* __restrict__ kh, const bf16* __restrict__ kl,
    const bf16* __restrict__ vth, const bf16* __restrict__ vtl,
    int jt0)
{
#pragma unroll
    for (int q = 0; q < 2; q++) {
        const int c = q * 256 + tid;
        const int dt = c >> 7, tt = (c >> 5) & 3, lane = c & 31;
        const long gk = ((long)((bh32 * 128 + jt0 + tt) * 4 + dt) * 32 + lane) * 8;
        const long gv = ((long)((bh32 * 4 + dt) * 128 + jt0 + tt) * 32 + lane) * 8;
        const uint32_t wk = (uint32_t)(s * AW_STAGE + (dt * 4 + tt) * 128 + lane * 4);
        const uint32_t wv = (uint32_t)(s * AW_STAGE + 4096 + (tt * 4 + dt) * 128 + lane * 4);
        cp16(sb + wk * 4,          &kh[gk]);
        cp16(sb + (wk + 2048) * 4, &kl[gk]);
        cp16(sb + wv * 4,          &vth[gv]);
        cp16(sb + (wv + 2048) * 4, &vtl[gv]);
    }
    cp_commit();
}

__global__ void __launch_bounds__(256, 2) attn_kernel(
    const uint32_t* __restrict__ qh32, const uint32_t* __restrict__ ql32,
    const bf16* __restrict__ kh, const bf16* __restrict__ kl,
    const bf16* __restrict__ vth, const bf16* __restrict__ vtl,
    uint32_t* __restrict__ yf32)
{
    extern __shared__ uint32_t smw[];
    const uint32_t sb = (uint32_t)__cvta_generic_to_shared(smw);

    const int tid  = threadIdx.x;
    const int wid  = tid >> 5, lane = tid & 31;
    const int gr   = lane >> 2, tg = lane & 3;
    const int bh32 = blockIdx.y;
    const int b    = bh32 >> 4, h = bh32 & 15;
    const int qa   = blockIdx.x * 128 + wid * 16;
    const int qt   = bh32 * 128 + (qa >> 4);

    attn_stage_cp(sb, 0, tid, bh32, kh, kl, vth, vtl, 0);
    attn_stage_cp(sb, 1, tid, bh32, kh, kl, vth, vtl, 4);

    // Q fragments: persistent in registers (loads overlap prologue cp.async)
    uint4 qfh[4], qfl[4];
#pragma unroll
    for (int kt = 0; kt < 4; kt++) {
        const int a = ((qt * 4 + kt) * 32 + lane) * 4;
        qfh[kt] = *(const uint4*)(qh32 + a);
        qfl[kt] = *(const uint4*)(ql32 + a);
    }

    float oacc[8][4];
#pragma unroll
    for (int nt = 0; nt < 8; nt++)
#pragma unroll
        for (int r = 0; r < 4; r++) oacc[nt][r] = 0.f;
    float lA = 0.f, lB = 0.f;

    int stq = 0;
    for (int jt = 0; jt < 32; jt++) {
        if (jt + 1 < 32) cp_wait<1>(); else cp_wait<0>();
        __syncthreads();
        if (jt + 2 < 32) {
            int s2 = stq + 2; if (s2 >= 3) s2 -= 3;
            attn_stage_cp(sb, s2, tid, bh32, kh, kl, vth, vtl, (jt + 2) * 4);
        }
        const uint32_t* base = smw + stq * AW_STAGE;

        // ---- S = Q K^T (3xBF16) ----
        float sacc[8][4];
#pragma unroll
        for (int nt = 0; nt < 8; nt++)
#pragma unroll
            for (int r = 0; r < 4; r++) sacc[nt][r] = 0.f;

#pragma unroll
        for (int kt = 0; kt < 4; kt++) {
#pragma unroll
            for (int hp = 0; hp < 2; hp++) {
                uint4 k4h[2], k4l[2];
#pragma unroll
                for (int p = 0; p < 2; p++) {
                    const int o = (kt * 4 + 2 * hp + p) * 128 + lane * 4;
                    k4h[p] = *(const uint4*)(base + o);
                    k4l[p] = *(const uint4*)(base + 2048 + o);
                }
#pragma unroll
                for (int p = 0; p < 2; p++) {
                    const int nt0_ = (2 * hp + p) * 2;
                    mma_bf16(sacc[nt0_],     (const uint32_t*)&qfh[kt], k4h[p].x, k4h[p].y);
                    mma_bf16(sacc[nt0_ + 1], (const uint32_t*)&qfh[kt], k4h[p].z, k4h[p].w);
                }
#pragma unroll
                for (int p = 0; p < 2; p++) {
                    const int nt0_ = (2 * hp + p) * 2;
                    mma_bf16(sacc[nt0_],     (const uint32_t*)&qfh[kt], k4l[p].x, k4l[p].y);
                    mma_bf16(sacc[nt0_ + 1], (const uint32_t*)&qfh[kt], k4l[p].z, k4l[p].w);
                }
#pragma unroll
                for (int p = 0; p < 2; p++) {
                    const int nt0_ = (2 * hp + p) * 2;
                    mma_bf16(sacc[nt0_],     (const uint32_t*)&qfl[kt], k4h[p].x, k4h[p].y);
                    mma_bf16(sacc[nt0_ + 1], (const uint32_t*)&qfl[kt], k4h[p].z, k4h[p].w);
                }
            }
        }

        // ---- softmax: p = 2^s; pack to bf16 P-fragments ----
        uint32_t pah[4][4], pal[4][4];
#pragma unroll
        for (int nt = 0; nt < 8; nt++) {
            float* s4 = sacc[nt];
            s4[0] = ex2f(s4[0]);
            s4[1] = ex2f(s4[1]);
            s4[2] = ex2f(s4[2]);
            s4[3] = ex2f(s4[3]);
            lA += s4[0] + s4[1];
            lB += s4[2] + s4[3];
            const int kt = nt >> 1, i = nt & 1;
            uint32_t w0 = pack2(s4[0], s4[1]);
            uint32_t w1 = pack2(s4[2], s4[3]);
            pah[kt][2 * i]     = w0;
            pah[kt][2 * i + 1] = w1;
            __nv_bfloat162 b0 = *(__nv_bfloat162*)&w0;
            __nv_bfloat162 b1 = *(__nv_bfloat162*)&w1;
            float2 f0 = __bfloat1622float2(b0);
            float2 f1 = __bfloat1622float2(b1);
            pal[kt][2 * i]     = pack2(s4[0] - f0.x, s4[1] - f0.y);
            pal[kt][2 * i + 1] = pack2(s4[2] - f1.x, s4[3] - f1.y);
        }

        // ---- O += P V ----
#pragma unroll
        for (int kt = 0; kt < 4; kt++) {
#pragma unroll
            for (int hp = 0; hp < 2; hp++) {
                uint4 v4h[2], v4l[2];
#pragma unroll
                for (int p = 0; p < 2; p++) {
                    const int o = 4096 + (kt * 4 + 2 * hp + p) * 128 + lane * 4;
                    v4h[p] = *(const uint4*)(base + o);
                    v4l[p] = *(const uint4*)(base + 2048 + o);
                }
#pragma unroll
                for (int p = 0; p < 2; p++) {
                    const int nt0_ = (2 * hp + p) * 2;
                    mma_bf16(oacc[nt0_],     pah[kt], v4h[p].x, v4h[p].y);
                    mma_bf16(oacc[nt0_ + 1], pah[kt], v4h[p].z, v4h[p].w);
                }
#pragma unroll
                for (int p = 0; p < 2; p++) {
                    const int nt0_ = (2 * hp + p) * 2;
                    mma_bf16(oacc[nt0_],     pah[kt], v4l[p].x, v4l[p].y);
                    mma_bf16(oacc[nt0_ + 1], pah[kt], v4l[p].z, v4l[p].w);
                }
#pragma unroll
                for (int p = 0; p < 2; p++) {
                    const int nt0_ = (2 * hp + p) * 2;
                    mma_bf16(oacc[nt0_],     pal[kt], v4h[p].x, v4h[p].y);
                    mma_bf16(oacc[nt0_ + 1], pal[kt], v4h[p].z, v4h[p].w);
                }
            }
        }
        if (++stq == 3) stq = 0;
    }

    // reductions + fp16 single-plane epilogue
    lA += __shfl_xor_sync(0xffffffffu, lA, 1);
    lA += __shfl_xor_sync(0xffffffffu, lA, 2);
    lB += __shfl_xor_sync(0xffffffffu, lB, 1);
    lB += __shfl_xor_sync(0xffffffffu, lB, 2);
    const float invA = 1.0f / (lA * 8.0f);
    const float invB = 1.0f / (lB * 8.0f);
    const int t = qa + gr;
    const int mtile = (b * TT + t) >> 4;
#pragma unroll
    for (int nt = 0; nt < 8; nt++) {
        const int ctile = h * 4 + (nt >> 1);
        const int a32 = ((mtile * 64 + ctile) * 32 + lane) * 4;
        const int w0 = 2 * (nt & 1);
        yf32[a32 + w0]     = pack2h(oacc[nt][0] * invA, oacc[nt][1] * invA);
        yf32[a32 + w0 + 1] = pack2h(oacc[nt][2] * invB, oacc[nt][3] * invB);
    }
}

// ---------------------------------------------------------------------------
extern "C" void kernel_launch(void* const* d_in, const int* in_sizes, int n_in,
                              void* d_out, int out_size)
{
    const float* x      = (const float*)d_in[0];
    const float* W_attn = (const float*)d_in[1];
    const float* b_attn = (const float*)d_in[2];
    const float* W_proj = (const float*)d_in[3];
    const float* b_proj = (const float*)d_in[4];
    float* out = (float*)d_out;

    bf16 *xh, *xl, *wth, *wtl;
    bf16 *qhp, *qlp, *khp, *klp, *vthp, *vtlp;
    half *wpfh, *wpfl, *yf;
    cudaGetSymbolAddress((void**)&xh,   g_xh);
    cudaGetSymbolAddress((void**)&xl,   g_xl);
    cudaGetSymbolAddress((void**)&wth,  g_wth);
    cudaGetSymbolAddress((void**)&wtl,  g_wtl);
    cudaGetSymbolAddress((void**)&wpfh, g_wpfh);
    cudaGetSymbolAddress((void**)&wpfl, g_wpfl);
    cudaGetSymbolAddress((void**)&qhp,  g_qh);
    cudaGetSymbolAddress((void**)&qlp,  g_ql);
    cudaGetSymbolAddress((void**)&khp,  g_kh);
    cudaGetSymbolAddress((void**)&klp,  g_kl);
    cudaGetSymbolAddress((void**)&vthp, g_vth);
    cudaGetSymbolAddress((void**)&vtlp, g_vtl);
    cudaGetSymbolAddress((void**)&yf,   g_yf);

    cudaFuncSetAttribute(gemm_qkv_kernel,
                         cudaFuncAttributeMaxDynamicSharedMemorySize,
                         GEMM_SMEM_BYTES);
    cudaFuncSetAttribute(gemm_proj_kernel,
                         cudaFuncAttributeMaxDynamicSharedMemorySize,
                         PROJ_SMEM_BYTES);
    cudaFuncSetAttribute(attn_kernel,
                         cudaFuncAttributeMaxDynamicSharedMemorySize,
                         AT_SMEM_BYTES);

    // prepasses
    split_a_kernel<<<(NTOK * CC / 4 + 255) / 256, 256>>>(
        x, (uint32_t*)xh, (uint32_t*)xl, NTOK * CC / 4);
    tsp_b_kernel<<<dim3(C3 / 32, CC / 32), 256>>>(W_attn, wth, wtl, C3);
    tsp_b_f16_kernel<<<dim3(CC / 32, CC / 32), 256>>>(W_proj, wpfh, wpfl, CC);

    // 1) QKV GEMM + routing epilogue (Q scaled by log2e)
    gemm_qkv_kernel<<<dim3(C3 / 128, NTOK / 128), 256, GEMM_SMEM_BYTES>>>(
        NTOK, C3, CC, xh, xl, wth, wtl, b_attn,
        (uint32_t*)qhp, (uint32_t*)qlp, (uint32_t*)khp, (uint32_t*)klp,
        vthp, vtlp);

    // 2) attention
    attn_kernel<<<dim3(TT / 128, BB * NH), 256, AT_SMEM_BYTES>>>(
        (const uint32_t*)qhp, (const uint32_t*)qlp, khp, klp, vthp, vtlp,
        (uint32_t*)yf);

    // 3) proj GEMM (fp16 2-term)
    gemm_proj_kernel<<<dim3(CC / 128, NTOK / 128), 256, PROJ_SMEM_BYTES>>>(
        NTOK, CC, CC, yf, wpfh, wpfl, b_proj, out);
}

// round 16
// speedup vs baseline: 1.4503x; 1.0040x over previous
#include <cuda_runtime.h>
#include <cuda_bf16.h>
#include <cuda_fp16.h>
#include <math.h>
#include <stdint.h>

#define BB   2
#define TT   2048
#define CC   1024
#define NH   16
#define DH   64
#define NTOK (BB * TT)
#define C3   (3 * CC)
#define LOG2E 1.4426950408889634f

typedef __nv_bfloat16 bf16;

// ---------------------------------------------------------------------------
// Fragment-major layouts (16x16 tiles, 32 lanes x 16B) — see round 11 notes.
// ---------------------------------------------------------------------------
__device__ bf16 g_xh[NTOK * CC],  g_xl[NTOK * CC];   // A-type
__device__ bf16 g_wth[C3 * CC],   g_wtl[C3 * CC];    // B-type
__device__ half g_wpfh[CC * CC],  g_wpfl[CC * CC];   // B-type fp16 (proj)
__device__ bf16 g_qh[NTOK * CC],  g_ql[NTOK * CC];   // A-type per (b,h)
__device__ bf16 g_kh[NTOK * CC],  g_kl[NTOK * CC];   // B-type per (b,h)
__device__ bf16 g_vth[NTOK * CC], g_vtl[NTOK * CC];  // B-type transposed
__device__ half g_yf[NTOK * CC];                     // A-type fp16 single

// ---------------------------------------------------------------------------
// helpers
// ---------------------------------------------------------------------------
__device__ __forceinline__ float bfr(float x) {
    return __bfloat162float(__float2bfloat16(x));
}
__device__ __forceinline__ void splitb(float x, float& h, float& l) {
    h = bfr(x);
    l = bfr(x - h);
}
__device__ __forceinline__ uint32_t pack2(float a, float b) {
    __nv_bfloat162 t = __floats2bfloat162_rn(a, b);
    return *(uint32_t*)&t;
}
__device__ __forceinline__ uint32_t pack2h(float a, float b) {
    __half2 t = __floats2half2_rn(a, b);
    return *(uint32_t*)&t;
}
__device__ __forceinline__ float ex2f(float x) {
    float y; asm("ex2.approx.f32 %0, %1;" : "=f"(y) : "f"(x)); return y;
}
__device__ __forceinline__ void mma_bf16(float* d, const uint32_t* a,
                                         uint32_t b0, uint32_t b1) {
    asm volatile(
        "mma.sync.aligned.m16n8k16.row.col.f32.bf16.bf16.f32 "
        "{%0,%1,%2,%3}, {%4,%5,%6,%7}, {%8,%9}, {%0,%1,%2,%3};"
        : "+f"(d[0]), "+f"(d[1]), "+f"(d[2]), "+f"(d[3])
        : "r"(a[0]), "r"(a[1]), "r"(a[2]), "r"(a[3]), "r"(b0), "r"(b1));
}
__device__ __forceinline__ void mma_f16(float* d, const uint32_t* a,
                                        uint32_t b0, uint32_t b1) {
    asm volatile(
        "mma.sync.aligned.m16n8k16.row.col.f32.f16.f16.f32 "
        "{%0,%1,%2,%3}, {%4,%5,%6,%7}, {%8,%9}, {%0,%1,%2,%3};"
        : "+f"(d[0]), "+f"(d[1]), "+f"(d[2]), "+f"(d[3])
        : "r"(a[0]), "r"(a[1]), "r"(a[2]), "r"(a[3]), "r"(b0), "r"(b1));
}
__device__ __forceinline__ void cp16(uint32_t d, const void* s) {
    asm volatile("cp.async.cg.shared.global [%0], [%1], 16;" :: "r"(d), "l"(s));
}
__device__ __forceinline__ void cp_commit() {
    asm volatile("cp.async.commit_group;");
}
template <int N> __device__ __forceinline__ void cp_wait() {
    asm volatile("cp.async.wait_group %0;" :: "n"(N));
}

// ---------------------------------------------------------------------------
// prepass 1: x -> A-type frag-major bf16 hi/lo
// ---------------------------------------------------------------------------
__global__ void __launch_bounds__(256) split_a_kernel(
    const float* __restrict__ in, uint32_t* __restrict__ oh,
    uint32_t* __restrict__ ol, int n4)
{
    const int i4 = blockIdx.x * 256 + threadIdx.x;
    if (i4 >= n4) return;
    const int g = i4 * 4;
    const int m = g >> 10, k0 = g & 1023;
    float4 v = *(const float4*)&in[g];

    const int r = m & 15, gr = r & 7, hi = (r >> 3) & 1;
    const int tile = ((m >> 4) << 6) + (k0 >> 4);
    const int p0 = (k0 & 15) >> 1;
#pragma unroll
    for (int q = 0; q < 2; q++) {
        const int p = p0 + q;
        const int lane = gr * 4 + (p & 3);
        const int w = hi + 2 * (p >> 2);
        const int a32 = (tile * 32 + lane) * 4 + w;
        float e0 = q ? v.z : v.x, e1 = q ? v.w : v.y;
        float h0, l0, h1, l1;
        splitb(e0, h0, l0);
        splitb(e1, h1, l1);
        oh[a32] = pack2(h0, h1);
        ol[a32] = pack2(l0, l1);
    }
}

// ---------------------------------------------------------------------------
// prepass 2a: W_attn[K][N] -> B-type frag-major bf16 hi/lo
// ---------------------------------------------------------------------------
__global__ void __launch_bounds__(256) tsp_b_kernel(
    const float* __restrict__ W, bf16* __restrict__ oh,
    bf16* __restrict__ ol, int N)
{
    __shared__ float t[32][33];
    const int bx = blockIdx.x * 32;
    const int by = blockIdx.y * 32;
    const int tx = threadIdx.x & 31, ty = threadIdx.x >> 5;
#pragma unroll
    for (int j = 0; j < 32; j += 8)
        t[ty + j][tx] = W[(long)(by + ty + j) * N + bx + tx];
    __syncthreads();
    const int k = by + tx;
    const int ki = k >> 4, kk = k & 15, p = kk >> 1, e = kk & 1;
#pragma unroll
    for (int j = 0; j < 32; j += 8) {
        const int n = bx + ty + j;
        const int c = n & 15;
        const int lane = (c & 7) * 4 + (p & 3);
        const int w = ((c >> 3) & 1) * 2 + (p >> 2);
        const long flat = ((long)(((n >> 4) << 6) + ki) * 32 + lane) * 8 + w * 2 + e;
        float h, l;
        splitb(t[tx][ty + j], h, l);
        oh[flat] = __float2bfloat16(h);
        ol[flat] = __float2bfloat16(l);
    }
}

// ---------------------------------------------------------------------------
// prepass 2b: W_proj[K][N] -> B-type frag-major FP16 hi/lo
// ---------------------------------------------------------------------------
__global__ void __launch_bounds__(256) tsp_b_f16_kernel(
    const float* __restrict__ W, half* __restrict__ oh,
    half* __restrict__ ol, int N)
{
    __shared__ float t[32][33];
    const int bx = blockIdx.x * 32;
    const int by = blockIdx.y * 32;
    const int tx = threadIdx.x & 31, ty = threadIdx.x >> 5;
#pragma unroll
    for (int j = 0; j < 32; j += 8)
        t[ty + j][tx] = W[(long)(by + ty + j) * N + bx + tx];
    __syncthreads();
    const int k = by + tx;
    const int ki = k >> 4, kk = k & 15, p = kk >> 1, e = kk & 1;
#pragma unroll
    for (int j = 0; j < 32; j += 8) {
        const int n = bx + ty + j;
        const int c = n & 15;
        const int lane = (c & 7) * 4 + (p & 3);
        const int w = ((c >> 3) & 1) * 2 + (p >> 2);
        const long flat = ((long)(((n >> 4) << 6) + ki) * 32 + lane) * 8 + w * 2 + e;
        const float v = t[tx][ty + j];
        half hh = __float2half_rn(v);
        half ll = __float2half_rn(v - __half2float(hh));
        oh[flat] = hh;
        ol[flat] = ll;
    }
}

// ---------------------------------------------------------------------------
// QKV GEMM (3xBF16): 256 thr, 8 warps (2x4), warp 64x32, CTA 128x128,
// BK=32, 3-stage cp.async (round-13 proven structure).
// ---------------------------------------------------------------------------
#define GW_STAGE 8192
#define GEMM_SMEM_BYTES (3 * GW_STAGE * 4)

__device__ __forceinline__ void gemm_stage_cp(
    uint32_t sb, int s, int tid,
    const bf16* __restrict__ Agh, const bf16* __restrict__ Agl,
    const bf16* __restrict__ Bgh, const bf16* __restrict__ Bgl,
    int mt0, int nt0, int kt0)
{
#pragma unroll
    for (int i = 0; i < 2; i++) {
        const int c = tid + i * 256;
        const int kt2 = c >> 8, t8 = (c >> 5) & 7, lane = c & 31;
        const uint32_t w = (uint32_t)(s * GW_STAGE + (kt2 * 8 + t8) * 128 + lane * 4);
        const long ga = ((long)((mt0 + t8) * 64 + kt0 + kt2) * 32 + lane) * 8;
        const long gb = ((long)((nt0 + t8) * 64 + kt0 + kt2) * 32 + lane) * 8;
        cp16(sb + w * 4,          &Agh[ga]);
        cp16(sb + (w + 2048) * 4, &Agl[ga]);
        cp16(sb + (w + 4096) * 4, &Bgh[gb]);
        cp16(sb + (w + 6144) * 4, &Bgl[gb]);
    }
    cp_commit();
}

__global__ void __launch_bounds__(256, 2) gemm_qkv_kernel(
    int M, int N, int K,
    const bf16* __restrict__ Agh, const bf16* __restrict__ Agl,
    const bf16* __restrict__ Bgh, const bf16* __restrict__ Bgl,
    const float* __restrict__ bias,
    uint32_t* __restrict__ qh32, uint32_t* __restrict__ ql32,
    uint32_t* __restrict__ kh32, uint32_t* __restrict__ kl32,
    bf16* __restrict__ vth, bf16* __restrict__ vtl)
{
    extern __shared__ uint32_t smw[];
    const uint32_t sb = (uint32_t)__cvta_generic_to_shared(smw);

    const int tid  = threadIdx.x;
    const int wid  = tid >> 5, lane = tid & 31;
    const int gr   = lane >> 2, tg = lane & 3;
    const int wr   = wid >> 2,  wc = wid & 3;
    const int m0   = blockIdx.y * 128;
    const int n0   = blockIdx.x * 128;
    const int mt0  = m0 >> 4, nt0 = n0 >> 4;

    float acc[4][4][4];
#pragma unroll
    for (int i = 0; i < 4; i++)
#pragma unroll
        for (int j = 0; j < 4; j++)
#pragma unroll
            for (int r = 0; r < 4; r++) acc[i][j][r] = 0.f;

    const int nIter = K / 32;
    gemm_stage_cp(sb, 0, tid, Agh, Agl, Bgh, Bgl, mt0, nt0, 0);
    gemm_stage_cp(sb, 1, tid, Agh, Agl, Bgh, Bgl, mt0, nt0, 2);

    int stq = 0;
    for (int it = 0; it < nIter; it++) {
        if (it + 1 < nIter) cp_wait<1>(); else cp_wait<0>();
        __syncthreads();
        if (it + 2 < nIter) {
            int s2 = stq + 2; if (s2 >= 3) s2 -= 3;
            gemm_stage_cp(sb, s2, tid, Agh, Agl, Bgh, Bgl,
                          mt0, nt0, (it + 2) * 2);
        }

        const uint32_t* base = smw + stq * GW_STAGE;
#pragma unroll
        for (int ks = 0; ks < 2; ks++) {
            uint4 afh[4], afl[4];
#pragma unroll
            for (int mt = 0; mt < 4; mt++) {
                const int o = (ks * 8 + wr * 4 + mt) * 128 + lane * 4;
                afh[mt] = *(const uint4*)(base + o);
                afl[mt] = *(const uint4*)(base + 2048 + o);
            }
#pragma unroll
            for (int j = 0; j < 2; j++) {
                const int o = (ks * 8 + wc * 2 + j) * 128 + lane * 4;
                uint4 bh4 = *(const uint4*)(base + 4096 + o);
                uint4 bl4 = *(const uint4*)(base + 6144 + o);
                const uint32_t bx[2][2] = {{bh4.x, bh4.y}, {bh4.z, bh4.w}};
                const uint32_t cx[2][2] = {{bl4.x, bl4.y}, {bl4.z, bl4.w}};
#pragma unroll
                for (int jj = 0; jj < 2; jj++)
#pragma unroll
                    for (int mt = 0; mt < 4; mt++)
                        mma_bf16(acc[mt][2 * j + jj], (const uint32_t*)&afh[mt],
                                 bx[jj][0], bx[jj][1]);
#pragma unroll
                for (int jj = 0; jj < 2; jj++)
#pragma unroll
                    for (int mt = 0; mt < 4; mt++)
                        mma_bf16(acc[mt][2 * j + jj], (const uint32_t*)&afh[mt],
                                 cx[jj][0], cx[jj][1]);
#pragma unroll
                for (int jj = 0; jj < 2; jj++)
#pragma unroll
                    for (int mt = 0; mt < 4; mt++)
                        mma_bf16(acc[mt][2 * j + jj], (const uint32_t*)&afl[mt],
                                 bx[jj][0], bx[jj][1]);
            }
        }
        if (++stq == 3) stq = 0;
    }

    // ---- routing epilogue ----
#pragma unroll
    for (int nt = 0; nt < 4; nt++) {
        const int col = n0 + wc * 32 + nt * 8 + tg * 2;
        const float2 bv = *(const float2*)&bias[col];
#pragma unroll
        for (int mt = 0; mt < 4; mt++) {
            const int row = m0 + wr * 64 + mt * 16 + gr;
            const float v00 = acc[mt][nt][0] + bv.x;
            const float v01 = acc[mt][nt][1] + bv.y;
            const float v10 = acc[mt][nt][2] + bv.x;
            const float v11 = acc[mt][nt][3] + bv.y;
            const int sec = col >> 10;
            const int dc  = col & 1023;
            const int hh  = dc >> 6, d0 = dc & 63;
#pragma unroll
            for (int rr = 0; rr < 2; rr++) {
                const int m = row + rr * 8;
                const int b = m >> 11, t = m & 2047;
                float u0 = rr ? v10 : v00;
                float u1 = rr ? v11 : v01;
                float h0, l0, h1, l1;
                if (sec == 0) {
                    u0 *= LOG2E; u1 *= LOG2E;
                    splitb(u0, h0, l0); splitb(u1, h1, l1);
                    const int lane_ = (t & 7) * 4 + ((d0 >> 1) & 3);
                    const int w = ((t >> 3) & 1) + 2 * ((d0 >> 3) & 1);
                    const int tile = ((b * NH + hh) * 128 + (t >> 4)) * 4 + (d0 >> 4);
                    const int a32 = (tile * 32 + lane_) * 4 + w;
                    qh32[a32] = pack2(h0, h1);
                    ql32[a32] = pack2(l0, l1);
                } else if (sec == 1) {
                    splitb(u0, h0, l0); splitb(u1, h1, l1);
                    const int lane_ = (t & 7) * 4 + ((d0 >> 1) & 3);
                    const int w = ((t >> 3) & 1) * 2 + ((d0 >> 3) & 1);
                    const int tile = ((b * NH + hh) * 128 + (t >> 4)) * 4 + (d0 >> 4);
                    const int a32 = (tile * 32 + lane_) * 4 + w;
                    kh32[a32] = pack2(h0, h1);
                    kl32[a32] = pack2(l0, l1);
                } else {
                    splitb(u0, h0, l0); splitb(u1, h1, l1);
                    const int lane_ = (d0 & 7) * 4 + ((t >> 1) & 3);
                    const int w = ((d0 >> 3) & 1) * 2 + ((t >> 3) & 1);
                    const int tile = ((b * NH + hh) * 4 + (d0 >> 4)) * 128 + (t >> 4);
                    const long f = ((long)tile * 32 + lane_) * 8 + w * 2 + (t & 1);
                    vth[f] = __float2bfloat16(h0);
                    vtl[f] = __float2bfloat16(l0);
                    vth[f + 32] = __float2bfloat16(h1);
                    vtl[f + 32] = __float2bfloat16(l1);
                }
            }
        }
    }
}

// ---------------------------------------------------------------------------
// PROJ GEMM (fp16 2-term), round-13 structure.
// ---------------------------------------------------------------------------
#define PW_STAGE 6144
#define PROJ_SMEM_BYTES (3 * PW_STAGE * 4)

__device__ __forceinline__ void proj_stage_cp(
    uint32_t sb, int s, int tid,
    const half* __restrict__ Af,
    const half* __restrict__ Bh, const half* __restrict__ Bl,
    int mt0, int nt0, int kt0)
{
#pragma unroll
    for (int i = 0; i < 2; i++) {
        const int c = tid + i * 256;
        const int kt2 = c >> 8, t8 = (c >> 5) & 7, lane = c & 31;
        const uint32_t w = (uint32_t)(s * PW_STAGE + (kt2 * 8 + t8) * 128 + lane * 4);
        const long ga = ((long)((mt0 + t8) * 64 + kt0 + kt2) * 32 + lane) * 8;
        cp16(sb + w * 4, &Af[ga]);
    }
#pragma unroll
    for (int i = 0; i < 2; i++) {
        const int c = tid + i * 256;
        const int kt2 = c >> 8, t8 = (c >> 5) & 7, lane = c & 31;
        const uint32_t w = (uint32_t)(s * PW_STAGE + 2048 + (kt2 * 8 + t8) * 128 + lane * 4);
        const long gb = ((long)((nt0 + t8) * 64 + kt0 + kt2) * 32 + lane) * 8;
        cp16(sb + w * 4, &Bh[gb]);
    }
#pragma unroll
    for (int i = 0; i < 2; i++) {
        const int c = tid + i * 256;
        const int kt2 = c >> 8, t8 = (c >> 5) & 7, lane = c & 31;
        const uint32_t w = (uint32_t)(s * PW_STAGE + 4096 + (kt2 * 8 + t8) * 128 + lane * 4);
        const long gb = ((long)((nt0 + t8) * 64 + kt0 + kt2) * 32 + lane) * 8;
        cp16(sb + w * 4, &Bl[gb]);
    }
    cp_commit();
}

__global__ void __launch_bounds__(256, 2) gemm_proj_kernel(
    int M, int N, int K,
    const half* __restrict__ Af,
    const half* __restrict__ Bh, const half* __restrict__ Bl,
    const float* __restrict__ bias, float* __restrict__ C)
{
    extern __shared__ uint32_t smw[];
    const uint32_t sb = (uint32_t)__cvta_generic_to_shared(smw);

    const int tid  = threadIdx.x;
    const int wid  = tid >> 5, lane = tid & 31;
    const int gr   = lane >> 2, tg = lane & 3;
    const int wr   = wid >> 2,  wc = wid & 3;
    const int m0   = blockIdx.y * 128;
    const int n0   = blockIdx.x * 128;
    const int mt0  = m0 >> 4, nt0 = n0 >> 4;

    float acc[4][4][4];
#pragma unroll
    for (int i = 0; i < 4; i++)
#pragma unroll
        for (int j = 0; j < 4; j++)
#pragma unroll
            for (int r = 0; r < 4; r++) acc[i][j][r] = 0.f;

    const int nIter = K / 32;
    proj_stage_cp(sb, 0, tid, Af, Bh, Bl, mt0, nt0, 0);
    proj_stage_cp(sb, 1, tid, Af, Bh, Bl, mt0, nt0, 2);

    int stq = 0;
    for (int it = 0; it < nIter; it++) {
        if (it + 1 < nIter) cp_wait<1>(); else cp_wait<0>();
        __syncthreads();
        if (it + 2 < nIter) {
            int s2 = stq + 2; if (s2 >= 3) s2 -= 3;
            proj_stage_cp(sb, s2, tid, Af, Bh, Bl, mt0, nt0, (it + 2) * 2);
        }

        const uint32_t* base = smw + stq * PW_STAGE;
#pragma unroll
        for (int ks = 0; ks < 2; ks++) {
            uint4 af[4];
#pragma unroll
            for (int mt = 0; mt < 4; mt++) {
                const int o = (ks * 8 + wr * 4 + mt) * 128 + lane * 4;
                af[mt] = *(const uint4*)(base + o);
            }
#pragma unroll
            for (int j = 0; j < 2; j++) {
                const int o = (ks * 8 + wc * 2 + j) * 128 + lane * 4;
                uint4 bh4 = *(const uint4*)(base + 2048 + o);
                uint4 bl4 = *(const uint4*)(base + 4096 + o);
                const uint32_t bx[2][2] = {{bh4.x, bh4.y}, {bh4.z, bh4.w}};
                const uint32_t cx[2][2] = {{bl4.x, bl4.y}, {bl4.z, bl4.w}};
#pragma unroll
                for (int jj = 0; jj < 2; jj++)
#pragma unroll
                    for (int mt = 0; mt < 4; mt++)
                        mma_f16(acc[mt][2 * j + jj], (const uint32_t*)&af[mt],
                                bx[jj][0], bx[jj][1]);
#pragma unroll
                for (int jj = 0; jj < 2; jj++)
#pragma unroll
                    for (int mt = 0; mt < 4; mt++)
                        mma_f16(acc[mt][2 * j + jj], (const uint32_t*)&af[mt],
                                cx[jj][0], cx[jj][1]);
            }
        }
        if (++stq == 3) stq = 0;
    }

#pragma unroll
    for (int nt = 0; nt < 4; nt++) {
        const int col = n0 + wc * 32 + nt * 8 + tg * 2;
        const float2 bv = *(const float2*)&bias[col];
#pragma unroll
        for (int mt = 0; mt < 4; mt++) {
            const int row = m0 + wr * 64 + mt * 16 + gr;
            *(float2*)&C[(long)row * N + col] =
                make_float2(acc[mt][nt][0] + bv.x, acc[mt][nt][1] + bv.y);
            *(float2*)&C[(long)(row + 8) * N + col] =
                make_float2(acc[mt][nt][2] + bv.x, acc[mt][nt][3] + bv.y);
        }
    }
}

// ---------------------------------------------------------------------------
// Attention: 512 thr (16 warps), warp = 16 q-rows, BQ=256, BK=64, 3-stage
// cp.async, Q persistent in regs. Grid = 8 x 32 = 256 CTAs -> SINGLE WAVE.
// ---------------------------------------------------------------------------
#define AW_STAGE 8192
#define AT_SMEM_BYTES (3 * AW_STAGE * 4)

__device__ __forceinline__ void attn_stage_cp(
    uint32_t sb, int s, int tid, int bh32,
    const bf16* __restrict__ kh, const bf16* __restrict__ kl,
    const bf16* __restrict__ vth, const bf16* __restrict__ vtl,
    int jt0)
{
    // 512 chunks, 512 threads: one chunk per thread per array
    const int c = tid;
    const int dt = c >> 7, tt = (c >> 5) & 3, lane = c & 31;
    const long gk = ((long)((bh32 * 128 + jt0 + tt) * 4 + dt) * 32 + lane) * 8;
    const long gv = ((long)((bh32 * 4 + dt) * 128 + jt0 + tt) * 32 + lane) * 8;
    const uint32_t wk = (uint32_t)(s * AW_STAGE + (dt * 4 + tt) * 128 + lane * 4);
    const uint32_t wv = (uint32_t)(s * AW_STAGE + 4096 + (tt * 4 + dt) * 128 + lane * 4);
    cp16(sb + wk * 4,          &kh[gk]);
    cp16(sb + (wk + 2048) * 4, &kl[gk]);
    cp16(sb + wv * 4,          &vth[gv]);
    cp16(sb + (wv + 2048) * 4, &vtl[gv]);
    cp_commit();
}

__global__ void __launch_bounds__(512, 1) attn_kernel(
    const uint32_t* __restrict__ qh32, const uint32_t* __restrict__ ql32,
    const bf16* __restrict__ kh, const bf16* __restrict__ kl,
    const bf16* __restrict__ vth, const bf16* __restrict__ vtl,
    uint32_t* __restrict__ yf32)
{
    extern __shared__ uint32_t smw[];
    const uint32_t sb = (uint32_t)__cvta_generic_to_shared(smw);

    const int tid  = threadIdx.x;
    const int wid  = tid >> 5, lane = tid & 31;
    const int gr   = lane >> 2, tg = lane & 3;
    const int bh32 = blockIdx.y;
    const int b    = bh32 >> 4, h = bh32 & 15;
    const int qa   = blockIdx.x * 256 + wid * 16;
    const int qt   = bh32 * 128 + (qa >> 4);

    attn_stage_cp(sb, 0, tid, bh32, kh, kl, vth, vtl, 0);
    attn_stage_cp(sb, 1, tid, bh32, kh, kl, vth, vtl, 4);

    // Q fragments: persistent in registers (loads overlap prologue cp.async)
    uint4 qfh[4], qfl[4];
#pragma unroll
    for (int kt = 0; kt < 4; kt++) {
        const int a = ((qt * 4 + kt) * 32 + lane) * 4;
        qfh[kt] = *(const uint4*)(qh32 + a);
        qfl[kt] = *(const uint4*)(ql32 + a);
    }

    float oacc[8][4];
#pragma unroll
    for (int nt = 0; nt < 8; nt++)
#pragma unroll
        for (int r = 0; r < 4; r++) oacc[nt][r] = 0.f;
    float lA = 0.f, lB = 0.f;

    int stq = 0;
    for (int jt = 0; jt < 32; jt++) {
        if (jt + 1 < 32) cp_wait<1>(); else cp_wait<0>();
        __syncthreads();
        if (jt + 2 < 32) {
            int s2 = stq + 2; if (s2 >= 3) s2 -= 3;
            attn_stage_cp(sb, s2, tid, bh32, kh, kl, vth, vtl, (jt + 2) * 4);
        }
        const uint32_t* base = smw + stq * AW_STAGE;

        // ---- S = Q K^T (3xBF16) ----
        float sacc[8][4];
#pragma unroll
        for (int nt = 0; nt < 8; nt++)
#pragma unroll
            for (int r = 0; r < 4; r++) sacc[nt][r] = 0.f;

#pragma unroll
        for (int kt = 0; kt < 4; kt++) {
#pragma unroll
            for (int hp = 0; hp < 2; hp++) {
                uint4 k4h[2], k4l[2];
#pragma unroll
                for (int p = 0; p < 2; p++) {
                    const int o = (kt * 4 + 2 * hp + p) * 128 + lane * 4;
                    k4h[p] = *(const uint4*)(base + o);
                    k4l[p] = *(const uint4*)(base + 2048 + o);
                }
#pragma unroll
                for (int p = 0; p < 2; p++) {
                    const int nt0_ = (2 * hp + p) * 2;
                    mma_bf16(sacc[nt0_],     (const uint32_t*)&qfh[kt], k4h[p].x, k4h[p].y);
                    mma_bf16(sacc[nt0_ + 1], (const uint32_t*)&qfh[kt], k4h[p].z, k4h[p].w);
                }
#pragma unroll
                for (int p = 0; p < 2; p++) {
                    const int nt0_ = (2 * hp + p) * 2;
                    mma_bf16(sacc[nt0_],     (const uint32_t*)&qfh[kt], k4l[p].x, k4l[p].y);
                    mma_bf16(sacc[nt0_ + 1], (const uint32_t*)&qfh[kt], k4l[p].z, k4l[p].w);
                }
#pragma unroll
                for (int p = 0; p < 2; p++) {
                    const int nt0_ = (2 * hp + p) * 2;
                    mma_bf16(sacc[nt0_],     (const uint32_t*)&qfl[kt], k4h[p].x, k4h[p].y);
                    mma_bf16(sacc[nt0_ + 1], (const uint32_t*)&qfl[kt], k4h[p].z, k4h[p].w);
                }
            }
        }

        // ---- softmax: p = 2^s; pack to bf16 P-fragments ----
        uint32_t pah[4][4], pal[4][4];
#pragma unroll
        for (int nt = 0; nt < 8; nt++) {
            float* s4 = sacc[nt];
            s4[0] = ex2f(s4[0]);
            s4[1] = ex2f(s4[1]);
            s4[2] = ex2f(s4[2]);
            s4[3] = ex2f(s4[3]);
            lA += s4[0] + s4[1];
            lB += s4[2] + s4[3];
            const int kt = nt >> 1, i = nt & 1;
            uint32_t w0 = pack2(s4[0], s4[1]);
            uint32_t w1 = pack2(s4[2], s4[3]);
            pah[kt][2 * i]     = w0;
            pah[kt][2 * i + 1] = w1;
            __nv_bfloat162 b0 = *(__nv_bfloat162*)&w0;
            __nv_bfloat162 b1 = *(__nv_bfloat162*)&w1;
            float2 f0 = __bfloat1622float2(b0);
            float2 f1 = __bfloat1622float2(b1);
            pal[kt][2 * i]     = pack2(s4[0] - f0.x, s4[1] - f0.y);
            pal[kt][2 * i + 1] = pack2(s4[2] - f1.x, s4[3] - f1.y);
        }

        // ---- O += P V ----
#pragma unroll
        for (int kt = 0; kt < 4; kt++) {
#pragma unroll
            for (int hp = 0; hp < 2; hp++) {
                uint4 v4h[2], v4l[2];
#pragma unroll
                for (int p = 0; p < 2; p++) {
                    const int o = 4096 + (kt * 4 + 2 * hp + p) * 128 + lane * 4;
                    v4h[p] = *(const uint4*)(base + o);
                    v4l[p] = *(const uint4*)(base + 2048 + o);
                }
#pragma unroll
                for (int p = 0; p < 2; p++) {
                    const int nt0_ = (2 * hp + p) * 2;
                    mma_bf16(oacc[nt0_],     pah[kt], v4h[p].x, v4h[p].y);
                    mma_bf16(oacc[nt0_ + 1], pah[kt], v4h[p].z, v4h[p].w);
                }
#pragma unroll
                for (int p = 0; p < 2; p++) {
                    const int nt0_ = (2 * hp + p) * 2;
                    mma_bf16(oacc[nt0_],     pah[kt], v4l[p].x, v4l[p].y);
                    mma_bf16(oacc[nt0_ + 1], pah[kt], v4l[p].z, v4l[p].w);
                }
#pragma unroll
                for (int p = 0; p < 2; p++) {
                    const int nt0_ = (2 * hp + p) * 2;
                    mma_bf16(oacc[nt0_],     pal[kt], v4h[p].x, v4h[p].y);
                    mma_bf16(oacc[nt0_ + 1], pal[kt], v4h[p].z, v4h[p].w);
                }
            }
        }
        if (++stq == 3) stq = 0;
    }

    // reductions + fp16 single-plane epilogue
    lA += __shfl_xor_sync(0xffffffffu, lA, 1);
    lA += __shfl_xor_sync(0xffffffffu, lA, 2);
    lB += __shfl_xor_sync(0xffffffffu, lB, 1);
    lB += __shfl_xor_sync(0xffffffffu, lB, 2);
    const float invA = 1.0f / (lA * 8.0f);
    const float invB = 1.0f / (lB * 8.0f);
    const int t = qa + gr;
    const int mtile = (b * TT + t) >> 4;
#pragma unroll
    for (int nt = 0; nt < 8; nt++) {
        const int ctile = h * 4 + (nt >> 1);
        const int a32 = ((mtile * 64 + ctile) * 32 + lane) * 4;
        const int w0 = 2 * (nt & 1);
        yf32[a32 + w0]     = pack2h(oacc[nt][0] * invA, oacc[nt][1] * invA);
        yf32[a32 + w0 + 1] = pack2h(oacc[nt][2] * invB, oacc[nt][3] * invB);
    }
}

// ---------------------------------------------------------------------------
extern "C" void kernel_launch(void* const* d_in, const int* in_sizes, int n_in,
                              void* d_out, int out_size)
{
    const float* x      = (const float*)d_in[0];
    const float* W_attn = (const float*)d_in[1];
    const float* b_attn = (const float*)d_in[2];
    const float* W_proj = (const float*)d_in[3];
    const float* b_proj = (const float*)d_in[4];
    float* out = (float*)d_out;

    bf16 *xh, *xl, *wth, *wtl;
    bf16 *qhp, *qlp, *khp, *klp, *vthp, *vtlp;
    half *wpfh, *wpfl, *yf;
    cudaGetSymbolAddress((void**)&xh,   g_xh);
    cudaGetSymbolAddress((void**)&xl,   g_xl);
    cudaGetSymbolAddress((void**)&wth,  g_wth);
    cudaGetSymbolAddress((void**)&wtl,  g_wtl);
    cudaGetSymbolAddress((void**)&wpfh, g_wpfh);
    cudaGetSymbolAddress((void**)&wpfl, g_wpfl);
    cudaGetSymbolAddress((void**)&qhp,  g_qh);
    cudaGetSymbolAddress((void**)&qlp,  g_ql);
    cudaGetSymbolAddress((void**)&khp,  g_kh);
    cudaGetSymbolAddress((void**)&klp,  g_kl);
    cudaGetSymbolAddress((void**)&vthp, g_vth);
    cudaGetSymbolAddress((void**)&vtlp, g_vtl);
    cudaGetSymbolAddress((void**)&yf,   g_yf);

    cudaFuncSetAttribute(gemm_qkv_kernel,
                         cudaFuncAttributeMaxDynamicSharedMemorySize,
                         GEMM_SMEM_BYTES);
    cudaFuncSetAttribute(gemm_proj_kernel,
                         cudaFuncAttributeMaxDynamicSharedMemorySize,
                         PROJ_SMEM_BYTES);
    cudaFuncSetAttribute(attn_kernel,
                         cudaFuncAttributeMaxDynamicSharedMemorySize,
                         AT_SMEM_BYTES);

    // prepasses
    split_a_kernel<<<(NTOK * CC / 4 + 255) / 256, 256>>>(
        x, (uint32_t*)xh, (uint32_t*)xl, NTOK * CC / 4);
    tsp_b_kernel<<<dim3(C3 / 32, CC / 32), 256>>>(W_attn, wth, wtl, C3);
    tsp_b_f16_kernel<<<dim3(CC / 32, CC / 32), 256>>>(W_proj, wpfh, wpfl, CC);

    // 1) QKV GEMM + routing epilogue (Q scaled by log2e)
    gemm_qkv_kernel<<<dim3(C3 / 128, NTOK / 128), 256, GEMM_SMEM_BYTES>>>(
        NTOK, C3, CC, xh, xl, wth, wtl, b_attn,
        (uint32_t*)qhp, (uint32_t*)qlp, (uint32_t*)khp, (uint32_t*)klp,
        vthp, vtlp);

    // 2) attention (single wave: 256 CTAs of 512 threads)
    attn_kernel<<<dim3(TT / 256, BB * NH), 512, AT_SMEM_BYTES>>>(
        (const uint32_t*)qhp, (const uint32_t*)qlp, khp, klp, vthp, vtlp,
        (uint32_t*)yf);

    // 3) proj GEMM (fp16 2-term)
    gemm_proj_kernel<<<dim3(CC / 128, NTOK / 128), 256, PROJ_SMEM_BYTES>>>(
        NTOK, CC, CC, yf, wpfh, wpfl, b_proj, out);
}

// round 17
// speedup vs baseline: 1.4547x; 1.0031x over previous
#include <cuda_runtime.h>
#include <cuda_bf16.h>
#include <cuda_fp16.h>
#include <math.h>
#include <stdint.h>

#define BB   2
#define TT   2048
#define CC   1024
#define NH   16
#define DH   64
#define NTOK (BB * TT)
#define C3   (3 * CC)
#define LOG2E 1.4426950408889634f

typedef __nv_bfloat16 bf16;

// ---------------------------------------------------------------------------
// Fragment-major layouts (16x16 tiles, 32 lanes x 16B) — see round 11 notes.
// ---------------------------------------------------------------------------
__device__ bf16 g_xh[NTOK * CC],  g_xl[NTOK * CC];   // A-type
__device__ bf16 g_wth[C3 * CC],   g_wtl[C3 * CC];    // B-type
__device__ half g_wpfh[CC * CC],  g_wpfl[CC * CC];   // B-type fp16 (proj)
__device__ bf16 g_qh[NTOK * CC],  g_ql[NTOK * CC];   // A-type per (b,h)
__device__ bf16 g_kh[NTOK * CC],  g_kl[NTOK * CC];   // B-type per (b,h)
__device__ bf16 g_vth[NTOK * CC], g_vtl[NTOK * CC];  // B-type transposed
__device__ half g_yf[NTOK * CC];                     // A-type fp16 single

// ---------------------------------------------------------------------------
// helpers
// ---------------------------------------------------------------------------
__device__ __forceinline__ float bfr(float x) {
    return __bfloat162float(__float2bfloat16(x));
}
__device__ __forceinline__ void splitb(float x, float& h, float& l) {
    h = bfr(x);
    l = bfr(x - h);
}
__device__ __forceinline__ uint32_t pack2(float a, float b) {
    __nv_bfloat162 t = __floats2bfloat162_rn(a, b);
    return *(uint32_t*)&t;
}
__device__ __forceinline__ uint32_t pack2h(float a, float b) {
    __half2 t = __floats2half2_rn(a, b);
    return *(uint32_t*)&t;
}
__device__ __forceinline__ float ex2f(float x) {
    float y; asm("ex2.approx.f32 %0, %1;" : "=f"(y) : "f"(x)); return y;
}
__device__ __forceinline__ void mma_bf16(float* d, const uint32_t* a,
                                         uint32_t b0, uint32_t b1) {
    asm volatile(
        "mma.sync.aligned.m16n8k16.row.col.f32.bf16.bf16.f32 "
        "{%0,%1,%2,%3}, {%4,%5,%6,%7}, {%8,%9}, {%0,%1,%2,%3};"
        : "+f"(d[0]), "+f"(d[1]), "+f"(d[2]), "+f"(d[3])
        : "r"(a[0]), "r"(a[1]), "r"(a[2]), "r"(a[3]), "r"(b0), "r"(b1));
}
__device__ __forceinline__ void mma_f16(float* d, const uint32_t* a,
                                        uint32_t b0, uint32_t b1) {
    asm volatile(
        "mma.sync.aligned.m16n8k16.row.col.f32.f16.f16.f32 "
        "{%0,%1,%2,%3}, {%4,%5,%6,%7}, {%8,%9}, {%0,%1,%2,%3};"
        : "+f"(d[0]), "+f"(d[1]), "+f"(d[2]), "+f"(d[3])
        : "r"(a[0]), "r"(a[1]), "r"(a[2]), "r"(a[3]), "r"(b0), "r"(b1));
}
__device__ __forceinline__ void cp16(uint32_t d, const void* s) {
    asm volatile("cp.async.cg.shared.global [%0], [%1], 16;" :: "r"(d), "l"(s));
}
__device__ __forceinline__ void cp_commit() {
    asm volatile("cp.async.commit_group;");
}
template <int N> __device__ __forceinline__ void cp_wait() {
    asm volatile("cp.async.wait_group %0;" :: "n"(N));
}

// ---------------------------------------------------------------------------
// prepass 1: x -> A-type frag-major bf16 hi/lo
// ---------------------------------------------------------------------------
__global__ void __launch_bounds__(256) split_a_kernel(
    const float* __restrict__ in, uint32_t* __restrict__ oh,
    uint32_t* __restrict__ ol, int n4)
{
    const int i4 = blockIdx.x * 256 + threadIdx.x;
    if (i4 >= n4) return;
    const int g = i4 * 4;
    const int m = g >> 10, k0 = g & 1023;
    float4 v = *(const float4*)&in[g];

    const int r = m & 15, gr = r & 7, hi = (r >> 3) & 1;
    const int tile = ((m >> 4) << 6) + (k0 >> 4);
    const int p0 = (k0 & 15) >> 1;
#pragma unroll
    for (int q = 0; q < 2; q++) {
        const int p = p0 + q;
        const int lane = gr * 4 + (p & 3);
        const int w = hi + 2 * (p >> 2);
        const int a32 = (tile * 32 + lane) * 4 + w;
        float e0 = q ? v.z : v.x, e1 = q ? v.w : v.y;
        float h0, l0, h1, l1;
        splitb(e0, h0, l0);
        splitb(e1, h1, l1);
        oh[a32] = pack2(h0, h1);
        ol[a32] = pack2(l0, l1);
    }
}

// ---------------------------------------------------------------------------
// prepass 2a: W_attn[K][N] -> B-type frag-major bf16 hi/lo
// ---------------------------------------------------------------------------
__global__ void __launch_bounds__(256) tsp_b_kernel(
    const float* __restrict__ W, bf16* __restrict__ oh,
    bf16* __restrict__ ol, int N)
{
    __shared__ float t[32][33];
    const int bx = blockIdx.x * 32;
    const int by = blockIdx.y * 32;
    const int tx = threadIdx.x & 31, ty = threadIdx.x >> 5;
#pragma unroll
    for (int j = 0; j < 32; j += 8)
        t[ty + j][tx] = W[(long)(by + ty + j) * N + bx + tx];
    __syncthreads();
    const int k = by + tx;
    const int ki = k >> 4, kk = k & 15, p = kk >> 1, e = kk & 1;
#pragma unroll
    for (int j = 0; j < 32; j += 8) {
        const int n = bx + ty + j;
        const int c = n & 15;
        const int lane = (c & 7) * 4 + (p & 3);
        const int w = ((c >> 3) & 1) * 2 + (p >> 2);
        const long flat = ((long)(((n >> 4) << 6) + ki) * 32 + lane) * 8 + w * 2 + e;
        float h, l;
        splitb(t[tx][ty + j], h, l);
        oh[flat] = __float2bfloat16(h);
        ol[flat] = __float2bfloat16(l);
    }
}

// ---------------------------------------------------------------------------
// prepass 2b: W_proj[K][N] -> B-type frag-major FP16 hi/lo
// ---------------------------------------------------------------------------
__global__ void __launch_bounds__(256) tsp_b_f16_kernel(
    const float* __restrict__ W, half* __restrict__ oh,
    half* __restrict__ ol, int N)
{
    __shared__ float t[32][33];
    const int bx = blockIdx.x * 32;
    const int by = blockIdx.y * 32;
    const int tx = threadIdx.x & 31, ty = threadIdx.x >> 5;
#pragma unroll
    for (int j = 0; j < 32; j += 8)
        t[ty + j][tx] = W[(long)(by + ty + j) * N + bx + tx];
    __syncthreads();
    const int k = by + tx;
    const int ki = k >> 4, kk = k & 15, p = kk >> 1, e = kk & 1;
#pragma unroll
    for (int j = 0; j < 32; j += 8) {
        const int n = bx + ty + j;
        const int c = n & 15;
        const int lane = (c & 7) * 4 + (p & 3);
        const int w = ((c >> 3) & 1) * 2 + (p >> 2);
        const long flat = ((long)(((n >> 4) << 6) + ki) * 32 + lane) * 8 + w * 2 + e;
        const float v = t[tx][ty + j];
        half hh = __float2half_rn(v);
        half ll = __float2half_rn(v - __half2float(hh));
        oh[flat] = hh;
        ol[flat] = ll;
    }
}

// ---------------------------------------------------------------------------
// QKV GEMM (3xBF16): 256 thr, 8 warps (2x4), warp 64x32, CTA 128x128,
// BK=32, 3-stage cp.async (round-13 structure).
// Epilogue: stage outputs in (now-dead) pipeline smem, then write gmem
// as fully coalesced 16B chunks.
// ---------------------------------------------------------------------------
#define GW_STAGE 8192
#define GEMM_SMEM_BYTES (3 * GW_STAGE * 4)

__device__ __forceinline__ void gemm_stage_cp(
    uint32_t sb, int s, int tid,
    const bf16* __restrict__ Agh, const bf16* __restrict__ Agl,
    const bf16* __restrict__ Bgh, const bf16* __restrict__ Bgl,
    int mt0, int nt0, int kt0)
{
#pragma unroll
    for (int i = 0; i < 2; i++) {
        const int c = tid + i * 256;
        const int kt2 = c >> 8, t8 = (c >> 5) & 7, lane = c & 31;
        const uint32_t w = (uint32_t)(s * GW_STAGE + (kt2 * 8 + t8) * 128 + lane * 4);
        const long ga = ((long)((mt0 + t8) * 64 + kt0 + kt2) * 32 + lane) * 8;
        const long gb = ((long)((nt0 + t8) * 64 + kt0 + kt2) * 32 + lane) * 8;
        cp16(sb + w * 4,          &Agh[ga]);
        cp16(sb + (w + 2048) * 4, &Agl[ga]);
        cp16(sb + (w + 4096) * 4, &Bgh[gb]);
        cp16(sb + (w + 6144) * 4, &Bgl[gb]);
    }
    cp_commit();
}

__global__ void __launch_bounds__(256, 2) gemm_qkv_kernel(
    int M, int N, int K,
    const bf16* __restrict__ Agh, const bf16* __restrict__ Agl,
    const bf16* __restrict__ Bgh, const bf16* __restrict__ Bgl,
    const float* __restrict__ bias,
    uint32_t* __restrict__ qh32, uint32_t* __restrict__ ql32,
    uint32_t* __restrict__ kh32, uint32_t* __restrict__ kl32,
    bf16* __restrict__ vth, bf16* __restrict__ vtl)
{
    extern __shared__ uint32_t smw[];
    const uint32_t sb = (uint32_t)__cvta_generic_to_shared(smw);

    const int tid  = threadIdx.x;
    const int wid  = tid >> 5, lane = tid & 31;
    const int gr   = lane >> 2, tg = lane & 3;
    const int wr   = wid >> 2,  wc = wid & 3;
    const int m0   = blockIdx.y * 128;
    const int n0   = blockIdx.x * 128;
    const int mt0  = m0 >> 4, nt0 = n0 >> 4;

    float acc[4][4][4];
#pragma unroll
    for (int i = 0; i < 4; i++)
#pragma unroll
        for (int j = 0; j < 4; j++)
#pragma unroll
            for (int r = 0; r < 4; r++) acc[i][j][r] = 0.f;

    const int nIter = K / 32;
    gemm_stage_cp(sb, 0, tid, Agh, Agl, Bgh, Bgl, mt0, nt0, 0);
    gemm_stage_cp(sb, 1, tid, Agh, Agl, Bgh, Bgl, mt0, nt0, 2);

    int stq = 0;
    for (int it = 0; it < nIter; it++) {
        if (it + 1 < nIter) cp_wait<1>(); else cp_wait<0>();
        __syncthreads();
        if (it + 2 < nIter) {
            int s2 = stq + 2; if (s2 >= 3) s2 -= 3;
            gemm_stage_cp(sb, s2, tid, Agh, Agl, Bgh, Bgl,
                          mt0, nt0, (it + 2) * 2);
        }

        const uint32_t* base = smw + stq * GW_STAGE;
#pragma unroll
        for (int ks = 0; ks < 2; ks++) {
            uint4 afh[4], afl[4];
#pragma unroll
            for (int mt = 0; mt < 4; mt++) {
                const int o = (ks * 8 + wr * 4 + mt) * 128 + lane * 4;
                afh[mt] = *(const uint4*)(base + o);
                afl[mt] = *(const uint4*)(base + 2048 + o);
            }
#pragma unroll
            for (int j = 0; j < 2; j++) {
                const int o = (ks * 8 + wc * 2 + j) * 128 + lane * 4;
                uint4 bh4 = *(const uint4*)(base + 4096 + o);
                uint4 bl4 = *(const uint4*)(base + 6144 + o);
                const uint32_t bx[2][2] = {{bh4.x, bh4.y}, {bh4.z, bh4.w}};
                const uint32_t cx[2][2] = {{bl4.x, bl4.y}, {bl4.z, bl4.w}};
#pragma unroll
                for (int jj = 0; jj < 2; jj++)
#pragma unroll
                    for (int mt = 0; mt < 4; mt++)
                        mma_bf16(acc[mt][2 * j + jj], (const uint32_t*)&afh[mt],
                                 bx[jj][0], bx[jj][1]);
#pragma unroll
                for (int jj = 0; jj < 2; jj++)
#pragma unroll
                    for (int mt = 0; mt < 4; mt++)
                        mma_bf16(acc[mt][2 * j + jj], (const uint32_t*)&afh[mt],
                                 cx[jj][0], cx[jj][1]);
#pragma unroll
                for (int jj = 0; jj < 2; jj++)
#pragma unroll
                    for (int mt = 0; mt < 4; mt++)
                        mma_bf16(acc[mt][2 * j + jj], (const uint32_t*)&afl[mt],
                                 bx[jj][0], bx[jj][1]);
            }
        }
        if (++stq == 3) stq = 0;
    }

    // ---- routing epilogue (smem-staged, coalesced gmem writeout) ----
    __syncthreads();                      // pipeline smem now dead
    const int sec     = n0 >> 10;         // 0=Q 1=K 2=V (uniform per CTA)
    const int hh_base = (n0 & 1023) >> 6; // even
    const int bb      = m0 >> 11;
    const int tt0     = (m0 & 2047) >> 4;

    if (sec < 2) {
        // phase 1: scatter into smem  [plane 2][hh2 2][ltile2 32][lane 32][w 4]
        uint32_t* sq = smw;
#pragma unroll
        for (int nt = 0; nt < 4; nt++) {
            const int col = n0 + wc * 32 + nt * 8 + tg * 2;
            const float2 bv = *(const float2*)&bias[col];
            const int dc  = col & 1023;
            const int hh2 = (dc >> 6) & 1;
            const int d0  = dc & 63;
#pragma unroll
            for (int mt = 0; mt < 4; mt++) {
                const int row = m0 + wr * 64 + mt * 16 + gr;
                const float v00 = acc[mt][nt][0] + bv.x;
                const float v01 = acc[mt][nt][1] + bv.y;
                const float v10 = acc[mt][nt][2] + bv.x;
                const float v11 = acc[mt][nt][3] + bv.y;
#pragma unroll
                for (int rr = 0; rr < 2; rr++) {
                    const int t = (row + rr * 8) & 2047;
                    float u0 = rr ? v10 : v00;
                    float u1 = rr ? v11 : v01;
                    if (sec == 0) { u0 *= LOG2E; u1 *= LOG2E; }
                    float h0, l0, h1, l1;
                    splitb(u0, h0, l0); splitb(u1, h1, l1);
                    const int lane_ = (t & 7) * 4 + ((d0 >> 1) & 3);
                    const int w = (sec == 0)
                        ? ((t >> 3) & 1) + 2 * ((d0 >> 3) & 1)
                        : ((t >> 3) & 1) * 2 + ((d0 >> 3) & 1);
                    const int ltile = hh2 * 32 + ((t >> 4) & 7) * 4 + (d0 >> 4);
                    const int sa = (ltile * 32 + lane_) * 4 + w;
                    sq[sa]        = pack2(h0, h1);
                    sq[8192 + sa] = pack2(l0, l1);
                }
            }
        }
        __syncthreads();
        // phase 2: 4096 coalesced 16B chunks
#pragma unroll
        for (int i = 0; i < 16; i++) {
            const int c = tid + i * 256;
            const int plane = c >> 11, hh2 = (c >> 10) & 1, off = c & 1023;
            const uint4 v = *(const uint4*)(smw + plane * 8192 + hh2 * 4096 + off * 4);
            const long gw = ((long)((bb * NH + hh_base + hh2) * 128 + tt0) * 4) * 128
                          + (long)off * 4;
            uint32_t* dst = (sec == 0) ? (plane ? ql32 : qh32)
                                       : (plane ? kl32 : kh32);
            *(uint4*)(dst + gw) = v;
        }
    } else {
        // phase 1: scatter into smem  [plane 2][hh2 2][dt 4][tt 8][lane 32][8 halves]
        bf16* sv = (bf16*)smw;
#pragma unroll
        for (int nt = 0; nt < 4; nt++) {
            const int col = n0 + wc * 32 + nt * 8 + tg * 2;
            const float2 bv = *(const float2*)&bias[col];
            const int dc  = col & 1023;
            const int hh2 = (dc >> 6) & 1;
            const int d0  = dc & 63;
#pragma unroll
            for (int mt = 0; mt < 4; mt++) {
                const int row = m0 + wr * 64 + mt * 16 + gr;
                const float v00 = acc[mt][nt][0] + bv.x;
                const float v01 = acc[mt][nt][1] + bv.y;
                const float v10 = acc[mt][nt][2] + bv.x;
                const float v11 = acc[mt][nt][3] + bv.y;
#pragma unroll
                for (int rr = 0; rr < 2; rr++) {
                    const int t = (row + rr * 8) & 2047;
                    const float u0 = rr ? v10 : v00;
                    const float u1 = rr ? v11 : v01;
                    float h0, l0, h1, l1;
                    splitb(u0, h0, l0); splitb(u1, h1, l1);
                    const int lane_ = (d0 & 7) * 4 + ((t >> 1) & 3);
                    const int w = ((d0 >> 3) & 1) * 2 + ((t >> 3) & 1);
                    const int ltile = (hh2 * 4 + (d0 >> 4)) * 8 + ((t >> 4) & 7);
                    const int sa = (ltile * 32 + lane_) * 8 + w * 2 + (t & 1);
                    sv[sa]              = __float2bfloat16(h0);
                    sv[16384 + sa]      = __float2bfloat16(l0);
                    sv[sa + 32]         = __float2bfloat16(h1);  // d0+1: lane_+4
                    sv[16384 + sa + 32] = __float2bfloat16(l1);
                }
            }
        }
        __syncthreads();
        // phase 2: 4096 coalesced 16B chunks (16 regions of 4KB)
#pragma unroll
        for (int i = 0; i < 16; i++) {
            const int c = tid + i * 256;
            const int plane = c >> 11, hh2 = (c >> 10) & 1;
            const int dt = (c >> 8) & 3, off = c & 255;
            const uint4 v = *(const uint4*)(smw +
                (plane * 2048 + (hh2 * 4 + dt) * 256 + off) * 4);
            const long gtile0 = ((long)(bb * NH + hh_base + hh2) * 4 + dt) * 128 + tt0;
            bf16* dst = plane ? vtl : vth;
            *(uint4*)(dst + gtile0 * 256 + (long)off * 8) = v;
        }
    }
}

// ---------------------------------------------------------------------------
// PROJ GEMM (fp16 2-term), round-13 structure.
// ---------------------------------------------------------------------------
#define PW_STAGE 6144
#define PROJ_SMEM_BYTES (3 * PW_STAGE * 4)

__device__ __forceinline__ void proj_stage_cp(
    uint32_t sb, int s, int tid,
    const half* __restrict__ Af,
    const half* __restrict__ Bh, const half* __restrict__ Bl,
    int mt0, int nt0, int kt0)
{
#pragma unroll
    for (int i = 0; i < 2; i++) {
        const int c = tid + i * 256;
        const int kt2 = c >> 8, t8 = (c >> 5) & 7, lane = c & 31;
        const uint32_t w = (uint32_t)(s * PW_STAGE + (kt2 * 8 + t8) * 128 + lane * 4);
        const long ga = ((long)((mt0 + t8) * 64 + kt0 + kt2) * 32 + lane) * 8;
        cp16(sb + w * 4, &Af[ga]);
    }
#pragma unroll
    for (int i = 0; i < 2; i++) {
        const int c = tid + i * 256;
        const int kt2 = c >> 8, t8 = (c >> 5) & 7, lane = c & 31;
        const uint32_t w = (uint32_t)(s * PW_STAGE + 2048 + (kt2 * 8 + t8) * 128 + lane * 4);
        const long gb = ((long)((nt0 + t8) * 64 + kt0 + kt2) * 32 + lane) * 8;
        cp16(sb + w * 4, &Bh[gb]);
    }
#pragma unroll
    for (int i = 0; i < 2; i++) {
        const int c = tid + i * 256;
        const int kt2 = c >> 8, t8 = (c >> 5) & 7, lane = c & 31;
        const uint32_t w = (uint32_t)(s * PW_STAGE + 4096 + (kt2 * 8 + t8) * 128 + lane * 4);
        const long gb = ((long)((nt0 + t8) * 64 + kt0 + kt2) * 32 + lane) * 8;
        cp16(sb + w * 4, &Bl[gb]);
    }
    cp_commit();
}

__global__ void __launch_bounds__(256, 2) gemm_proj_kernel(
    int M, int N, int K,
    const half* __restrict__ Af,
    const half* __restrict__ Bh, const half* __restrict__ Bl,
    const float* __restrict__ bias, float* __restrict__ C)
{
    extern __shared__ uint32_t smw[];
    const uint32_t sb = (uint32_t)__cvta_generic_to_shared(smw);

    const int tid  = threadIdx.x;
    const int wid  = tid >> 5, lane = tid & 31;
    const int gr   = lane >> 2, tg = lane & 3;
    const int wr   = wid >> 2,  wc = wid & 3;
    const int m0   = blockIdx.y * 128;
    const int n0   = blockIdx.x * 128;
    const int mt0  = m0 >> 4, nt0 = n0 >> 4;

    float acc[4][4][4];
#pragma unroll
    for (int i = 0; i < 4; i++)
#pragma unroll
        for (int j = 0; j < 4; j++)
#pragma unroll
            for (int r = 0; r < 4; r++) acc[i][j][r] = 0.f;

    const int nIter = K / 32;
    proj_stage_cp(sb, 0, tid, Af, Bh, Bl, mt0, nt0, 0);
    proj_stage_cp(sb, 1, tid, Af, Bh, Bl, mt0, nt0, 2);

    int stq = 0;
    for (int it = 0; it < nIter; it++) {
        if (it + 1 < nIter) cp_wait<1>(); else cp_wait<0>();
        __syncthreads();
        if (it + 2 < nIter) {
            int s2 = stq + 2; if (s2 >= 3) s2 -= 3;
            proj_stage_cp(sb, s2, tid, Af, Bh, Bl, mt0, nt0, (it + 2) * 2);
        }

        const uint32_t* base = smw + stq * PW_STAGE;
#pragma unroll
        for (int ks = 0; ks < 2; ks++) {
            uint4 af[4];
#pragma unroll
            for (int mt = 0; mt < 4; mt++) {
                const int o = (ks * 8 + wr * 4 + mt) * 128 + lane * 4;
                af[mt] = *(const uint4*)(base + o);
            }
#pragma unroll
            for (int j = 0; j < 2; j++) {
                const int o = (ks * 8 + wc * 2 + j) * 128 + lane * 4;
                uint4 bh4 = *(const uint4*)(base + 2048 + o);
                uint4 bl4 = *(const uint4*)(base + 4096 + o);
                const uint32_t bx[2][2] = {{bh4.x, bh4.y}, {bh4.z, bh4.w}};
                const uint32_t cx[2][2] = {{bl4.x, bl4.y}, {bl4.z, bl4.w}};
#pragma unroll
                for (int jj = 0; jj < 2; jj++)
#pragma unroll
                    for (int mt = 0; mt < 4; mt++)
                        mma_f16(acc[mt][2 * j + jj], (const uint32_t*)&af[mt],
                                bx[jj][0], bx[jj][1]);
#pragma unroll
                for (int jj = 0; jj < 2; jj++)
#pragma unroll
                    for (int mt = 0; mt < 4; mt++)
                        mma_f16(acc[mt][2 * j + jj], (const uint32_t*)&af[mt],
                                cx[jj][0], cx[jj][1]);
            }
        }
        if (++stq == 3) stq = 0;
    }

#pragma unroll
    for (int nt = 0; nt < 4; nt++) {
        const int col = n0 + wc * 32 + nt * 8 + tg * 2;
        const float2 bv = *(const float2*)&bias[col];
#pragma unroll
        for (int mt = 0; mt < 4; mt++) {
            const int row = m0 + wr * 64 + mt * 16 + gr;
            *(float2*)&C[(long)row * N + col] =
                make_float2(acc[mt][nt][0] + bv.x, acc[mt][nt][1] + bv.y);
            *(float2*)&C[(long)(row + 8) * N + col] =
                make_float2(acc[mt][nt][2] + bv.x, acc[mt][nt][3] + bv.y);
        }
    }
}

// ---------------------------------------------------------------------------
// Attention: 512 thr (16 warps), warp = 16 q-rows, BQ=256, BK=64, 3-stage
// cp.async, Q persistent in regs (round-16 proven).
// ---------------------------------------------------------------------------
#define AW_STAGE 8192
#define AT_SMEM_BYTES (3 * AW_STAGE * 4)

__device__ __forceinline__ void attn_stage_cp(
    uint32_t sb, int s, int tid, int bh32,
    const bf16* __restrict__ kh, const bf16* __restrict__ kl,
    const bf16* __restrict__ vth, const bf16* __restrict__ vtl,
    int jt0)
{
    const int c = tid;
    const int dt = c >> 7, tt = (c >> 5) & 3, lane = c & 31;
    const long gk = ((long)((bh32 * 128 + jt0 + tt) * 4 + dt) * 32 + lane) * 8;
    const long gv = ((long)((bh32 * 4 + dt) * 128 + jt0 + tt) * 32 + lane) * 8;
    const uint32_t wk = (uint32_t)(s * AW_STAGE + (dt * 4 + tt) * 128 + lane * 4);
    const uint32_t wv = (uint32_t)(s * AW_STAGE + 4096 + (tt * 4 + dt) * 128 + lane * 4);
    cp16(sb + wk * 4,          &kh[gk]);
    cp16(sb + (wk + 2048) * 4, &kl[gk]);
    cp16(sb + wv * 4,          &vth[gv]);
    cp16(sb + (wv + 2048) * 4, &vtl[gv]);
    cp_commit();
}

__global__ void __launch_bounds__(512, 1) attn_kernel(
    const uint32_t* __restrict__ qh32, const uint32_t* __restrict__ ql32,
    const bf16* __restrict__ kh, const bf16* __restrict__ kl,
    const bf16* __restrict__ vth, const bf16* __restrict__ vtl,
    uint32_t* __restrict__ yf32)
{
    extern __shared__ uint32_t smw[];
    const uint32_t sb = (uint32_t)__cvta_generic_to_shared(smw);

    const int tid  = threadIdx.x;
    const int wid  = tid >> 5, lane = tid & 31;
    const int gr   = lane >> 2, tg = lane & 3;
    const int bh32 = blockIdx.y;
    const int b    = bh32 >> 4, h = bh32 & 15;
    const int qa   = blockIdx.x * 256 + wid * 16;
    const int qt   = bh32 * 128 + (qa >> 4);

    attn_stage_cp(sb, 0, tid, bh32, kh, kl, vth, vtl, 0);
    attn_stage_cp(sb, 1, tid, bh32, kh, kl, vth, vtl, 4);

    uint4 qfh[4], qfl[4];
#pragma unroll
    for (int kt = 0; kt < 4; kt++) {
        const int a = ((qt * 4 + kt) * 32 + lane) * 4;
        qfh[kt] = *(const uint4*)(qh32 + a);
        qfl[kt] = *(const uint4*)(ql32 + a);
    }

    float oacc[8][4];
#pragma unroll
    for (int nt = 0; nt < 8; nt++)
#pragma unroll
        for (int r = 0; r < 4; r++) oacc[nt][r] = 0.f;
    float lA = 0.f, lB = 0.f;

    int stq = 0;
    for (int jt = 0; jt < 32; jt++) {
        if (jt + 1 < 32) cp_wait<1>(); else cp_wait<0>();
        __syncthreads();
        if (jt + 2 < 32) {
            int s2 = stq + 2; if (s2 >= 3) s2 -= 3;
            attn_stage_cp(sb, s2, tid, bh32, kh, kl, vth, vtl, (jt + 2) * 4);
        }
        const uint32_t* base = smw + stq * AW_STAGE;

        float sacc[8][4];
#pragma unroll
        for (int nt = 0; nt < 8; nt++)
#pragma unroll
            for (int r = 0; r < 4; r++) sacc[nt][r] = 0.f;

#pragma unroll
        for (int kt = 0; kt < 4; kt++) {
#pragma unroll
            for (int hp = 0; hp < 2; hp++) {
                uint4 k4h[2], k4l[2];
#pragma unroll
                for (int p = 0; p < 2; p++) {
                    const int o = (kt * 4 + 2 * hp + p) * 128 + lane * 4;
                    k4h[p] = *(const uint4*)(base + o);
                    k4l[p] = *(const uint4*)(base + 2048 + o);
                }
#pragma unroll
                for (int p = 0; p < 2; p++) {
                    const int nt0_ = (2 * hp + p) * 2;
                    mma_bf16(sacc[nt0_],     (const uint32_t*)&qfh[kt], k4h[p].x, k4h[p].y);
                    mma_bf16(sacc[nt0_ + 1], (const uint32_t*)&qfh[kt], k4h[p].z, k4h[p].w);
                }
#pragma unroll
                for (int p = 0; p < 2; p++) {
                    const int nt0_ = (2 * hp + p) * 2;
                    mma_bf16(sacc[nt0_],     (const uint32_t*)&qfh[kt], k4l[p].x, k4l[p].y);
                    mma_bf16(sacc[nt0_ + 1], (const uint32_t*)&qfh[kt], k4l[p].z, k4l[p].w);
                }
#pragma unroll
                for (int p = 0; p < 2; p++) {
                    const int nt0_ = (2 * hp + p) * 2;
                    mma_bf16(sacc[nt0_],     (const uint32_t*)&qfl[kt], k4h[p].x, k4h[p].y);
                    mma_bf16(sacc[nt0_ + 1], (const uint32_t*)&qfl[kt], k4h[p].z, k4h[p].w);
                }
            }
        }

        uint32_t pah[4][4], pal[4][4];
#pragma unroll
        for (int nt = 0; nt < 8; nt++) {
            float* s4 = sacc[nt];
            s4[0] = ex2f(s4[0]);
            s4[1] = ex2f(s4[1]);
            s4[2] = ex2f(s4[2]);
            s4[3] = ex2f(s4[3]);
            lA += s4[0] + s4[1];
            lB += s4[2] + s4[3];
            const int kt = nt >> 1, i = nt & 1;
            uint32_t w0 = pack2(s4[0], s4[1]);
            uint32_t w1 = pack2(s4[2], s4[3]);
            pah[kt][2 * i]     = w0;
            pah[kt][2 * i + 1] = w1;
            __nv_bfloat162 b0 = *(__nv_bfloat162*)&w0;
            __nv_bfloat162 b1 = *(__nv_bfloat162*)&w1;
            float2 f0 = __bfloat1622float2(b0);
            float2 f1 = __bfloat1622float2(b1);
            pal[kt][2 * i]     = pack2(s4[0] - f0.x, s4[1] - f0.y);
            pal[kt][2 * i + 1] = pack2(s4[2] - f1.x, s4[3] - f1.y);
        }

#pragma unroll
        for (int kt = 0; kt < 4; kt++) {
#pragma unroll
            for (int hp = 0; hp < 2; hp++) {
                uint4 v4h[2], v4l[2];
#pragma unroll
                for (int p = 0; p < 2; p++) {
                    const int o = 4096 + (kt * 4 + 2 * hp + p) * 128 + lane * 4;
                    v4h[p] = *(const uint4*)(base + o);
                    v4l[p] = *(const uint4*)(base + 2048 + o);
                }
#pragma unroll
                for (int p = 0; p < 2; p++) {
                    const int nt0_ = (2 * hp + p) * 2;
                    mma_bf16(oacc[nt0_],     pah[kt], v4h[p].x, v4h[p].y);
                    mma_bf16(oacc[nt0_ + 1], pah[kt], v4h[p].z, v4h[p].w);
                }
#pragma unroll
                for (int p = 0; p < 2; p++) {
                    const int nt0_ = (2 * hp + p) * 2;
                    mma_bf16(oacc[nt0_],     pah[kt], v4l[p].x, v4l[p].y);
                    mma_bf16(oacc[nt0_ + 1], pah[kt], v4l[p].z, v4l[p].w);
                }
#pragma unroll
                for (int p = 0; p < 2; p++) {
                    const int nt0_ = (2 * hp + p) * 2;
                    mma_bf16(oacc[nt0_],     pal[kt], v4h[p].x, v4h[p].y);
                    mma_bf16(oacc[nt0_ + 1], pal[kt], v4h[p].z, v4h[p].w);
                }
            }
        }
        if (++stq == 3) stq = 0;
    }

    lA += __shfl_xor_sync(0xffffffffu, lA, 1);
    lA += __shfl_xor_sync(0xffffffffu, lA, 2);
    lB += __shfl_xor_sync(0xffffffffu, lB, 1);
    lB += __shfl_xor_sync(0xffffffffu, lB, 2);
    const float invA = 1.0f / (lA * 8.0f);
    const float invB = 1.0f / (lB * 8.0f);
    const int t = qa + gr;
    const int mtile = (b * TT + t) >> 4;
#pragma unroll
    for (int nt = 0; nt < 8; nt++) {
        const int ctile = h * 4 + (nt >> 1);
        const int a32 = ((mtile * 64 + ctile) * 32 + lane) * 4;
        const int w0 = 2 * (nt & 1);
        yf32[a32 + w0]     = pack2h(oacc[nt][0] * invA, oacc[nt][1] * invA);
        yf32[a32 + w0 + 1] = pack2h(oacc[nt][2] * invB, oacc[nt][3] * invB);
    }
}

// ---------------------------------------------------------------------------
extern "C" void kernel_launch(void* const* d_in, const int* in_sizes, int n_in,
                              void* d_out, int out_size)
{
    const float* x      = (const float*)d_in[0];
    const float* W_attn = (const float*)d_in[1];
    const float* b_attn = (const float*)d_in[2];
    const float* W_proj = (const float*)d_in[3];
    const float* b_proj = (const float*)d_in[4];
    float* out = (float*)d_out;

    bf16 *xh, *xl, *wth, *wtl;
    bf16 *qhp, *qlp, *khp, *klp, *vthp, *vtlp;
    half *wpfh, *wpfl, *yf;
    cudaGetSymbolAddress((void**)&xh,   g_xh);
    cudaGetSymbolAddress((void**)&xl,   g_xl);
    cudaGetSymbolAddress((void**)&wth,  g_wth);
    cudaGetSymbolAddress((void**)&wtl,  g_wtl);
    cudaGetSymbolAddress((void**)&wpfh, g_wpfh);
    cudaGetSymbolAddress((void**)&wpfl, g_wpfl);
    cudaGetSymbolAddress((void**)&qhp,  g_qh);
    cudaGetSymbolAddress((void**)&qlp,  g_ql);
    cudaGetSymbolAddress((void**)&khp,  g_kh);
    cudaGetSymbolAddress((void**)&klp,  g_kl);
    cudaGetSymbolAddress((void**)&vthp, g_vth);
    cudaGetSymbolAddress((void**)&vtlp, g_vtl);
    cudaGetSymbolAddress((void**)&yf,   g_yf);

    cudaFuncSetAttribute(gemm_qkv_kernel,
                         cudaFuncAttributeMaxDynamicSharedMemorySize,
                         GEMM_SMEM_BYTES);
    cudaFuncSetAttribute(gemm_proj_kernel,
                         cudaFuncAttributeMaxDynamicSharedMemorySize,
                         PROJ_SMEM_BYTES);
    cudaFuncSetAttribute(attn_kernel,
                         cudaFuncAttributeMaxDynamicSharedMemorySize,
                         AT_SMEM_BYTES);

    // prepasses
    split_a_kernel<<<(NTOK * CC / 4 + 255) / 256, 256>>>(
        x, (uint32_t*)xh, (uint32_t*)xl, NTOK * CC / 4);
    tsp_b_kernel<<<dim3(C3 / 32, CC / 32), 256>>>(W_attn, wth, wtl, C3);
    tsp_b_f16_kernel<<<dim3(CC / 32, CC / 32), 256>>>(W_proj, wpfh, wpfl, CC);

    // 1) QKV GEMM + routing epilogue (Q scaled by log2e)
    gemm_qkv_kernel<<<dim3(C3 / 128, NTOK / 128), 256, GEMM_SMEM_BYTES>>>(
        NTOK, C3, CC, xh, xl, wth, wtl, b_attn,
        (uint32_t*)qhp, (uint32_t*)qlp, (uint32_t*)khp, (uint32_t*)klp,
        vthp, vtlp);

    // 2) attention
    attn_kernel<<<dim3(TT / 256, BB * NH), 512, AT_SMEM_BYTES>>>(
        (const uint32_t*)qhp, (const uint32_t*)qlp, khp, klp, vthp, vtlp,
        (uint32_t*)yf);

    // 3) proj GEMM (fp16 2-term)
    gemm_proj_kernel<<<dim3(CC / 128, NTOK / 128), 256, PROJ_SMEM_BYTES>>>(
        NTOK, CC, CC, yf, wpfh, wpfl, b_proj, out);
}